// round 1
// baseline (speedup 1.0000x reference)
#include <cuda_runtime.h>
#include <cuda_bf16.h>

// ---------------------------------------------------------------------------
// Gemma3-270M forward: 18 layers + LM head, all fp32 with f32x2 packed FMA.
// ---------------------------------------------------------------------------

#define D_MODEL 640
#define NHEADS  4
#define HEADDIM 256
#define DFF     2048
#define NLAYERS 18
#define SEQ     1024
#define VOCAB   262144
#define EMB_SCALE 25.298221281347036f

// -------------------- scratch (device globals; no allocs) ------------------
__device__ float g_x[SEQ * D_MODEL];
__device__ float g_xn[SEQ * D_MODEL];
__device__ float g_tmpd[SEQ * D_MODEL];
__device__ float g_q[SEQ * NHEADS * HEADDIM];
__device__ float g_k[SEQ * HEADDIM];
__device__ float g_v[SEQ * HEADDIM];
__device__ float g_scores[NHEADS * SEQ * SEQ];
__device__ float g_ctx[SEQ * NHEADS * HEADDIM];
__device__ float g_g[SEQ * DFF];
__device__ float g_u[SEQ * DFF];

// -------------------- reductions -------------------------------------------
__device__ __forceinline__ float block_reduce_sum(float v) {
    __shared__ float red[32];
    __syncthreads();                    // protect smem reuse across calls
    int lane = threadIdx.x & 31, wid = threadIdx.x >> 5;
    #pragma unroll
    for (int o = 16; o > 0; o >>= 1) v += __shfl_down_sync(0xffffffffu, v, o);
    if (lane == 0) red[wid] = v;
    __syncthreads();
    int nw = (blockDim.x + 31) >> 5;
    v = (threadIdx.x < (unsigned)nw) ? red[threadIdx.x] : 0.0f;
    if (wid == 0) {
        #pragma unroll
        for (int o = 16; o > 0; o >>= 1) v += __shfl_down_sync(0xffffffffu, v, o);
        if (lane == 0) red[0] = v;
    }
    __syncthreads();
    return red[0];
}

__device__ __forceinline__ float block_reduce_max(float v) {
    __shared__ float redm[32];
    __syncthreads();
    int lane = threadIdx.x & 31, wid = threadIdx.x >> 5;
    #pragma unroll
    for (int o = 16; o > 0; o >>= 1) v = fmaxf(v, __shfl_down_sync(0xffffffffu, v, o));
    if (lane == 0) redm[wid] = v;
    __syncthreads();
    int nw = (blockDim.x + 31) >> 5;
    v = (threadIdx.x < (unsigned)nw) ? redm[threadIdx.x] : -3.0e38f;
    if (wid == 0) {
        #pragma unroll
        for (int o = 16; o > 0; o >>= 1) v = fmaxf(v, __shfl_down_sync(0xffffffffu, v, o));
        if (lane == 0) redm[0] = v;
    }
    __syncthreads();
    return redm[0];
}

// -------------------- f32x2 helpers -----------------------------------------
__device__ __forceinline__ unsigned long long pack_dup(float a) {
    unsigned long long r;
    unsigned int au = __float_as_uint(a);
    asm("mov.b64 %0, {%1, %2};" : "=l"(r) : "r"(au), "r"(au));
    return r;
}
__device__ __forceinline__ void fma2(unsigned long long& c, unsigned long long a,
                                     unsigned long long b) {
    asm("fma.rn.f32x2 %0, %1, %2, %0;" : "+l"(c) : "l"(a), "l"(b));
}
__device__ __forceinline__ void unpack2(unsigned long long p, float& lo, float& hi) {
    unsigned int l, h;
    asm("mov.b64 {%0, %1}, %2;" : "=r"(l), "=r"(h) : "l"(p));
    lo = __uint_as_float(l); hi = __uint_as_float(h);
}

// -------------------- GEMM NT: C[m,n] = sum_k A[m,k]*B[n,k] ----------------
// 64x64 tile, BK=16, 256 threads, 4x4 per thread, f32x2 FMAs.
__global__ void __launch_bounds__(256) gemm_nt(
    const float* __restrict__ A, const float* __restrict__ B, float* __restrict__ C,
    int K, int lda, int ldb, int ldc,
    long strideA, long strideB, long strideC)
{
    A += (long)blockIdx.z * strideA;
    B += (long)blockIdx.z * strideB;
    C += (long)blockIdx.z * strideC;
    __shared__ float As[16][64];
    __shared__ float Bs[16][64];
    const int tid = threadIdx.x;
    const int tx = tid & 15, ty = tid >> 4;
    const int m0 = blockIdx.y << 6;
    const int n0 = blockIdx.x << 6;
    const int lr = tid >> 2;          // 0..63
    const int lc = (tid & 3) << 2;    // 0,4,8,12

    unsigned long long acc[4][2];
    #pragma unroll
    for (int i = 0; i < 4; i++) { acc[i][0] = 0ull; acc[i][1] = 0ull; }

    const float* aptr = A + (long)(m0 + lr) * lda + lc;
    const float* bptr = B + (long)(n0 + lr) * ldb + lc;

    for (int k0 = 0; k0 < K; k0 += 16) {
        float4 av = *reinterpret_cast<const float4*>(aptr + k0);
        float4 bv = *reinterpret_cast<const float4*>(bptr + k0);
        As[lc + 0][lr] = av.x; As[lc + 1][lr] = av.y;
        As[lc + 2][lr] = av.z; As[lc + 3][lr] = av.w;
        Bs[lc + 0][lr] = bv.x; Bs[lc + 1][lr] = bv.y;
        Bs[lc + 2][lr] = bv.z; Bs[lc + 3][lr] = bv.w;
        __syncthreads();
        #pragma unroll
        for (int kk = 0; kk < 16; kk++) {
            const unsigned long long* bp =
                reinterpret_cast<const unsigned long long*>(&Bs[kk][tx << 2]);
            unsigned long long b0 = bp[0], b1 = bp[1];
            float4 a4 = *reinterpret_cast<const float4*>(&As[kk][ty << 2]);
            unsigned long long ap0 = pack_dup(a4.x), ap1 = pack_dup(a4.y);
            unsigned long long ap2 = pack_dup(a4.z), ap3 = pack_dup(a4.w);
            fma2(acc[0][0], ap0, b0); fma2(acc[0][1], ap0, b1);
            fma2(acc[1][0], ap1, b0); fma2(acc[1][1], ap1, b1);
            fma2(acc[2][0], ap2, b0); fma2(acc[2][1], ap2, b1);
            fma2(acc[3][0], ap3, b0); fma2(acc[3][1], ap3, b1);
        }
        __syncthreads();
    }
    #pragma unroll
    for (int i = 0; i < 4; i++) {
        int m = m0 + (ty << 2) + i;
        float* crow = C + (long)m * ldc + n0 + (tx << 2);
        float v0, v1, v2, v3;
        unpack2(acc[i][0], v0, v1);
        unpack2(acc[i][1], v2, v3);
        crow[0] = v0; crow[1] = v1; crow[2] = v2; crow[3] = v3;
    }
}

// -------------------- GEMM NN: C[m,n] = sum_k A[m,k]*B[k,n] ----------------
__global__ void __launch_bounds__(256) gemm_nn(
    const float* __restrict__ A, const float* __restrict__ B, float* __restrict__ C,
    int K, int lda, int ldb, int ldc,
    long strideA, long strideB, long strideC)
{
    A += (long)blockIdx.z * strideA;
    B += (long)blockIdx.z * strideB;
    C += (long)blockIdx.z * strideC;
    __shared__ float As[16][64];
    __shared__ float Bs[16][64];
    const int tid = threadIdx.x;
    const int tx = tid & 15, ty = tid >> 4;
    const int m0 = blockIdx.y << 6;
    const int n0 = blockIdx.x << 6;
    const int lr = tid >> 2;          // 0..63 (A row)
    const int lc = (tid & 3) << 2;    // A k-offset
    const int br = tid >> 4;          // 0..15 (B row = k)
    const int bc = (tid & 15) << 2;   // B col offset

    unsigned long long acc[4][2];
    #pragma unroll
    for (int i = 0; i < 4; i++) { acc[i][0] = 0ull; acc[i][1] = 0ull; }

    const float* aptr = A + (long)(m0 + lr) * lda + lc;

    for (int k0 = 0; k0 < K; k0 += 16) {
        float4 av = *reinterpret_cast<const float4*>(aptr + k0);
        As[lc + 0][lr] = av.x; As[lc + 1][lr] = av.y;
        As[lc + 2][lr] = av.z; As[lc + 3][lr] = av.w;
        float4 bv = *reinterpret_cast<const float4*>(B + (long)(k0 + br) * ldb + n0 + bc);
        *reinterpret_cast<float4*>(&Bs[br][bc]) = bv;
        __syncthreads();
        #pragma unroll
        for (int kk = 0; kk < 16; kk++) {
            const unsigned long long* bp =
                reinterpret_cast<const unsigned long long*>(&Bs[kk][tx << 2]);
            unsigned long long b0 = bp[0], b1 = bp[1];
            float4 a4 = *reinterpret_cast<const float4*>(&As[kk][ty << 2]);
            unsigned long long ap0 = pack_dup(a4.x), ap1 = pack_dup(a4.y);
            unsigned long long ap2 = pack_dup(a4.z), ap3 = pack_dup(a4.w);
            fma2(acc[0][0], ap0, b0); fma2(acc[0][1], ap0, b1);
            fma2(acc[1][0], ap1, b0); fma2(acc[1][1], ap1, b1);
            fma2(acc[2][0], ap2, b0); fma2(acc[2][1], ap2, b1);
            fma2(acc[3][0], ap3, b0); fma2(acc[3][1], ap3, b1);
        }
        __syncthreads();
    }
    #pragma unroll
    for (int i = 0; i < 4; i++) {
        int m = m0 + (ty << 2) + i;
        float* crow = C + (long)m * ldc + n0 + (tx << 2);
        float v0, v1, v2, v3;
        unpack2(acc[i][0], v0, v1);
        unpack2(acc[i][1], v2, v3);
        crow[0] = v0; crow[1] = v1; crow[2] = v2; crow[3] = v3;
    }
}

// -------------------- elementwise / norm kernels ----------------------------
__global__ void embed_kernel(const int* __restrict__ ids,
                             const float* __restrict__ emb,
                             float* __restrict__ x) {
    int t = blockIdx.x;
    long id = (long)ids[t];
    for (int d = threadIdx.x; d < D_MODEL; d += blockDim.x)
        x[(long)t * D_MODEL + d] = emb[id * D_MODEL + d] * EMB_SCALE;
}

__global__ void rmsnorm_kernel(const float* __restrict__ x,
                               const float* __restrict__ w,
                               float* __restrict__ o) {
    int t = blockIdx.x;
    const float* row = x + (long)t * D_MODEL;
    float ss = 0.0f;
    for (int d = threadIdx.x; d < D_MODEL; d += blockDim.x) {
        float v = row[d]; ss += v * v;
    }
    ss = block_reduce_sum(ss);
    float scale = rsqrtf(ss / (float)D_MODEL + 1e-6f);
    for (int d = threadIdx.x; d < D_MODEL; d += blockDim.x)
        o[(long)t * D_MODEL + d] = row[d] * scale * (1.0f + w[d]);
}

// x[t,:] += rms(tmp[t,:], w)
__global__ void rmsadd_kernel(float* __restrict__ x,
                              const float* __restrict__ tmp,
                              const float* __restrict__ w) {
    int t = blockIdx.x;
    const float* row = tmp + (long)t * D_MODEL;
    float ss = 0.0f;
    for (int d = threadIdx.x; d < D_MODEL; d += blockDim.x) {
        float v = row[d]; ss += v * v;
    }
    ss = block_reduce_sum(ss);
    float scale = rsqrtf(ss / (float)D_MODEL + 1e-6f);
    for (int d = threadIdx.x; d < D_MODEL; d += blockDim.x)
        x[(long)t * D_MODEL + d] += row[d] * scale * (1.0f + w[d]);
}

// per-(t, head) RMS over 256 dims + RoPE.  128 threads per block.
__global__ void qknorm_rope_kernel(float* __restrict__ q,
                                   const float* __restrict__ w,
                                   int rowstride, float base) {
    int t = blockIdx.x, h = blockIdx.y, d = threadIdx.x;  // d in [0,128)
    float* row = q + (long)t * rowstride + h * HEADDIM;
    float v1 = row[d], v2 = row[d + 128];
    float ss = block_reduce_sum(v1 * v1 + v2 * v2);
    float scale = rsqrtf(ss / (float)HEADDIM + 1e-6f);
    float q1 = v1 * scale * (1.0f + w[d]);
    float q2 = v2 * scale * (1.0f + w[d + 128]);
    float invf = powf(base, -((float)d) / 128.0f);
    float ang = (float)t * invf;
    float s, c;
    sincosf(ang, &s, &c);
    row[d]       = q1 * c - q2 * s;
    row[d + 128] = q1 * s + q2 * c;
}

// masked windowed softmax on scores row; scale 0.0625 folded in.
__global__ void softmax_kernel(float* __restrict__ S, int win) {
    int i = blockIdx.x, h = blockIdx.y;
    float* row = S + ((long)h << 20) + ((long)i << 10);
    int lo = i - win + 1; if (lo < 0) lo = 0;
    float mx = -3.0e38f;
    for (int j = lo + threadIdx.x; j <= i; j += blockDim.x)
        mx = fmaxf(mx, row[j] * 0.0625f);
    mx = block_reduce_max(mx);
    float sum = 0.0f;
    for (int j = lo + threadIdx.x; j <= i; j += blockDim.x)
        sum += expf(row[j] * 0.0625f - mx);
    sum = block_reduce_sum(sum);
    float inv = 1.0f / sum;
    for (int j = threadIdx.x; j < SEQ; j += blockDim.x) {
        float v = 0.0f;
        if (j >= lo && j <= i) v = expf(row[j] * 0.0625f - mx) * inv;
        row[j] = v;
    }
}

__global__ void gelu_mul_kernel(float* __restrict__ g, const float* __restrict__ u, int n) {
    int i = blockIdx.x * blockDim.x + threadIdx.x;
    if (i >= n) return;
    float x = g[i];
    float t = tanhf(0.7978845608028654f * (x + 0.044715f * x * x * x));
    g[i] = 0.5f * x * (1.0f + t) * u[i];
}

// -------------------- launch ------------------------------------------------
extern "C" void kernel_launch(void* const* d_in, const int* in_sizes, int n_in,
                              void* d_out, int out_size) {
    const int*   input_ids = (const int*)  d_in[0];
    const float* embed     = (const float*)d_in[1];
    const float* ln_in     = (const float*)d_in[2];
    const float* wq        = (const float*)d_in[3];
    const float* wk        = (const float*)d_in[4];
    const float* wv        = (const float*)d_in[5];
    const float* qnw       = (const float*)d_in[6];
    const float* knw       = (const float*)d_in[7];
    const float* wo        = (const float*)d_in[8];
    const float* ln_pa     = (const float*)d_in[9];
    const float* ln_pf     = (const float*)d_in[10];
    const float* wg        = (const float*)d_in[11];
    const float* wu        = (const float*)d_in[12];
    const float* wd        = (const float*)d_in[13];
    const float* ln_ff     = (const float*)d_in[14];
    const float* norm_f    = (const float*)d_in[15];
    float* out = (float*)d_out;

    float *x, *xn, *tmpd, *q, *k, *v, *sc, *ctx, *gg, *uu;
    cudaGetSymbolAddress((void**)&x,    g_x);
    cudaGetSymbolAddress((void**)&xn,   g_xn);
    cudaGetSymbolAddress((void**)&tmpd, g_tmpd);
    cudaGetSymbolAddress((void**)&q,    g_q);
    cudaGetSymbolAddress((void**)&k,    g_k);
    cudaGetSymbolAddress((void**)&v,    g_v);
    cudaGetSymbolAddress((void**)&sc,   g_scores);
    cudaGetSymbolAddress((void**)&ctx,  g_ctx);
    cudaGetSymbolAddress((void**)&gg,   g_g);
    cudaGetSymbolAddress((void**)&uu,   g_u);

    embed_kernel<<<SEQ, 256>>>(input_ids, embed, x);

    for (int l = 0; l < NLAYERS; l++) {
        const float* ln_in_l = ln_in + l * D_MODEL;
        const float* wq_l    = wq + (long)l * NHEADS * HEADDIM * D_MODEL;
        const float* wk_l    = wk + (long)l * HEADDIM * D_MODEL;
        const float* wv_l    = wv + (long)l * HEADDIM * D_MODEL;
        const float* qnw_l   = qnw + l * HEADDIM;
        const float* knw_l   = knw + l * HEADDIM;
        const float* wo_l    = wo + (long)l * D_MODEL * NHEADS * HEADDIM;
        const float* ln_pa_l = ln_pa + l * D_MODEL;
        const float* ln_pf_l = ln_pf + l * D_MODEL;
        const float* wg_l    = wg + (long)l * DFF * D_MODEL;
        const float* wu_l    = wu + (long)l * DFF * D_MODEL;
        const float* wd_l    = wd + (long)l * D_MODEL * DFF;
        const float* ln_ff_l = ln_ff + l * D_MODEL;

        bool is_global = ((l + 1) % 6) == 0;
        float base = is_global ? 1000000.0f : 10000.0f;
        int   win  = is_global ? 32768 : 512;

        // xn = rms(x)
        rmsnorm_kernel<<<SEQ, 256>>>(x, ln_in_l, xn);
        // q,k,v projections
        gemm_nt<<<dim3(16, 16, 1), 256>>>(xn, wq_l, q, D_MODEL, D_MODEL, D_MODEL, 1024, 0, 0, 0);
        gemm_nt<<<dim3(4, 16, 1),  256>>>(xn, wk_l, k, D_MODEL, D_MODEL, D_MODEL, 256, 0, 0, 0);
        gemm_nt<<<dim3(4, 16, 1),  256>>>(xn, wv_l, v, D_MODEL, D_MODEL, D_MODEL, 256, 0, 0, 0);
        // q/k RMS + RoPE
        qknorm_rope_kernel<<<dim3(SEQ, NHEADS), 128>>>(q, qnw_l, NHEADS * HEADDIM, base);
        qknorm_rope_kernel<<<dim3(SEQ, 1),      128>>>(k, knw_l, HEADDIM, base);
        // scores (batched over heads): S_h = q_h @ k^T
        gemm_nt<<<dim3(16, 16, NHEADS), 256>>>(q, k, sc, HEADDIM,
                                               1024, 256, 1024,
                                               HEADDIM, 0, (long)1 << 20);
        // masked softmax
        softmax_kernel<<<dim3(SEQ, NHEADS), 256>>>(sc, win);
        // ctx_h = S_h @ v
        gemm_nn<<<dim3(4, 16, NHEADS), 256>>>(sc, v, ctx, SEQ,
                                              1024, 256, 1024,
                                              (long)1 << 20, 0, HEADDIM);
        // attention out projection
        gemm_nt<<<dim3(10, 16, 1), 256>>>(ctx, wo_l, tmpd, NHEADS * HEADDIM,
                                          1024, 1024, D_MODEL, 0, 0, 0);
        // x += rms(attn_out)
        rmsadd_kernel<<<SEQ, 256>>>(x, tmpd, ln_pa_l);
        // x3 = rms(x)
        rmsnorm_kernel<<<SEQ, 256>>>(x, ln_pf_l, xn);
        // MLP
        gemm_nt<<<dim3(32, 16, 1), 256>>>(xn, wg_l, gg, D_MODEL, D_MODEL, D_MODEL, DFF, 0, 0, 0);
        gemm_nt<<<dim3(32, 16, 1), 256>>>(xn, wu_l, uu, D_MODEL, D_MODEL, D_MODEL, DFF, 0, 0, 0);
        gelu_mul_kernel<<<(SEQ * DFF + 255) / 256, 256>>>(gg, uu, SEQ * DFF);
        gemm_nt<<<dim3(10, 16, 1), 256>>>(gg, wd_l, tmpd, DFF, DFF, DFF, D_MODEL, 0, 0, 0);
        // x += rms(mlp_out)
        rmsadd_kernel<<<SEQ, 256>>>(x, tmpd, ln_ff_l);
    }

    // final norm + LM head
    rmsnorm_kernel<<<SEQ, 256>>>(x, norm_f, xn);
    gemm_nt<<<dim3(VOCAB / 64, 16, 1), 256>>>(xn, embed, out, D_MODEL,
                                              D_MODEL, D_MODEL, VOCAB, 0, 0, 0);
    (void)in_sizes; (void)n_in; (void)out_size;
}

// round 2
// speedup vs baseline: 2.5262x; 2.5262x over previous
#include <cuda_runtime.h>
#include <cuda_bf16.h>

// ---------------------------------------------------------------------------
// Gemma3-270M forward. All GEMMs on tensor cores: bf16x3-split mma.sync
// (m16n8k16, fp32 accum) => ~fp32 accuracy at tensor-pipe speed.
// ---------------------------------------------------------------------------

#define D_MODEL 640
#define NHEADS  4
#define HEADDIM 256
#define DFF     2048
#define NLAYERS 18
#define SEQ     1024
#define VOCAB   262144
#define EMB_SCALE 25.298221281347036f

// -------------------- scratch (device globals; no allocs) ------------------
__device__ float g_x[SEQ * D_MODEL];
__device__ float g_xn[SEQ * D_MODEL];
__device__ float g_tmpd[SEQ * D_MODEL];
__device__ float g_q[SEQ * NHEADS * HEADDIM];
__device__ float g_k[SEQ * HEADDIM];
__device__ float g_v[SEQ * HEADDIM];
__device__ float g_vt[HEADDIM * SEQ];
__device__ float g_scores[NHEADS * SEQ * SEQ];
__device__ float g_ctx[SEQ * NHEADS * HEADDIM];
__device__ float g_g[SEQ * DFF];
__device__ float g_u[SEQ * DFF];

// -------------------- reductions -------------------------------------------
__device__ __forceinline__ float block_reduce_sum(float v) {
    __shared__ float red[32];
    __syncthreads();
    int lane = threadIdx.x & 31, wid = threadIdx.x >> 5;
    #pragma unroll
    for (int o = 16; o > 0; o >>= 1) v += __shfl_down_sync(0xffffffffu, v, o);
    if (lane == 0) red[wid] = v;
    __syncthreads();
    int nw = (blockDim.x + 31) >> 5;
    v = (threadIdx.x < (unsigned)nw) ? red[threadIdx.x] : 0.0f;
    if (wid == 0) {
        #pragma unroll
        for (int o = 16; o > 0; o >>= 1) v += __shfl_down_sync(0xffffffffu, v, o);
        if (lane == 0) red[0] = v;
    }
    __syncthreads();
    return red[0];
}

__device__ __forceinline__ float block_reduce_max(float v) {
    __shared__ float redm[32];
    __syncthreads();
    int lane = threadIdx.x & 31, wid = threadIdx.x >> 5;
    #pragma unroll
    for (int o = 16; o > 0; o >>= 1) v = fmaxf(v, __shfl_down_sync(0xffffffffu, v, o));
    if (lane == 0) redm[wid] = v;
    __syncthreads();
    int nw = (blockDim.x + 31) >> 5;
    v = (threadIdx.x < (unsigned)nw) ? redm[threadIdx.x] : -3.0e38f;
    if (wid == 0) {
        #pragma unroll
        for (int o = 16; o > 0; o >>= 1) v = fmaxf(v, __shfl_down_sync(0xffffffffu, v, o));
        if (lane == 0) redm[0] = v;
    }
    __syncthreads();
    return redm[0];
}

// -------------------- bf16 split helpers ------------------------------------
__device__ __forceinline__ void split_store(__nv_bfloat16* hp, __nv_bfloat16* lp,
                                            float4 v) {
    __nv_bfloat16 h0 = __float2bfloat16(v.x);
    __nv_bfloat16 h1 = __float2bfloat16(v.y);
    __nv_bfloat16 h2 = __float2bfloat16(v.z);
    __nv_bfloat16 h3 = __float2bfloat16(v.w);
    __nv_bfloat162* hp2 = reinterpret_cast<__nv_bfloat162*>(hp);
    hp2[0] = __halves2bfloat162(h0, h1);
    hp2[1] = __halves2bfloat162(h2, h3);
    __nv_bfloat16 l0 = __float2bfloat16(v.x - __bfloat162float(h0));
    __nv_bfloat16 l1 = __float2bfloat16(v.y - __bfloat162float(h1));
    __nv_bfloat16 l2 = __float2bfloat16(v.z - __bfloat162float(h2));
    __nv_bfloat16 l3 = __float2bfloat16(v.w - __bfloat162float(h3));
    __nv_bfloat162* lp2 = reinterpret_cast<__nv_bfloat162*>(lp);
    lp2[0] = __halves2bfloat162(l0, l1);
    lp2[1] = __halves2bfloat162(l2, l3);
}

__device__ __forceinline__ void mma_bf16(float* c, const unsigned* a, const unsigned* b) {
    asm volatile(
        "mma.sync.aligned.m16n8k16.row.col.f32.bf16.bf16.f32 "
        "{%0,%1,%2,%3}, {%4,%5,%6,%7}, {%8,%9}, {%0,%1,%2,%3};\n"
        : "+f"(c[0]), "+f"(c[1]), "+f"(c[2]), "+f"(c[3])
        : "r"(a[0]), "r"(a[1]), "r"(a[2]), "r"(a[3]), "r"(b[0]), "r"(b[1]));
}

// -------------------- GEMM NT (tensor core, bf16x3): C = A @ B^T ------------
// A: [M,K] fp32 row-major, B: [N,K] fp32 row-major, C: [M,N] fp32.
// BM=128, BN=64, BK=32. 256 threads = 8 warps (4m x 2n), warp tile 32x32.
// win  > 0: block-skip for banded-causal scores (row i keeps cols [i-win+1, i]).
// kwin > 0: restrict k-loop to [m0-kwin+1, m0+BM) (ctx gemm over banded probs).
// swapxy: blockIdx.x indexes M (for LM head L2 reuse of B tiles).
__global__ void __launch_bounds__(256, 2) gemm_nt_mma(
    const float* __restrict__ A, const float* __restrict__ B, float* __restrict__ C,
    int K, int lda, int ldb, int ldc,
    long sA, long sB, long sC, int win, int kwin, int swapxy)
{
    A += (long)blockIdx.z * sA;
    B += (long)blockIdx.z * sB;
    C += (long)blockIdx.z * sC;
    const int m0 = (swapxy ? blockIdx.x : blockIdx.y) << 7;
    const int n0 = (swapxy ? blockIdx.y : blockIdx.x) << 6;
    if (win > 0) {
        if (n0 > m0 + 127) return;          // fully above causal diagonal
        if (n0 + 63 < m0 - win + 1) return; // fully below window
    }
    __shared__ __nv_bfloat16 Ah[128][40], Al[128][40], Bh[64][40], Bl[64][40];
    const int tid = threadIdx.x, lane = tid & 31, warp = tid >> 5;
    const int wm = warp >> 1, wn = warp & 1;
    const int gid = lane >> 2, tig = lane & 3;

    float acc[2][4][4];
    #pragma unroll
    for (int mt = 0; mt < 2; mt++)
        #pragma unroll
        for (int nt = 0; nt < 4; nt++)
            #pragma unroll
            for (int i = 0; i < 4; i++) acc[mt][nt][i] = 0.0f;

    int kbeg = 0, kend = K;
    if (kwin > 0) {
        kbeg = m0 - kwin + 1; if (kbeg < 0) kbeg = 0; kbeg &= ~31;
        kend = m0 + 128; if (kend > K) kend = K;
    }

    for (int k0 = kbeg; k0 < kend; k0 += 32) {
        // load A tile 128x32 fp32 -> split bf16 (4 float4 per thread)
        #pragma unroll
        for (int i = 0; i < 4; i++) {
            int idx = tid + (i << 8);
            int r = idx >> 3, c = (idx & 7) << 2;
            float4 v = *reinterpret_cast<const float4*>(A + (long)(m0 + r) * lda + k0 + c);
            split_store(&Ah[r][c], &Al[r][c], v);
        }
        // load B tile 64x32 (2 float4 per thread)
        #pragma unroll
        for (int i = 0; i < 2; i++) {
            int idx = tid + (i << 8);
            int r = idx >> 3, c = (idx & 7) << 2;
            float4 v = *reinterpret_cast<const float4*>(B + (long)(n0 + r) * ldb + k0 + c);
            split_store(&Bh[r][c], &Bl[r][c], v);
        }
        __syncthreads();
        #pragma unroll
        for (int kk = 0; kk < 2; kk++) {
            unsigned ah[2][4], al[2][4], bh[4][2], bl[4][2];
            #pragma unroll
            for (int mt = 0; mt < 2; mt++) {
                int r = (wm << 5) + (mt << 4) + gid;
                int c = (kk << 4) + (tig << 1);
                ah[mt][0] = *reinterpret_cast<const unsigned*>(&Ah[r][c]);
                ah[mt][1] = *reinterpret_cast<const unsigned*>(&Ah[r + 8][c]);
                ah[mt][2] = *reinterpret_cast<const unsigned*>(&Ah[r][c + 8]);
                ah[mt][3] = *reinterpret_cast<const unsigned*>(&Ah[r + 8][c + 8]);
                al[mt][0] = *reinterpret_cast<const unsigned*>(&Al[r][c]);
                al[mt][1] = *reinterpret_cast<const unsigned*>(&Al[r + 8][c]);
                al[mt][2] = *reinterpret_cast<const unsigned*>(&Al[r][c + 8]);
                al[mt][3] = *reinterpret_cast<const unsigned*>(&Al[r + 8][c + 8]);
            }
            #pragma unroll
            for (int nt = 0; nt < 4; nt++) {
                int r = (wn << 5) + (nt << 3) + gid;
                int c = (kk << 4) + (tig << 1);
                bh[nt][0] = *reinterpret_cast<const unsigned*>(&Bh[r][c]);
                bh[nt][1] = *reinterpret_cast<const unsigned*>(&Bh[r][c + 8]);
                bl[nt][0] = *reinterpret_cast<const unsigned*>(&Bl[r][c]);
                bl[nt][1] = *reinterpret_cast<const unsigned*>(&Bl[r][c + 8]);
            }
            #pragma unroll
            for (int mt = 0; mt < 2; mt++)
                #pragma unroll
                for (int nt = 0; nt < 4; nt++) {
                    mma_bf16(acc[mt][nt], ah[mt], bh[nt]);
                    mma_bf16(acc[mt][nt], ah[mt], bl[nt]);
                    mma_bf16(acc[mt][nt], al[mt], bh[nt]);
                }
        }
        __syncthreads();
    }
    // epilogue
    #pragma unroll
    for (int mt = 0; mt < 2; mt++) {
        int r = m0 + (wm << 5) + (mt << 4) + gid;
        #pragma unroll
        for (int nt = 0; nt < 4; nt++) {
            int cc = n0 + (wn << 5) + (nt << 3) + (tig << 1);
            *reinterpret_cast<float2*>(C + (long)r * ldc + cc) =
                make_float2(acc[mt][nt][0], acc[mt][nt][1]);
            *reinterpret_cast<float2*>(C + (long)(r + 8) * ldc + cc) =
                make_float2(acc[mt][nt][2], acc[mt][nt][3]);
        }
    }
}

// -------------------- transpose (for v) --------------------------------------
__global__ void transpose_kernel(const float* __restrict__ in, float* __restrict__ out,
                                 int rows, int cols) {
    __shared__ float tile[32][33];
    int r0 = blockIdx.y << 5, c0 = blockIdx.x << 5;
    int x = threadIdx.x, y = threadIdx.y;  // (32, 8)
    #pragma unroll
    for (int i = 0; i < 32; i += 8)
        tile[y + i][x] = in[(long)(r0 + y + i) * cols + c0 + x];
    __syncthreads();
    #pragma unroll
    for (int i = 0; i < 32; i += 8)
        out[(long)(c0 + y + i) * rows + r0 + x] = tile[x][y + i];
}

// -------------------- elementwise / norm kernels ----------------------------
__global__ void embed_kernel(const int* __restrict__ ids,
                             const float* __restrict__ emb,
                             float* __restrict__ x) {
    int t = blockIdx.x;
    long id = (long)ids[t];
    for (int d = threadIdx.x; d < D_MODEL; d += blockDim.x)
        x[(long)t * D_MODEL + d] = emb[id * D_MODEL + d] * EMB_SCALE;
}

__global__ void rmsnorm_kernel(const float* __restrict__ x,
                               const float* __restrict__ w,
                               float* __restrict__ o) {
    int t = blockIdx.x;
    const float* row = x + (long)t * D_MODEL;
    float ss = 0.0f;
    for (int d = threadIdx.x; d < D_MODEL; d += blockDim.x) {
        float v = row[d]; ss += v * v;
    }
    ss = block_reduce_sum(ss);
    float scale = rsqrtf(ss / (float)D_MODEL + 1e-6f);
    for (int d = threadIdx.x; d < D_MODEL; d += blockDim.x)
        o[(long)t * D_MODEL + d] = row[d] * scale * (1.0f + w[d]);
}

__global__ void rmsadd_kernel(float* __restrict__ x,
                              const float* __restrict__ tmp,
                              const float* __restrict__ w) {
    int t = blockIdx.x;
    const float* row = tmp + (long)t * D_MODEL;
    float ss = 0.0f;
    for (int d = threadIdx.x; d < D_MODEL; d += blockDim.x) {
        float v = row[d]; ss += v * v;
    }
    ss = block_reduce_sum(ss);
    float scale = rsqrtf(ss / (float)D_MODEL + 1e-6f);
    for (int d = threadIdx.x; d < D_MODEL; d += blockDim.x)
        x[(long)t * D_MODEL + d] += row[d] * scale * (1.0f + w[d]);
}

__global__ void qknorm_rope_kernel(float* __restrict__ q,
                                   const float* __restrict__ w,
                                   int rowstride, float base) {
    int t = blockIdx.x, h = blockIdx.y, d = threadIdx.x;  // d in [0,128)
    float* row = q + (long)t * rowstride + h * HEADDIM;
    float v1 = row[d], v2 = row[d + 128];
    float ss = block_reduce_sum(v1 * v1 + v2 * v2);
    float scale = rsqrtf(ss / (float)HEADDIM + 1e-6f);
    float q1 = v1 * scale * (1.0f + w[d]);
    float q2 = v2 * scale * (1.0f + w[d + 128]);
    float invf = powf(base, -((float)d) / 128.0f);
    float ang = (float)t * invf;
    float s, c;
    sincosf(ang, &s, &c);
    row[d]       = q1 * c - q2 * s;
    row[d + 128] = q1 * s + q2 * c;
}

// masked windowed softmax; writes only the k-range the ctx gemm will read.
__global__ void softmax_kernel(float* __restrict__ S, int win) {
    int i = blockIdx.x, h = blockIdx.y;
    float* row = S + ((long)h << 20) + ((long)i << 10);
    int lo = i - win + 1; if (lo < 0) lo = 0;
    float mx = -3.0e38f;
    for (int j = lo + threadIdx.x; j <= i; j += blockDim.x)
        mx = fmaxf(mx, row[j] * 0.0625f);
    mx = block_reduce_max(mx);
    float sum = 0.0f;
    for (int j = lo + threadIdx.x; j <= i; j += blockDim.x)
        sum += expf(row[j] * 0.0625f - mx);
    sum = block_reduce_sum(sum);
    float inv = 1.0f / sum;
    int m0 = i & ~127;
    int jlo = m0 - win + 1; if (jlo < 0) jlo = 0; jlo &= ~31;
    int jhi = m0 + 128; if (jhi > SEQ) jhi = SEQ;
    for (int j = jlo + threadIdx.x; j < jhi; j += blockDim.x) {
        float v = 0.0f;
        if (j >= lo && j <= i) v = expf(row[j] * 0.0625f - mx) * inv;
        row[j] = v;
    }
}

__global__ void gelu_mul_kernel(float* __restrict__ g, const float* __restrict__ u, int n) {
    int i = blockIdx.x * blockDim.x + threadIdx.x;
    if (i >= n) return;
    float x = g[i];
    float t = tanhf(0.7978845608028654f * (x + 0.044715f * x * x * x));
    g[i] = 0.5f * x * (1.0f + t) * u[i];
}

// -------------------- launch ------------------------------------------------
extern "C" void kernel_launch(void* const* d_in, const int* in_sizes, int n_in,
                              void* d_out, int out_size) {
    const int*   input_ids = (const int*)  d_in[0];
    const float* embed     = (const float*)d_in[1];
    const float* ln_in     = (const float*)d_in[2];
    const float* wq        = (const float*)d_in[3];
    const float* wk        = (const float*)d_in[4];
    const float* wv        = (const float*)d_in[5];
    const float* qnw       = (const float*)d_in[6];
    const float* knw       = (const float*)d_in[7];
    const float* wo        = (const float*)d_in[8];
    const float* ln_pa     = (const float*)d_in[9];
    const float* ln_pf     = (const float*)d_in[10];
    const float* wg        = (const float*)d_in[11];
    const float* wu        = (const float*)d_in[12];
    const float* wd        = (const float*)d_in[13];
    const float* ln_ff     = (const float*)d_in[14];
    const float* norm_f    = (const float*)d_in[15];
    float* out = (float*)d_out;

    float *x, *xn, *tmpd, *q, *k, *v, *vt, *sc, *ctx, *gg, *uu;
    cudaGetSymbolAddress((void**)&x,    g_x);
    cudaGetSymbolAddress((void**)&xn,   g_xn);
    cudaGetSymbolAddress((void**)&tmpd, g_tmpd);
    cudaGetSymbolAddress((void**)&q,    g_q);
    cudaGetSymbolAddress((void**)&k,    g_k);
    cudaGetSymbolAddress((void**)&v,    g_v);
    cudaGetSymbolAddress((void**)&vt,   g_vt);
    cudaGetSymbolAddress((void**)&sc,   g_scores);
    cudaGetSymbolAddress((void**)&ctx,  g_ctx);
    cudaGetSymbolAddress((void**)&gg,   g_g);
    cudaGetSymbolAddress((void**)&uu,   g_u);

    embed_kernel<<<SEQ, 256>>>(input_ids, embed, x);

    for (int l = 0; l < NLAYERS; l++) {
        const float* ln_in_l = ln_in + l * D_MODEL;
        const float* wq_l    = wq + (long)l * NHEADS * HEADDIM * D_MODEL;
        const float* wk_l    = wk + (long)l * HEADDIM * D_MODEL;
        const float* wv_l    = wv + (long)l * HEADDIM * D_MODEL;
        const float* qnw_l   = qnw + l * HEADDIM;
        const float* knw_l   = knw + l * HEADDIM;
        const float* wo_l    = wo + (long)l * D_MODEL * NHEADS * HEADDIM;
        const float* ln_pa_l = ln_pa + l * D_MODEL;
        const float* ln_pf_l = ln_pf + l * D_MODEL;
        const float* wg_l    = wg + (long)l * DFF * D_MODEL;
        const float* wu_l    = wu + (long)l * DFF * D_MODEL;
        const float* wd_l    = wd + (long)l * D_MODEL * DFF;
        const float* ln_ff_l = ln_ff + l * D_MODEL;

        bool is_global = ((l + 1) % 6) == 0;
        float base = is_global ? 1000000.0f : 10000.0f;
        int   win  = is_global ? 32768 : 512;

        // xn = rms(x)
        rmsnorm_kernel<<<SEQ, 256>>>(x, ln_in_l, xn);
        // q,k,v projections
        gemm_nt_mma<<<dim3(16, 8, 1), 256>>>(xn, wq_l, q, D_MODEL, D_MODEL, D_MODEL, 1024,
                                             0, 0, 0, -1, -1, 0);
        gemm_nt_mma<<<dim3(4, 8, 1),  256>>>(xn, wk_l, k, D_MODEL, D_MODEL, D_MODEL, 256,
                                             0, 0, 0, -1, -1, 0);
        gemm_nt_mma<<<dim3(4, 8, 1),  256>>>(xn, wv_l, v, D_MODEL, D_MODEL, D_MODEL, 256,
                                             0, 0, 0, -1, -1, 0);
        // q/k RMS + RoPE
        qknorm_rope_kernel<<<dim3(SEQ, NHEADS), 128>>>(q, qnw_l, NHEADS * HEADDIM, base);
        qknorm_rope_kernel<<<dim3(SEQ, 1),      128>>>(k, knw_l, HEADDIM, base);
        // v^T for the ctx gemm
        transpose_kernel<<<dim3(HEADDIM / 32, SEQ / 32), dim3(32, 8)>>>(v, vt, SEQ, HEADDIM);
        // scores: S_h = q_h @ k^T (banded-causal block skip)
        gemm_nt_mma<<<dim3(16, 8, NHEADS), 256>>>(q, k, sc, HEADDIM,
                                                  1024, 256, 1024,
                                                  HEADDIM, 0, (long)1 << 20, win, -1, 0);
        // masked softmax
        softmax_kernel<<<dim3(SEQ, NHEADS), 256>>>(sc, win);
        // ctx_h = P_h @ v  (= P_h @ (v^T)^T), k-range limited to the band
        gemm_nt_mma<<<dim3(4, 8, NHEADS), 256>>>(sc, vt, ctx, SEQ,
                                                 1024, 1024, 1024,
                                                 (long)1 << 20, 0, HEADDIM, -1, win, 0);
        // attention out projection
        gemm_nt_mma<<<dim3(10, 8, 1), 256>>>(ctx, wo_l, tmpd, NHEADS * HEADDIM,
                                             1024, 1024, D_MODEL, 0, 0, 0, -1, -1, 0);
        // x += rms(attn_out)
        rmsadd_kernel<<<SEQ, 256>>>(x, tmpd, ln_pa_l);
        // x3 = rms(x)
        rmsnorm_kernel<<<SEQ, 256>>>(x, ln_pf_l, xn);
        // MLP
        gemm_nt_mma<<<dim3(32, 8, 1), 256>>>(xn, wg_l, gg, D_MODEL, D_MODEL, D_MODEL, DFF,
                                             0, 0, 0, -1, -1, 0);
        gemm_nt_mma<<<dim3(32, 8, 1), 256>>>(xn, wu_l, uu, D_MODEL, D_MODEL, D_MODEL, DFF,
                                             0, 0, 0, -1, -1, 0);
        gelu_mul_kernel<<<(SEQ * DFF + 255) / 256, 256>>>(gg, uu, SEQ * DFF);
        gemm_nt_mma<<<dim3(10, 8, 1), 256>>>(gg, wd_l, tmpd, DFF, DFF, DFF, D_MODEL,
                                             0, 0, 0, -1, -1, 0);
        // x += rms(mlp_out)
        rmsadd_kernel<<<SEQ, 256>>>(x, tmpd, ln_ff_l);
    }

    // final norm + LM head (m-fastest grid for B-tile L2 reuse)
    rmsnorm_kernel<<<SEQ, 256>>>(x, norm_f, xn);
    gemm_nt_mma<<<dim3(8, VOCAB / 64, 1), 256>>>(xn, embed, out, D_MODEL,
                                                 D_MODEL, D_MODEL, VOCAB,
                                                 0, 0, 0, -1, -1, 1);
    (void)in_sizes; (void)n_in; (void)out_size;
}

// round 5
// speedup vs baseline: 2.8982x; 1.1473x over previous
#include <cuda_runtime.h>
#include <cuda_bf16.h>

#define D_MODEL 640
#define NHEADS  4
#define HEADDIM 256
#define DFF     2048
#define NLAYERS 18
#define SEQ     1024
#define VOCAB   262144
#define EMB_SCALE 25.298221281347036f

// smem tile geometry
#define PADR 40                                   // 80B row stride: 16B-aligned, ldsm conflict-free
#define STAGE_ELEMS ((128 + 128 + 64 + 64) * PADR)
#define GEMM_SMEM (2 * STAGE_ELEMS * 2)           // 61440 bytes

// -------------------- scratch (device globals) ------------------------------
// split storage: [2][rows][cols]  (plane 0 = hi, plane 1 = lo)
__device__ __align__(256) float g_x[SEQ * D_MODEL];
__device__ __align__(256) float g_tmpd[SEQ * D_MODEL];
__device__ __align__(256) __nv_bfloat16 g_xn2[2 * SEQ * D_MODEL];
__device__ __align__(256) float g_qkv[SEQ * 1536];
__device__ __align__(256) __nv_bfloat16 g_q2[2 * SEQ * 1024];
__device__ __align__(256) __nv_bfloat16 g_k2[2 * SEQ * 256];
__device__ __align__(256) __nv_bfloat16 g_vt2[2 * HEADDIM * SEQ];
__device__ __align__(256) float g_sc[NHEADS * SEQ * SEQ];
__device__ __align__(256) __nv_bfloat16 g_p2[(long)NHEADS * 2 * SEQ * SEQ];
__device__ __align__(256) __nv_bfloat16 g_ctx2[2 * SEQ * 1024];
__device__ __align__(256) float g_ggu[SEQ * 4096];
__device__ __align__(256) __nv_bfloat16 g_ga2[2 * SEQ * DFF];
__device__ __align__(256) __nv_bfloat16 g_wqkv2[(long)NLAYERS * 2 * 1536 * 640];
__device__ __align__(256) __nv_bfloat16 g_wo2[(long)NLAYERS * 2 * 640 * 1024];
__device__ __align__(256) __nv_bfloat16 g_wgu2[(long)NLAYERS * 2 * 4096 * 640];
__device__ __align__(256) __nv_bfloat16 g_wd2[(long)NLAYERS * 2 * 640 * 2048];
__device__ __align__(256) __nv_bfloat16 g_emb2[(long)2 * VOCAB * 640];

// -------------------- asm helpers -------------------------------------------
__device__ __forceinline__ void cp_async16(void* smem, const void* gmem) {
    unsigned s = (unsigned)__cvta_generic_to_shared(smem);
    asm volatile("cp.async.cg.shared.global [%0], [%1], 16;\n" :: "r"(s), "l"(gmem));
}
__device__ __forceinline__ void cp_commit() { asm volatile("cp.async.commit_group;\n"); }
template <int N> __device__ __forceinline__ void cp_wait() {
    asm volatile("cp.async.wait_group %0;\n" :: "n"(N));
}
__device__ __forceinline__ void ldsm_x4(unsigned* r, const void* p) {
    unsigned a = (unsigned)__cvta_generic_to_shared(p);
    asm volatile("ldmatrix.sync.aligned.m8n8.x4.shared.b16 {%0,%1,%2,%3}, [%4];"
                 : "=r"(r[0]), "=r"(r[1]), "=r"(r[2]), "=r"(r[3]) : "r"(a));
}
__device__ __forceinline__ void mma_bf16(float* c, const unsigned* a, const unsigned* b) {
    asm volatile(
        "mma.sync.aligned.m16n8k16.row.col.f32.bf16.bf16.f32 "
        "{%0,%1,%2,%3}, {%4,%5,%6,%7}, {%8,%9}, {%0,%1,%2,%3};\n"
        : "+f"(c[0]), "+f"(c[1]), "+f"(c[2]), "+f"(c[3])
        : "r"(a[0]), "r"(a[1]), "r"(a[2]), "r"(a[3]), "r"(b[0]), "r"(b[1]));
}
// split fp32 -> hi at p[0], lo at p[planeStride]
__device__ __forceinline__ void store_split_plane(__nv_bfloat16* p, long ps, float x) {
    __nv_bfloat16 h = __float2bfloat16(x);
    p[0]  = h;
    p[ps] = __float2bfloat16(x - __bfloat162float(h));
}

// -------------------- reductions -------------------------------------------
__device__ __forceinline__ float block_reduce_sum(float v) {
    __shared__ float red[32];
    __syncthreads();
    int lane = threadIdx.x & 31, wid = threadIdx.x >> 5;
    #pragma unroll
    for (int o = 16; o > 0; o >>= 1) v += __shfl_down_sync(0xffffffffu, v, o);
    if (lane == 0) red[wid] = v;
    __syncthreads();
    int nw = (blockDim.x + 31) >> 5;
    v = (threadIdx.x < (unsigned)nw) ? red[threadIdx.x] : 0.0f;
    if (wid == 0) {
        #pragma unroll
        for (int o = 16; o > 0; o >>= 1) v += __shfl_down_sync(0xffffffffu, v, o);
        if (lane == 0) red[0] = v;
    }
    __syncthreads();
    return red[0];
}
__device__ __forceinline__ float block_reduce_max(float v) {
    __shared__ float redm[32];
    __syncthreads();
    int lane = threadIdx.x & 31, wid = threadIdx.x >> 5;
    #pragma unroll
    for (int o = 16; o > 0; o >>= 1) v = fmaxf(v, __shfl_down_sync(0xffffffffu, v, o));
    if (lane == 0) redm[wid] = v;
    __syncthreads();
    int nw = (blockDim.x + 31) >> 5;
    v = (threadIdx.x < (unsigned)nw) ? redm[threadIdx.x] : -3.0e38f;
    if (wid == 0) {
        #pragma unroll
        for (int o = 16; o > 0; o >>= 1) v = fmaxf(v, __shfl_down_sync(0xffffffffu, v, o));
        if (lane == 0) redm[0] = v;
    }
    __syncthreads();
    return redm[0];
}

// -------------------- 3-term split bf16 GEMM: C = A @ B^T -------------------
// A: hi plane at A, lo plane at A+planeA (row-major [M][K], row stride lda).
// B likewise. acc += Ah*Bh + Ah*Bl + Al*Bh  (fp32 mma accum).
// BM=128, BN=64, BK=32, 256 threads = 8 warps (4m x 2n), warp tile 32x32.
__global__ void __launch_bounds__(256) gemm3(
    const __nv_bfloat16* __restrict__ A, const __nv_bfloat16* __restrict__ B,
    float* __restrict__ Cf, __nv_bfloat16* __restrict__ Cs,
    int K, int lda, int ldb, long planeA, long planeB,
    int ldc, long planeC,
    long sA, long sB, long sC, int win, int kwin, int swapxy)
{
    extern __shared__ __nv_bfloat16 sm[];
    A += (long)blockIdx.z * sA;
    B += (long)blockIdx.z * sB;
    if (Cf) Cf += (long)blockIdx.z * sC; else Cs += (long)blockIdx.z * sC;

    const int m0 = (swapxy ? blockIdx.x : blockIdx.y) << 7;
    const int n0 = (swapxy ? blockIdx.y : blockIdx.x) << 6;
    if (win > 0) {
        if (n0 > m0 + 127) return;
        if (n0 + 63 < m0 - win + 1) return;
    }
    const int tid = threadIdx.x, lane = tid & 31, warp = tid >> 5;
    const int wm = warp >> 1, wn = warp & 1;
    const int gid = lane >> 2, tig = lane & 3;

    int kbeg = 0, kend = K;
    if (kwin > 0) {
        kbeg = m0 - kwin + 1; if (kbeg < 0) kbeg = 0; kbeg &= ~31;
        kend = m0 + 128; if (kend > K) kend = K;
    }
    const int nk = (kend - kbeg) >> 5;

    float acc[2][4][4];
    #pragma unroll
    for (int mt = 0; mt < 2; mt++)
        #pragma unroll
        for (int nt = 0; nt < 4; nt++)
            #pragma unroll
            for (int i = 0; i < 4; i++) acc[mt][nt][i] = 0.0f;

    const __nv_bfloat16* Abase = A + (long)m0 * lda;
    const __nv_bfloat16* Bbase = B + (long)n0 * ldb;

    // tile loader: stage layout Ah[128][40] Al[128][40] Bh[64][40] Bl[64][40]
    auto load_tile = [&](int s, int k0) {
        __nv_bfloat16* st = sm + s * STAGE_ELEMS;
        const __nv_bfloat16* Ab = Abase + k0;
        #pragma unroll
        for (int i = 0; i < 2; i++) {
            int idx = tid + (i << 8);
            int r = idx >> 2, c = (idx & 3) << 3;
            cp_async16(st + r * PADR + c, Ab + (long)r * lda + c);
            cp_async16(st + 128 * PADR + r * PADR + c, Ab + planeA + (long)r * lda + c);
        }
        const __nv_bfloat16* Bb = Bbase + k0;
        {
            int r = tid >> 2, c = (tid & 3) << 3;
            cp_async16(st + 256 * PADR + r * PADR + c, Bb + (long)r * ldb + c);
            cp_async16(st + 320 * PADR + r * PADR + c, Bb + planeB + (long)r * ldb + c);
        }
        cp_commit();
    };

    load_tile(0, kbeg);

    const int arow = wm * 32 + (lane & 15);
    const int acol = (lane >> 4) << 3;
    const int brow = wn * 32 + ((lane >> 4) << 3) + (lane & 7);
    const int bcol = ((lane >> 3) & 1) << 3;

    for (int kt = 0; kt < nk; kt++) {
        if (kt + 1 < nk) {
            load_tile((kt + 1) & 1, kbeg + ((kt + 1) << 5));
            cp_wait<1>();
        } else {
            cp_wait<0>();
        }
        __syncthreads();

        const __nv_bfloat16* Ahp = sm + (kt & 1) * STAGE_ELEMS;
        const __nv_bfloat16* Alp = Ahp + 128 * PADR;
        const __nv_bfloat16* Bhp = Ahp + 256 * PADR;
        const __nv_bfloat16* Blp = Ahp + 320 * PADR;

        #pragma unroll
        for (int kk = 0; kk < 2; kk++) {
            unsigned ah[2][4], al[2][4], bh[2][4], bl[2][4];
            #pragma unroll
            for (int mt = 0; mt < 2; mt++) {
                ldsm_x4(ah[mt], Ahp + (long)(arow + mt * 16) * PADR + kk * 16 + acol);
                ldsm_x4(al[mt], Alp + (long)(arow + mt * 16) * PADR + kk * 16 + acol);
            }
            #pragma unroll
            for (int p = 0; p < 2; p++) {
                ldsm_x4(bh[p], Bhp + (long)(brow + p * 16) * PADR + kk * 16 + bcol);
                ldsm_x4(bl[p], Blp + (long)(brow + p * 16) * PADR + kk * 16 + bcol);
            }
            #pragma unroll
            for (int mt = 0; mt < 2; mt++)
                #pragma unroll
                for (int nt = 0; nt < 4; nt++) {
                    const unsigned* bhf = &bh[nt >> 1][(nt & 1) << 1];
                    const unsigned* blf = &bl[nt >> 1][(nt & 1) << 1];
                    mma_bf16(acc[mt][nt], ah[mt], bhf);
                    mma_bf16(acc[mt][nt], ah[mt], blf);
                    mma_bf16(acc[mt][nt], al[mt], bhf);
                }
        }
        __syncthreads();
    }

    // ---- epilogue ----
    #pragma unroll
    for (int mt = 0; mt < 2; mt++) {
        int r = m0 + wm * 32 + mt * 16 + gid;
        #pragma unroll
        for (int nt = 0; nt < 4; nt++) {
            int cc = n0 + wn * 32 + nt * 8 + tig * 2;
            if (Cf) {
                *reinterpret_cast<float2*>(Cf + (long)r * ldc + cc) =
                    make_float2(acc[mt][nt][0], acc[mt][nt][1]);
                *reinterpret_cast<float2*>(Cf + (long)(r + 8) * ldc + cc) =
                    make_float2(acc[mt][nt][2], acc[mt][nt][3]);
            } else {
                store_split_plane(Cs + (long)r * ldc + cc,           planeC, acc[mt][nt][0]);
                store_split_plane(Cs + (long)r * ldc + cc + 1,       planeC, acc[mt][nt][1]);
                store_split_plane(Cs + (long)(r + 8) * ldc + cc,     planeC, acc[mt][nt][2]);
                store_split_plane(Cs + (long)(r + 8) * ldc + cc + 1, planeC, acc[mt][nt][3]);
            }
        }
    }
}

// -------------------- conversion: fp32 -> split planes ----------------------
__global__ void conv_split(const float* __restrict__ src, __nv_bfloat16* __restrict__ dst,
                           long srcLS, long dstLS, long dstOff, long planeStride, int n) {
    src += (long)blockIdx.z * srcLS;
    dst += (long)blockIdx.z * dstLS + dstOff;
    int n4 = n >> 2;
    for (int i = blockIdx.x * blockDim.x + threadIdx.x; i < n4; i += gridDim.x * blockDim.x) {
        float4 v = reinterpret_cast<const float4*>(src)[i];
        __nv_bfloat16* o = dst + ((long)i << 2);
        store_split_plane(o,     planeStride, v.x);
        store_split_plane(o + 1, planeStride, v.y);
        store_split_plane(o + 2, planeStride, v.z);
        store_split_plane(o + 3, planeStride, v.w);
    }
}

// -------------------- elementwise / norm kernels ----------------------------
__global__ void embed_kernel(const int* __restrict__ ids, const float* __restrict__ emb,
                             float* __restrict__ x) {
    int t = blockIdx.x;
    long id = (long)ids[t];
    for (int d = threadIdx.x; d < D_MODEL; d += blockDim.x)
        x[(long)t * D_MODEL + d] = emb[id * D_MODEL + d] * EMB_SCALE;
}

__global__ void rmsnorm_split_kernel(const float* __restrict__ x, const float* __restrict__ w,
                                     __nv_bfloat16* __restrict__ o2, long plane) {
    int t = blockIdx.x;
    const float* row = x + (long)t * D_MODEL;
    float ss = 0.0f;
    for (int d = threadIdx.x; d < D_MODEL; d += blockDim.x) { float v = row[d]; ss += v * v; }
    ss = block_reduce_sum(ss);
    float scale = rsqrtf(ss / (float)D_MODEL + 1e-6f);
    for (int d = threadIdx.x; d < D_MODEL; d += blockDim.x)
        store_split_plane(o2 + (long)t * D_MODEL + d, plane, row[d] * scale * (1.0f + w[d]));
}

__global__ void rmsadd_kernel(float* __restrict__ x, const float* __restrict__ tmp,
                              const float* __restrict__ w) {
    int t = blockIdx.x;
    const float* row = tmp + (long)t * D_MODEL;
    float ss = 0.0f;
    for (int d = threadIdx.x; d < D_MODEL; d += blockDim.x) { float v = row[d]; ss += v * v; }
    ss = block_reduce_sum(ss);
    float scale = rsqrtf(ss / (float)D_MODEL + 1e-6f);
    for (int d = threadIdx.x; d < D_MODEL; d += blockDim.x)
        x[(long)t * D_MODEL + d] += row[d] * scale * (1.0f + w[d]);
}

// per-(t,head) rms + rope: src fp32 row stride rs; dst split planes, row stride rd
__global__ void qknorm_rope_split(const float* __restrict__ src, const float* __restrict__ w,
                                  __nv_bfloat16* __restrict__ dst, int rs, int rd,
                                  long plane, float base) {
    int t = blockIdx.x, h = blockIdx.y, d = threadIdx.x;  // d in [0,128)
    const float* row = src + (long)t * rs + h * HEADDIM;
    __nv_bfloat16* orow = dst + (long)t * rd + h * HEADDIM;
    float v1 = row[d], v2 = row[d + 128];
    float ss = block_reduce_sum(v1 * v1 + v2 * v2);
    float scale = rsqrtf(ss / (float)HEADDIM + 1e-6f);
    float q1 = v1 * scale * (1.0f + w[d]);
    float q2 = v2 * scale * (1.0f + w[d + 128]);
    float invf = powf(base, -((float)d) / 128.0f);
    float s, c;
    sincosf((float)t * invf, &s, &c);
    store_split_plane(orow + d,       plane, q1 * c - q2 * s);
    store_split_plane(orow + d + 128, plane, q1 * s + q2 * c);
}

// v [1024 x 256] (row stride rs, fp32) -> vt planes [256][1024]
__global__ void transpose_split(const float* __restrict__ in, int rs,
                                __nv_bfloat16* __restrict__ out, long plane) {
    __shared__ float tile[32][33];
    int r0 = blockIdx.y << 5, c0 = blockIdx.x << 5;
    int x = threadIdx.x, y = threadIdx.y;  // (32,8)
    #pragma unroll
    for (int i = 0; i < 32; i += 8)
        tile[y + i][x] = in[(long)(r0 + y + i) * rs + c0 + x];
    __syncthreads();
    #pragma unroll
    for (int i = 0; i < 32; i += 8)
        store_split_plane(out + (long)(c0 + y + i) * SEQ + r0 + x, plane, tile[x][y + i]);
}

// banded softmax -> split planes; fills exactly the band the ctx gemm reads
__global__ void softmax_split_kernel(const float* __restrict__ S,
                                     __nv_bfloat16* __restrict__ P, int win) {
    int i = blockIdx.x, h = blockIdx.y;
    const float* row = S + ((long)h << 20) + ((long)i << 10);
    __nv_bfloat16* prow = P + (long)h * (2 << 20) + ((long)i << 10);
    const long plane = 1 << 20;
    int lo = i - win + 1; if (lo < 0) lo = 0;
    float mx = -3.0e38f;
    for (int j = lo + threadIdx.x; j <= i; j += blockDim.x)
        mx = fmaxf(mx, row[j] * 0.0625f);
    mx = block_reduce_max(mx);
    float sum = 0.0f;
    for (int j = lo + threadIdx.x; j <= i; j += blockDim.x)
        sum += expf(row[j] * 0.0625f - mx);
    sum = block_reduce_sum(sum);
    float inv = 1.0f / sum;
    int m0 = i & ~127;
    int jlo = m0 - win + 1; if (jlo < 0) jlo = 0; jlo &= ~31;
    int jhi = m0 + 128; if (jhi > SEQ) jhi = SEQ;
    for (int j = jlo + threadIdx.x; j < jhi; j += blockDim.x) {
        float v = 0.0f;
        if (j >= lo && j <= i) v = expf(row[j] * 0.0625f - mx) * inv;
        store_split_plane(prow + j, plane, v);
    }
}

// ggu [1024][4096] (g cols 0..2047, u cols 2048..4095) -> ga planes [1024][2048]
__global__ void gelu_mul_split(const float* __restrict__ ggu,
                               __nv_bfloat16* __restrict__ out, long plane) {
    int i = blockIdx.x * blockDim.x + threadIdx.x;
    if (i >= SEQ * DFF) return;
    int t = i >> 11, c = i & 2047;
    float g = ggu[(long)t * 4096 + c];
    float u = ggu[(long)t * 4096 + 2048 + c];
    float th = tanhf(0.7978845608028654f * (g + 0.044715f * g * g * g));
    store_split_plane(out + (long)i, plane, 0.5f * g * (1.0f + th) * u);
}

// -------------------- launch ------------------------------------------------
extern "C" void kernel_launch(void* const* d_in, const int* in_sizes, int n_in,
                              void* d_out, int out_size) {
    const int*   input_ids = (const int*)  d_in[0];
    const float* embed     = (const float*)d_in[1];
    const float* ln_in     = (const float*)d_in[2];
    const float* wq        = (const float*)d_in[3];
    const float* wk        = (const float*)d_in[4];
    const float* wv        = (const float*)d_in[5];
    const float* qnw       = (const float*)d_in[6];
    const float* knw       = (const float*)d_in[7];
    const float* wo        = (const float*)d_in[8];
    const float* ln_pa     = (const float*)d_in[9];
    const float* ln_pf     = (const float*)d_in[10];
    const float* wg        = (const float*)d_in[11];
    const float* wu        = (const float*)d_in[12];
    const float* wd        = (const float*)d_in[13];
    const float* ln_ff     = (const float*)d_in[14];
    const float* norm_f    = (const float*)d_in[15];
    float* out = (float*)d_out;

    cudaFuncSetAttribute(gemm3, cudaFuncAttributeMaxDynamicSharedMemorySize, GEMM_SMEM);

    float *x, *tmpd, *qkv, *sc, *ggu;
    __nv_bfloat16 *xn2, *q2, *k2, *vt2, *p2, *ctx2, *ga2;
    __nv_bfloat16 *wqkv2, *wo2, *wgu2, *wd2, *emb2;
    cudaGetSymbolAddress((void**)&x,     g_x);
    cudaGetSymbolAddress((void**)&tmpd,  g_tmpd);
    cudaGetSymbolAddress((void**)&xn2,   g_xn2);
    cudaGetSymbolAddress((void**)&qkv,   g_qkv);
    cudaGetSymbolAddress((void**)&q2,    g_q2);
    cudaGetSymbolAddress((void**)&k2,    g_k2);
    cudaGetSymbolAddress((void**)&vt2,   g_vt2);
    cudaGetSymbolAddress((void**)&sc,    g_sc);
    cudaGetSymbolAddress((void**)&p2,    g_p2);
    cudaGetSymbolAddress((void**)&ctx2,  g_ctx2);
    cudaGetSymbolAddress((void**)&ggu,   g_ggu);
    cudaGetSymbolAddress((void**)&ga2,   g_ga2);
    cudaGetSymbolAddress((void**)&wqkv2, g_wqkv2);
    cudaGetSymbolAddress((void**)&wo2,   g_wo2);
    cudaGetSymbolAddress((void**)&wgu2,  g_wgu2);
    cudaGetSymbolAddress((void**)&wd2,   g_wd2);
    cudaGetSymbolAddress((void**)&emb2,  g_emb2);

    // plane strides
    const long pXN  = (long)SEQ * D_MODEL;          // 655360
    const long pQ   = (long)SEQ * 1024;             // q2 / ctx2 planes
    const long pK   = (long)SEQ * 256;
    const long pVT  = (long)HEADDIM * SEQ;
    const long pGA  = (long)SEQ * DFF;
    const long pQKV = (long)1536 * 640;
    const long pWO  = (long)640 * 1024;
    const long pWGU = (long)4096 * 640;
    const long pWD  = (long)640 * 2048;
    const long pEMB = (long)VOCAB * 640;

    // ---- one-time weight conversion ----
    conv_split<<<dim3(640, 1, NLAYERS), 256>>>(wq, wqkv2, 1024L*640, 2*pQKV, 0,          pQKV, 1024*640);
    conv_split<<<dim3(160, 1, NLAYERS), 256>>>(wk, wqkv2,  256L*640, 2*pQKV, 1024L*640,  pQKV,  256*640);
    conv_split<<<dim3(160, 1, NLAYERS), 256>>>(wv, wqkv2,  256L*640, 2*pQKV, 1280L*640,  pQKV,  256*640);
    conv_split<<<dim3(640, 1, NLAYERS), 256>>>(wo, wo2,    640L*1024, 2*pWO,  0,         pWO,   640*1024);
    conv_split<<<dim3(1280,1, NLAYERS), 256>>>(wg, wgu2,  2048L*640, 2*pWGU, 0,          pWGU, 2048*640);
    conv_split<<<dim3(1280,1, NLAYERS), 256>>>(wu, wgu2,  2048L*640, 2*pWGU, 2048L*640,  pWGU, 2048*640);
    conv_split<<<dim3(1280,1, NLAYERS), 256>>>(wd, wd2,    640L*2048, 2*pWD,  0,         pWD,   640*2048);
    conv_split<<<dim3(65536,1,1), 256>>>(embed, emb2, 0, 0, 0, pEMB, VOCAB * 640);

    embed_kernel<<<SEQ, 256>>>(input_ids, embed, x);

    for (int l = 0; l < NLAYERS; l++) {
        const float* ln_in_l = ln_in + l * D_MODEL;
        const float* qnw_l   = qnw + l * HEADDIM;
        const float* knw_l   = knw + l * HEADDIM;
        const float* ln_pa_l = ln_pa + l * D_MODEL;
        const float* ln_pf_l = ln_pf + l * D_MODEL;
        const float* ln_ff_l = ln_ff + l * D_MODEL;
        const __nv_bfloat16* wqkv_l = wqkv2 + (long)l * 2 * pQKV;
        const __nv_bfloat16* wo_l   = wo2   + (long)l * 2 * pWO;
        const __nv_bfloat16* wgu_l  = wgu2  + (long)l * 2 * pWGU;
        const __nv_bfloat16* wd_l   = wd2   + (long)l * 2 * pWD;

        bool is_global = ((l + 1) % 6) == 0;
        float base = is_global ? 1000000.0f : 10000.0f;
        int   win  = is_global ? 32768 : 512;

        rmsnorm_split_kernel<<<SEQ, 256>>>(x, ln_in_l, xn2, pXN);
        // qkv: [1024,1536]
        gemm3<<<dim3(24, 8), 256, GEMM_SMEM>>>(xn2, wqkv_l, qkv, nullptr,
            640, 640, 640, pXN, pQKV, 1536, 0, 0, 0, 0, -1, -1, 0);
        qknorm_rope_split<<<dim3(SEQ, NHEADS), 128>>>(qkv,        qnw_l, q2, 1536, 1024, pQ, base);
        qknorm_rope_split<<<dim3(SEQ, 1),      128>>>(qkv + 1024, knw_l, k2, 1536, 256,  pK, base);
        transpose_split<<<dim3(8, 32), dim3(32, 8)>>>(qkv + 1280, 1536, vt2, pVT);
        // scores: S_h = q_h @ k^T (banded-causal skip); per-head A col offset 256
        gemm3<<<dim3(16, 8, NHEADS), 256, GEMM_SMEM>>>(q2, k2, sc, nullptr,
            256, 1024, 256, pQ, pK, 1024, 0, 256, 0, (long)1 << 20, win, -1, 0);
        softmax_split_kernel<<<dim3(SEQ, NHEADS), 256>>>(sc, p2, win);
        // ctx_h = P_h @ v (k-band), split output at head col offset
        gemm3<<<dim3(4, 8, NHEADS), 256, GEMM_SMEM>>>(p2, vt2, nullptr, ctx2,
            1024, 1024, 1024, pQ, pVT, 1024, pQ, (long)2 << 20, 0, 256, -1, win, 0);
        // out projection
        gemm3<<<dim3(10, 8), 256, GEMM_SMEM>>>(ctx2, wo_l, tmpd, nullptr,
            1024, 1024, 1024, pQ, pWO, D_MODEL, 0, 0, 0, 0, -1, -1, 0);
        rmsadd_kernel<<<SEQ, 256>>>(x, tmpd, ln_pa_l);
        rmsnorm_split_kernel<<<SEQ, 256>>>(x, ln_pf_l, xn2, pXN);
        // fused gate+up: [1024,4096]
        gemm3<<<dim3(64, 8), 256, GEMM_SMEM>>>(xn2, wgu_l, ggu, nullptr,
            640, 640, 640, pXN, pWGU, 4096, 0, 0, 0, 0, -1, -1, 0);
        gelu_mul_split<<<(SEQ * DFF + 255) / 256, 256>>>(ggu, ga2, pGA);
        // down projection
        gemm3<<<dim3(10, 8), 256, GEMM_SMEM>>>(ga2, wd_l, tmpd, nullptr,
            2048, 2048, 2048, pGA, pWD, D_MODEL, 0, 0, 0, 0, -1, -1, 0);
        rmsadd_kernel<<<SEQ, 256>>>(x, tmpd, ln_ff_l);
    }

    // final norm + LM head (m fastest => B tiles reused in L2 across 8 m-blocks)
    rmsnorm_split_kernel<<<SEQ, 256>>>(x, norm_f, xn2, pXN);
    gemm3<<<dim3(8, VOCAB / 64), 256, GEMM_SMEM>>>(xn2, emb2, out, nullptr,
        640, 640, 640, pXN, pEMB, VOCAB, 0, 0, 0, 0, -1, -1, 1);
    (void)in_sizes; (void)n_in; (void)out_size;
}

// round 6
// speedup vs baseline: 2.9909x; 1.0320x over previous
#include <cuda_runtime.h>
#include <cuda_bf16.h>

#define D_MODEL 640
#define NHEADS  4
#define HEADDIM 256
#define DFF     2048
#define NLAYERS 18
#define SEQ     1024
#define VOCAB   262144
#define EMB_SCALE 25.298221281347036f

#define PADR 40   // smem row stride (bf16): 80B, 16B-aligned, ldsm conflict-free

// -------------------- scratch (device globals) ------------------------------
__device__ __align__(256) float g_x[SEQ * D_MODEL];
__device__ __align__(256) float g_tmpd[SEQ * D_MODEL];
__device__ __align__(256) __nv_bfloat16 g_xn2[2 * SEQ * D_MODEL];
__device__ __align__(256) float g_qkv[SEQ * 1536];
__device__ __align__(256) __nv_bfloat16 g_q2[2 * SEQ * 1024];
__device__ __align__(256) __nv_bfloat16 g_k2[2 * SEQ * 256];
__device__ __align__(256) __nv_bfloat16 g_vt2[2 * HEADDIM * SEQ];
__device__ __align__(256) float g_sc[NHEADS * SEQ * SEQ];
__device__ __align__(256) __nv_bfloat16 g_p2[(long)NHEADS * 2 * SEQ * SEQ];
__device__ __align__(256) __nv_bfloat16 g_ctx2[2 * SEQ * 1024];
__device__ __align__(256) float g_ggu[SEQ * 4096];
__device__ __align__(256) __nv_bfloat16 g_ga2[2 * SEQ * DFF];
__device__ __align__(256) __nv_bfloat16 g_wqkv2[(long)NLAYERS * 2 * 1536 * 640];
__device__ __align__(256) __nv_bfloat16 g_wo2[(long)NLAYERS * 2 * 640 * 1024];
__device__ __align__(256) __nv_bfloat16 g_wgu2[(long)NLAYERS * 2 * 4096 * 640];
__device__ __align__(256) __nv_bfloat16 g_wd2[(long)NLAYERS * 2 * 640 * 2048];

// -------------------- asm / pack helpers -------------------------------------
__device__ __forceinline__ void cp_async16(void* smem, const void* gmem) {
    unsigned s = (unsigned)__cvta_generic_to_shared(smem);
    asm volatile("cp.async.cg.shared.global [%0], [%1], 16;\n" :: "r"(s), "l"(gmem));
}
__device__ __forceinline__ void cp_commit() { asm volatile("cp.async.commit_group;\n"); }
template <int N> __device__ __forceinline__ void cp_wait() {
    asm volatile("cp.async.wait_group %0;\n" :: "n"(N));
}
__device__ __forceinline__ void ldsm_x4(unsigned* r, const void* p) {
    unsigned a = (unsigned)__cvta_generic_to_shared(p);
    asm volatile("ldmatrix.sync.aligned.m8n8.x4.shared.b16 {%0,%1,%2,%3}, [%4];"
                 : "=r"(r[0]), "=r"(r[1]), "=r"(r[2]), "=r"(r[3]) : "r"(a));
}
__device__ __forceinline__ void mma_bf16(float* c, const unsigned* a, const unsigned* b) {
    asm volatile(
        "mma.sync.aligned.m16n8k16.row.col.f32.bf16.bf16.f32 "
        "{%0,%1,%2,%3}, {%4,%5,%6,%7}, {%8,%9}, {%0,%1,%2,%3};\n"
        : "+f"(c[0]), "+f"(c[1]), "+f"(c[2]), "+f"(c[3])
        : "r"(a[0]), "r"(a[1]), "r"(a[2]), "r"(a[3]), "r"(b[0]), "r"(b[1]));
}
__device__ __forceinline__ void store_split_plane(__nv_bfloat16* p, long ps, float x) {
    __nv_bfloat16 h = __float2bfloat16(x);
    p[0]  = h;
    p[ps] = __float2bfloat16(x - __bfloat162float(h));
}
__device__ __forceinline__ unsigned pack2(__nv_bfloat16 a, __nv_bfloat16 b) {
    __nv_bfloat162 v = __halves2bfloat162(a, b);
    return *reinterpret_cast<unsigned*>(&v);
}
// split float4 -> 4 hi bf16 (uint2) + 4 lo bf16 (uint2)
__device__ __forceinline__ void split4(float4 v, uint2& hi, uint2& lo) {
    __nv_bfloat16 h0 = __float2bfloat16(v.x), h1 = __float2bfloat16(v.y);
    __nv_bfloat16 h2 = __float2bfloat16(v.z), h3 = __float2bfloat16(v.w);
    hi.x = pack2(h0, h1); hi.y = pack2(h2, h3);
    lo.x = pack2(__float2bfloat16(v.x - __bfloat162float(h0)),
                 __float2bfloat16(v.y - __bfloat162float(h1)));
    lo.y = pack2(__float2bfloat16(v.z - __bfloat162float(h2)),
                 __float2bfloat16(v.w - __bfloat162float(h3)));
}

// -------------------- reductions -------------------------------------------
__device__ __forceinline__ float block_reduce_sum(float v) {
    __shared__ float red[32];
    __syncthreads();
    int lane = threadIdx.x & 31, wid = threadIdx.x >> 5;
    #pragma unroll
    for (int o = 16; o > 0; o >>= 1) v += __shfl_down_sync(0xffffffffu, v, o);
    if (lane == 0) red[wid] = v;
    __syncthreads();
    int nw = (blockDim.x + 31) >> 5;
    v = (threadIdx.x < (unsigned)nw) ? red[threadIdx.x] : 0.0f;
    if (wid == 0) {
        #pragma unroll
        for (int o = 16; o > 0; o >>= 1) v += __shfl_down_sync(0xffffffffu, v, o);
        if (lane == 0) red[0] = v;
    }
    __syncthreads();
    return red[0];
}
__device__ __forceinline__ float block_reduce_max(float v) {
    __shared__ float redm[32];
    __syncthreads();
    int lane = threadIdx.x & 31, wid = threadIdx.x >> 5;
    #pragma unroll
    for (int o = 16; o > 0; o >>= 1) v = fmaxf(v, __shfl_down_sync(0xffffffffu, v, o));
    if (lane == 0) redm[wid] = v;
    __syncthreads();
    int nw = (blockDim.x + 31) >> 5;
    v = (threadIdx.x < (unsigned)nw) ? redm[threadIdx.x] : -3.0e38f;
    if (wid == 0) {
        #pragma unroll
        for (int o = 16; o > 0; o >>= 1) v = fmaxf(v, __shfl_down_sync(0xffffffffu, v, o));
        if (lane == 0) redm[0] = v;
    }
    __syncthreads();
    return redm[0];
}

// -------------------- 3-term split bf16 GEMM: C = A @ B^T -------------------
// acc += Ah*Bh + Ah*Bl + Al*Bh.  BM=128, BN template (64/128), BK=32.
// 256 threads = 8 warps (4m x 2n), warp tile 32 x BN/2.
// BFP32: B is fp32 (row-major [N][K]); converted to split planes in-kernel.
template <int BN, int BFP32>
__global__ void __launch_bounds__(256) gemm3(
    const __nv_bfloat16* __restrict__ A, const void* __restrict__ Bv,
    float* __restrict__ Cf, __nv_bfloat16* __restrict__ Cs,
    int K, int lda, int ldb, long planeA, long planeB,
    int ldc, long planeC,
    long sA, long sB, long sC, int win, int kwin, int swapxy)
{
    constexpr int WN   = BN / 2;      // warp n-tile
    constexpr int PCNT = WN / 16;     // ldsm groups per plane
    constexpr int NTC  = WN / 8;      // n8 tiles per warp
    constexpr int STAGE = (256 + 2 * BN) * PADR;
    extern __shared__ __nv_bfloat16 sm[];

    A += (long)blockIdx.z * sA;
    const __nv_bfloat16* B = (const __nv_bfloat16*)Bv + (BFP32 ? 0 : (long)blockIdx.z * sB);
    const float* Bf = (const float*)Bv;
    if (Cf) Cf += (long)blockIdx.z * sC; else Cs += (long)blockIdx.z * sC;

    const int m0 = (swapxy ? blockIdx.x : blockIdx.y) << 7;
    const int n0 = (swapxy ? blockIdx.y : blockIdx.x) * BN;
    if (win > 0) {
        if (n0 > m0 + 127) return;
        if (n0 + BN - 1 < m0 - win + 1) return;
    }
    const int tid = threadIdx.x, lane = tid & 31, warp = tid >> 5;
    const int wm = warp >> 1, wn = warp & 1;
    const int gid = lane >> 2, tig = lane & 3;

    int kbeg = 0, kend = K;
    if (kwin > 0) {
        kbeg = m0 - kwin + 1; if (kbeg < 0) kbeg = 0; kbeg &= ~31;
        kend = m0 + 128; if (kend > K) kend = K;
    }
    const int nk = (kend - kbeg) >> 5;

    float acc[2][NTC][4];
    #pragma unroll
    for (int mt = 0; mt < 2; mt++)
        #pragma unroll
        for (int nt = 0; nt < NTC; nt++)
            #pragma unroll
            for (int i = 0; i < 4; i++) acc[mt][nt][i] = 0.0f;

    const __nv_bfloat16* Abase = A + (long)m0 * lda;
    const __nv_bfloat16* Bbase = B + (long)n0 * ldb;

    // A loader (split bf16 planes via cp.async); B loader for split-bf16 case.
    auto load_tile = [&](int s, int k0) {
        __nv_bfloat16* st = sm + s * STAGE;
        const __nv_bfloat16* Ab = Abase + k0;
        #pragma unroll
        for (int i = 0; i < 2; i++) {
            int idx = tid + (i << 8);
            int r = idx >> 2, c = (idx & 3) << 3;
            cp_async16(st + r * PADR + c, Ab + (long)r * lda + c);
            cp_async16(st + 128 * PADR + r * PADR + c, Ab + planeA + (long)r * lda + c);
        }
        if (!BFP32) {
            const __nv_bfloat16* Bb = Bbase + k0;
            #pragma unroll
            for (int i = 0; i < BN / 64; i++) {
                int idx = tid + (i << 8);
                int r = idx >> 2, c = (idx & 3) << 3;
                cp_async16(st + 256 * PADR + r * PADR + c, Bb + (long)r * ldb + c);
                cp_async16(st + (256 + BN) * PADR + r * PADR + c, Bb + planeB + (long)r * ldb + c);
            }
        }
        cp_commit();
    };

    // fp32-B path: LDG into regs (issued a tile early), convert+STS after MMA.
    float4 breg[4];
    const int br = tid >> 1, bc16 = (tid & 1) << 4;   // row 0..127, col 0/16
    auto ldgB = [&](int k0) {
        const float4* bp = reinterpret_cast<const float4*>(
            Bf + (long)(n0 + br) * ldb + k0 + bc16);
        breg[0] = bp[0]; breg[1] = bp[1]; breg[2] = bp[2]; breg[3] = bp[3];
    };
    auto stsB = [&](int s) {
        __nv_bfloat16* Bh = sm + s * STAGE + 256 * PADR + br * PADR + bc16;
        __nv_bfloat16* Bl = Bh + BN * PADR;
        #pragma unroll
        for (int q = 0; q < 4; q++) {
            uint2 hi, lo;
            split4(breg[q], hi, lo);
            *reinterpret_cast<uint2*>(Bh + q * 4) = hi;
            *reinterpret_cast<uint2*>(Bl + q * 4) = lo;
        }
    };

    if (BFP32) ldgB(kbeg);
    load_tile(0, kbeg);
    if (BFP32) stsB(0);

    const int arow = wm * 32 + (lane & 15);
    const int acol = (lane >> 4) << 3;
    const int brow = wn * WN + ((lane >> 4) << 3) + (lane & 7);
    const int bcol = ((lane >> 3) & 1) << 3;

    for (int kt = 0; kt < nk; kt++) {
        const bool pf = (kt + 1 < nk);
        if (pf) {
            if (BFP32) ldgB(kbeg + ((kt + 1) << 5));
            load_tile((kt + 1) & 1, kbeg + ((kt + 1) << 5));
            cp_wait<1>();
        } else {
            cp_wait<0>();
        }
        __syncthreads();

        const __nv_bfloat16* Ahp = sm + (kt & 1) * STAGE;
        const __nv_bfloat16* Alp = Ahp + 128 * PADR;
        const __nv_bfloat16* Bhp = Ahp + 256 * PADR;
        const __nv_bfloat16* Blp = Ahp + (256 + BN) * PADR;

        #pragma unroll
        for (int kk = 0; kk < 2; kk++) {
            unsigned ah[2][4], al[2][4], bh[PCNT][4], bl[PCNT][4];
            #pragma unroll
            for (int mt = 0; mt < 2; mt++) {
                ldsm_x4(ah[mt], Ahp + (long)(arow + mt * 16) * PADR + kk * 16 + acol);
                ldsm_x4(al[mt], Alp + (long)(arow + mt * 16) * PADR + kk * 16 + acol);
            }
            #pragma unroll
            for (int p = 0; p < PCNT; p++) {
                ldsm_x4(bh[p], Bhp + (long)(brow + p * 16) * PADR + kk * 16 + bcol);
                ldsm_x4(bl[p], Blp + (long)(brow + p * 16) * PADR + kk * 16 + bcol);
            }
            #pragma unroll
            for (int mt = 0; mt < 2; mt++)
                #pragma unroll
                for (int nt = 0; nt < NTC; nt++) {
                    const unsigned* bhf = &bh[nt >> 1][(nt & 1) << 1];
                    const unsigned* blf = &bl[nt >> 1][(nt & 1) << 1];
                    mma_bf16(acc[mt][nt], ah[mt], bhf);
                    mma_bf16(acc[mt][nt], ah[mt], blf);
                    mma_bf16(acc[mt][nt], al[mt], bhf);
                }
        }
        if (pf && BFP32) stsB((kt + 1) & 1);
        __syncthreads();
    }

    // ---- epilogue ----
    #pragma unroll
    for (int mt = 0; mt < 2; mt++) {
        int r = m0 + wm * 32 + mt * 16 + gid;
        #pragma unroll
        for (int nt = 0; nt < NTC; nt++) {
            int cc = n0 + wn * WN + nt * 8 + tig * 2;
            if (Cf) {
                *reinterpret_cast<float2*>(Cf + (long)r * ldc + cc) =
                    make_float2(acc[mt][nt][0], acc[mt][nt][1]);
                *reinterpret_cast<float2*>(Cf + (long)(r + 8) * ldc + cc) =
                    make_float2(acc[mt][nt][2], acc[mt][nt][3]);
            } else {
                store_split_plane(Cs + (long)r * ldc + cc,           planeC, acc[mt][nt][0]);
                store_split_plane(Cs + (long)r * ldc + cc + 1,       planeC, acc[mt][nt][1]);
                store_split_plane(Cs + (long)(r + 8) * ldc + cc,     planeC, acc[mt][nt][2]);
                store_split_plane(Cs + (long)(r + 8) * ldc + cc + 1, planeC, acc[mt][nt][3]);
            }
        }
    }
}

// -------------------- conversion: fp32 -> split planes (16B stores) ---------
__global__ void conv_split(const float* __restrict__ src, __nv_bfloat16* __restrict__ dst,
                           long srcLS, long dstLS, long dstOff, long planeStride, int n) {
    src += (long)blockIdx.z * srcLS;
    dst += (long)blockIdx.z * dstLS + dstOff;
    int n8 = n >> 3;
    for (int i = blockIdx.x * blockDim.x + threadIdx.x; i < n8; i += gridDim.x * blockDim.x) {
        float4 a = reinterpret_cast<const float4*>(src)[2 * i];
        float4 b = reinterpret_cast<const float4*>(src)[2 * i + 1];
        uint2 h0, l0, h1, l1;
        split4(a, h0, l0); split4(b, h1, l1);
        uint4 hv; hv.x = h0.x; hv.y = h0.y; hv.z = h1.x; hv.w = h1.y;
        uint4 lv; lv.x = l0.x; lv.y = l0.y; lv.z = l1.x; lv.w = l1.y;
        *reinterpret_cast<uint4*>(dst + ((long)i << 3)) = hv;
        *reinterpret_cast<uint4*>(dst + planeStride + ((long)i << 3)) = lv;
    }
}

// -------------------- elementwise / norm kernels ----------------------------
__global__ void embed_kernel(const int* __restrict__ ids, const float* __restrict__ emb,
                             float* __restrict__ x) {
    int t = blockIdx.x;
    long id = (long)ids[t];
    for (int d = threadIdx.x; d < D_MODEL; d += blockDim.x)
        x[(long)t * D_MODEL + d] = emb[id * D_MODEL + d] * EMB_SCALE;
}

__global__ void rmsnorm_split_kernel(const float* __restrict__ x, const float* __restrict__ w,
                                     __nv_bfloat16* __restrict__ o2, long plane) {
    int t = blockIdx.x;
    const float* row = x + (long)t * D_MODEL;
    float ss = 0.0f;
    for (int d = threadIdx.x; d < D_MODEL; d += blockDim.x) { float v = row[d]; ss += v * v; }
    ss = block_reduce_sum(ss);
    float scale = rsqrtf(ss / (float)D_MODEL + 1e-6f);
    for (int d = threadIdx.x; d < D_MODEL; d += blockDim.x)
        store_split_plane(o2 + (long)t * D_MODEL + d, plane, row[d] * scale * (1.0f + w[d]));
}

// fused: x += rms(tmp, wa); o2 = split(rms(x, wn))    (256 threads, D=640)
__global__ void rmsadd_norm_split(float* __restrict__ x, const float* __restrict__ tmp,
                                  const float* __restrict__ wa, const float* __restrict__ wn,
                                  __nv_bfloat16* __restrict__ o2, long plane) {
    int t = blockIdx.x, tid = threadIdx.x;
    float* xr = x + (long)t * D_MODEL;
    const float* tr = tmp + (long)t * D_MODEL;
    float tv[3];
    float ss = 0.0f;
    #pragma unroll
    for (int i = 0; i < 3; i++) {
        int d = tid + (i << 8);
        if (d < D_MODEL) { tv[i] = tr[d]; ss += tv[i] * tv[i]; }
    }
    ss = block_reduce_sum(ss);
    float s1 = rsqrtf(ss / (float)D_MODEL + 1e-6f);
    float xv[3];
    ss = 0.0f;
    #pragma unroll
    for (int i = 0; i < 3; i++) {
        int d = tid + (i << 8);
        if (d < D_MODEL) {
            xv[i] = xr[d] + tv[i] * s1 * (1.0f + wa[d]);
            xr[d] = xv[i];
            ss += xv[i] * xv[i];
        }
    }
    ss = block_reduce_sum(ss);
    float s2 = rsqrtf(ss / (float)D_MODEL + 1e-6f);
    #pragma unroll
    for (int i = 0; i < 3; i++) {
        int d = tid + (i << 8);
        if (d < D_MODEL)
            store_split_plane(o2 + (long)t * D_MODEL + d, plane, xv[i] * s2 * (1.0f + wn[d]));
    }
}

__global__ void qknorm_rope_split(const float* __restrict__ src, const float* __restrict__ w,
                                  __nv_bfloat16* __restrict__ dst, int rs, int rd,
                                  long plane, float base) {
    int t = blockIdx.x, h = blockIdx.y, d = threadIdx.x;  // d in [0,128)
    const float* row = src + (long)t * rs + h * HEADDIM;
    __nv_bfloat16* orow = dst + (long)t * rd + h * HEADDIM;
    float v1 = row[d], v2 = row[d + 128];
    float ss = block_reduce_sum(v1 * v1 + v2 * v2);
    float scale = rsqrtf(ss / (float)HEADDIM + 1e-6f);
    float q1 = v1 * scale * (1.0f + w[d]);
    float q2 = v2 * scale * (1.0f + w[d + 128]);
    float invf = powf(base, -((float)d) / 128.0f);
    float s, c;
    sincosf((float)t * invf, &s, &c);
    store_split_plane(orow + d,       plane, q1 * c - q2 * s);
    store_split_plane(orow + d + 128, plane, q1 * s + q2 * c);
}

__global__ void transpose_split(const float* __restrict__ in, int rs,
                                __nv_bfloat16* __restrict__ out, long plane) {
    __shared__ float tile[32][33];
    int r0 = blockIdx.y << 5, c0 = blockIdx.x << 5;
    int x = threadIdx.x, y = threadIdx.y;  // (32,8)
    #pragma unroll
    for (int i = 0; i < 32; i += 8)
        tile[y + i][x] = in[(long)(r0 + y + i) * rs + c0 + x];
    __syncthreads();
    #pragma unroll
    for (int i = 0; i < 32; i += 8)
        store_split_plane(out + (long)(c0 + y + i) * SEQ + r0 + x, plane, tile[x][y + i]);
}

__global__ void softmax_split_kernel(const float* __restrict__ S,
                                     __nv_bfloat16* __restrict__ P, int win) {
    int i = blockIdx.x, h = blockIdx.y;
    const float* row = S + ((long)h << 20) + ((long)i << 10);
    __nv_bfloat16* prow = P + (long)h * (2 << 20) + ((long)i << 10);
    const long plane = 1 << 20;
    int lo = i - win + 1; if (lo < 0) lo = 0;
    float mx = -3.0e38f;
    for (int j = lo + threadIdx.x; j <= i; j += blockDim.x)
        mx = fmaxf(mx, row[j] * 0.0625f);
    mx = block_reduce_max(mx);
    float sum = 0.0f;
    for (int j = lo + threadIdx.x; j <= i; j += blockDim.x)
        sum += expf(row[j] * 0.0625f - mx);
    sum = block_reduce_sum(sum);
    float inv = 1.0f / sum;
    int m0 = i & ~127;
    int jlo = m0 - win + 1; if (jlo < 0) jlo = 0; jlo &= ~31;
    int jhi = m0 + 128; if (jhi > SEQ) jhi = SEQ;
    for (int j = jlo + threadIdx.x; j < jhi; j += blockDim.x) {
        float v = 0.0f;
        if (j >= lo && j <= i) v = expf(row[j] * 0.0625f - mx) * inv;
        store_split_plane(prow + j, plane, v);
    }
}

__global__ void gelu_mul_split(const float* __restrict__ ggu,
                               __nv_bfloat16* __restrict__ out, long plane) {
    int i = blockIdx.x * blockDim.x + threadIdx.x;
    if (i >= SEQ * DFF) return;
    int t = i >> 11, c = i & 2047;
    float g = ggu[(long)t * 4096 + c];
    float u = ggu[(long)t * 4096 + 2048 + c];
    float th = tanhf(0.7978845608028654f * (g + 0.044715f * g * g * g));
    store_split_plane(out + (long)i, plane, 0.5f * g * (1.0f + th) * u);
}

// -------------------- launch ------------------------------------------------
extern "C" void kernel_launch(void* const* d_in, const int* in_sizes, int n_in,
                              void* d_out, int out_size) {
    const int*   input_ids = (const int*)  d_in[0];
    const float* embed     = (const float*)d_in[1];
    const float* ln_in     = (const float*)d_in[2];
    const float* wq        = (const float*)d_in[3];
    const float* wk        = (const float*)d_in[4];
    const float* wv        = (const float*)d_in[5];
    const float* qnw       = (const float*)d_in[6];
    const float* knw       = (const float*)d_in[7];
    const float* wo        = (const float*)d_in[8];
    const float* ln_pa     = (const float*)d_in[9];
    const float* ln_pf     = (const float*)d_in[10];
    const float* wg        = (const float*)d_in[11];
    const float* wu        = (const float*)d_in[12];
    const float* wd        = (const float*)d_in[13];
    const float* ln_ff     = (const float*)d_in[14];
    const float* norm_f    = (const float*)d_in[15];
    float* out = (float*)d_out;

    const int SMEM64  = 2 * (256 + 128) * PADR * 2;   // 61440
    const int SMEM128 = 2 * (256 + 256) * PADR * 2;   // 81920
    cudaFuncSetAttribute(gemm3<64, 0>,  cudaFuncAttributeMaxDynamicSharedMemorySize, SMEM64);
    cudaFuncSetAttribute(gemm3<128, 0>, cudaFuncAttributeMaxDynamicSharedMemorySize, SMEM128);
    cudaFuncSetAttribute(gemm3<128, 1>, cudaFuncAttributeMaxDynamicSharedMemorySize, SMEM128);

    float *x, *tmpd, *qkv, *sc, *ggu;
    __nv_bfloat16 *xn2, *q2, *k2, *vt2, *p2, *ctx2, *ga2;
    __nv_bfloat16 *wqkv2, *wo2, *wgu2, *wd2;
    cudaGetSymbolAddress((void**)&x,     g_x);
    cudaGetSymbolAddress((void**)&tmpd,  g_tmpd);
    cudaGetSymbolAddress((void**)&xn2,   g_xn2);
    cudaGetSymbolAddress((void**)&qkv,   g_qkv);
    cudaGetSymbolAddress((void**)&q2,    g_q2);
    cudaGetSymbolAddress((void**)&k2,    g_k2);
    cudaGetSymbolAddress((void**)&vt2,   g_vt2);
    cudaGetSymbolAddress((void**)&sc,    g_sc);
    cudaGetSymbolAddress((void**)&p2,    g_p2);
    cudaGetSymbolAddress((void**)&ctx2,  g_ctx2);
    cudaGetSymbolAddress((void**)&ggu,   g_ggu);
    cudaGetSymbolAddress((void**)&ga2,   g_ga2);
    cudaGetSymbolAddress((void**)&wqkv2, g_wqkv2);
    cudaGetSymbolAddress((void**)&wo2,   g_wo2);
    cudaGetSymbolAddress((void**)&wgu2,  g_wgu2);
    cudaGetSymbolAddress((void**)&wd2,   g_wd2);

    // plane strides
    const long pXN  = (long)SEQ * D_MODEL;
    const long pQ   = (long)SEQ * 1024;
    const long pK   = (long)SEQ * 256;
    const long pVT  = (long)HEADDIM * SEQ;
    const long pGA  = (long)SEQ * DFF;
    const long pQKV = (long)1536 * 640;
    const long pWO  = (long)640 * 1024;
    const long pWGU = (long)4096 * 640;
    const long pWD  = (long)640 * 2048;

    // ---- one-time weight conversion (embedding NOT converted: LM head reads fp32)
    conv_split<<<dim3(320, 1, NLAYERS), 256>>>(wq, wqkv2, 1024L*640, 2*pQKV, 0,         pQKV, 1024*640);
    conv_split<<<dim3(80,  1, NLAYERS), 256>>>(wk, wqkv2,  256L*640, 2*pQKV, 1024L*640, pQKV,  256*640);
    conv_split<<<dim3(80,  1, NLAYERS), 256>>>(wv, wqkv2,  256L*640, 2*pQKV, 1280L*640, pQKV,  256*640);
    conv_split<<<dim3(320, 1, NLAYERS), 256>>>(wo, wo2,    640L*1024, 2*pWO,  0,        pWO,   640*1024);
    conv_split<<<dim3(640, 1, NLAYERS), 256>>>(wg, wgu2,  2048L*640, 2*pWGU, 0,         pWGU, 2048*640);
    conv_split<<<dim3(640, 1, NLAYERS), 256>>>(wu, wgu2,  2048L*640, 2*pWGU, 2048L*640, pWGU, 2048*640);
    conv_split<<<dim3(640, 1, NLAYERS), 256>>>(wd, wd2,    640L*2048, 2*pWD,  0,        pWD,   640*2048);

    embed_kernel<<<SEQ, 256>>>(input_ids, embed, x);
    rmsnorm_split_kernel<<<SEQ, 256>>>(x, ln_in, xn2, pXN);

    for (int l = 0; l < NLAYERS; l++) {
        const float* qnw_l   = qnw + l * HEADDIM;
        const float* knw_l   = knw + l * HEADDIM;
        const float* ln_pa_l = ln_pa + l * D_MODEL;
        const float* ln_pf_l = ln_pf + l * D_MODEL;
        const float* ln_ff_l = ln_ff + l * D_MODEL;
        const float* next_w  = (l + 1 < NLAYERS) ? (ln_in + (l + 1) * D_MODEL) : norm_f;
        const __nv_bfloat16* wqkv_l = wqkv2 + (long)l * 2 * pQKV;
        const __nv_bfloat16* wo_l   = wo2   + (long)l * 2 * pWO;
        const __nv_bfloat16* wgu_l  = wgu2  + (long)l * 2 * pWGU;
        const __nv_bfloat16* wd_l   = wd2   + (long)l * 2 * pWD;

        bool is_global = ((l + 1) % 6) == 0;
        float base = is_global ? 1000000.0f : 10000.0f;
        int   win  = is_global ? 32768 : 512;

        // qkv: [1024,1536]
        gemm3<128, 0><<<dim3(12, 8), 256, SMEM128>>>(xn2, wqkv_l, qkv, nullptr,
            640, 640, 640, pXN, pQKV, 1536, 0, 0, 0, 0, -1, -1, 0);
        qknorm_rope_split<<<dim3(SEQ, NHEADS), 128>>>(qkv,        qnw_l, q2, 1536, 1024, pQ, base);
        qknorm_rope_split<<<dim3(SEQ, 1),      128>>>(qkv + 1024, knw_l, k2, 1536, 256,  pK, base);
        transpose_split<<<dim3(8, 32), dim3(32, 8)>>>(qkv + 1280, 1536, vt2, pVT);
        // scores: S_h = q_h @ k^T (banded-causal skip)
        gemm3<64, 0><<<dim3(16, 8, NHEADS), 256, SMEM64>>>(q2, k2, sc, nullptr,
            256, 1024, 256, pQ, pK, 1024, 0, 256, 0, (long)1 << 20, win, -1, 0);
        softmax_split_kernel<<<dim3(SEQ, NHEADS), 256>>>(sc, p2, win);
        // ctx_h = P_h @ v (k-band), split output
        gemm3<64, 0><<<dim3(4, 8, NHEADS), 256, SMEM64>>>(p2, vt2, nullptr, ctx2,
            1024, 1024, 1024, pQ, pVT, 1024, pQ, (long)2 << 20, 0, 256, -1, win, 0);
        // out projection
        gemm3<64, 0><<<dim3(10, 8), 256, SMEM64>>>(ctx2, wo_l, tmpd, nullptr,
            1024, 1024, 1024, pQ, pWO, D_MODEL, 0, 0, 0, 0, -1, -1, 0);
        rmsadd_norm_split<<<SEQ, 256>>>(x, tmpd, ln_pa_l, ln_pf_l, xn2, pXN);
        // fused gate+up: [1024,4096]
        gemm3<128, 0><<<dim3(32, 8), 256, SMEM128>>>(xn2, wgu_l, ggu, nullptr,
            640, 640, 640, pXN, pWGU, 4096, 0, 0, 0, 0, -1, -1, 0);
        gelu_mul_split<<<(SEQ * DFF + 255) / 256, 256>>>(ggu, ga2, pGA);
        // down projection
        gemm3<64, 0><<<dim3(10, 8), 256, SMEM64>>>(ga2, wd_l, tmpd, nullptr,
            2048, 2048, 2048, pGA, pWD, D_MODEL, 0, 0, 0, 0, -1, -1, 0);
        // x += rms(mlp,-); xn2 = split(rms(x, next layer norm / final norm))
        rmsadd_norm_split<<<SEQ, 256>>>(x, tmpd, ln_ff_l, next_w, xn2, pXN);
    }

    // LM head: B = fp32 embedding converted in-kernel; m-fastest for L2 reuse
    gemm3<128, 1><<<dim3(8, VOCAB / 128), 256, SMEM128>>>(xn2, embed, out, nullptr,
        640, 640, 640, pXN, 0, VOCAB, 0, 0, 0, 0, -1, -1, 1);
    (void)in_sizes; (void)n_in; (void)out_size;
}

// round 8
// speedup vs baseline: 3.9869x; 1.3330x over previous
#include <cuda_runtime.h>
#include <cuda_bf16.h>
#include <cuda_fp16.h>
#include <cstdint>

#define D_MODEL 640
#define NHEADS  4
#define HEADDIM 256
#define DFF     2048
#define NLAYERS 18
#define SEQ     1024
#define VOCAB   262144
#define EMB_SCALE 25.298221281347036f

#define PADR 40   // smem row stride (bf16/fp16 elems): 80B, ldsm conflict-free

// -------------------- scratch (device globals) ------------------------------
__device__ __align__(256) float g_x[SEQ * D_MODEL];
__device__ __align__(256) float g_tmpd[SEQ * D_MODEL];
__device__ __align__(256) __nv_bfloat16 g_xn2[2 * SEQ * D_MODEL];
__device__ __align__(256) __half g_xnh[SEQ * D_MODEL];
__device__ __align__(256) float g_qkv[SEQ * 1536];
__device__ __align__(256) __nv_bfloat16 g_q2[2 * SEQ * 1024];
__device__ __align__(256) __nv_bfloat16 g_k2[2 * SEQ * 256];
__device__ __align__(256) __nv_bfloat16 g_vt2[2 * HEADDIM * SEQ];
__device__ __align__(256) float g_sc[NHEADS * SEQ * SEQ];
__device__ __align__(256) __nv_bfloat16 g_p2[(long)NHEADS * 2 * SEQ * SEQ];
__device__ __align__(256) __nv_bfloat16 g_ctx2[2 * SEQ * 1024];
__device__ __align__(256) float g_ggu[SEQ * 4096];
__device__ __align__(256) __nv_bfloat16 g_ga2[2 * SEQ * DFF];
__device__ __align__(256) __nv_bfloat16 g_wqkv2[(long)NLAYERS * 2 * 1536 * 640];
__device__ __align__(256) __nv_bfloat16 g_wo2[(long)NLAYERS * 2 * 640 * 1024];
__device__ __align__(256) __nv_bfloat16 g_wgu2[(long)NLAYERS * 2 * 4096 * 640];
__device__ __align__(256) __nv_bfloat16 g_wd2[(long)NLAYERS * 2 * 640 * 2048];
__device__ __align__(256) __half g_embh[(long)VOCAB * 640];

// -------------------- asm / pack helpers -------------------------------------
__device__ __forceinline__ unsigned smem_u32(const void* p) {
    return (unsigned)__cvta_generic_to_shared(p);
}
__device__ __forceinline__ void cp_async16(void* smem, const void* gmem) {
    asm volatile("cp.async.cg.shared.global [%0], [%1], 16;\n"
                 :: "r"(smem_u32(smem)), "l"(gmem));
}
__device__ __forceinline__ void cp_commit() { asm volatile("cp.async.commit_group;\n"); }
template <int N> __device__ __forceinline__ void cp_wait() {
    asm volatile("cp.async.wait_group %0;\n" :: "n"(N));
}
__device__ __forceinline__ void ldsm_x4(unsigned* r, const void* p) {
    asm volatile("ldmatrix.sync.aligned.m8n8.x4.shared.b16 {%0,%1,%2,%3}, [%4];"
                 : "=r"(r[0]), "=r"(r[1]), "=r"(r[2]), "=r"(r[3]) : "r"(smem_u32(p)));
}
__device__ __forceinline__ void mma_bf16(float* c, const unsigned* a, const unsigned* b) {
    asm volatile(
        "mma.sync.aligned.m16n8k16.row.col.f32.bf16.bf16.f32 "
        "{%0,%1,%2,%3}, {%4,%5,%6,%7}, {%8,%9}, {%0,%1,%2,%3};\n"
        : "+f"(c[0]), "+f"(c[1]), "+f"(c[2]), "+f"(c[3])
        : "r"(a[0]), "r"(a[1]), "r"(a[2]), "r"(a[3]), "r"(b[0]), "r"(b[1]));
}
__device__ __forceinline__ void mma_fp16(float* c, const unsigned* a, const unsigned* b) {
    asm volatile(
        "mma.sync.aligned.m16n8k16.row.col.f32.f16.f16.f32 "
        "{%0,%1,%2,%3}, {%4,%5,%6,%7}, {%8,%9}, {%0,%1,%2,%3};\n"
        : "+f"(c[0]), "+f"(c[1]), "+f"(c[2]), "+f"(c[3])
        : "r"(a[0]), "r"(a[1]), "r"(a[2]), "r"(a[3]), "r"(b[0]), "r"(b[1]));
}
__device__ __forceinline__ void store_split_plane(__nv_bfloat16* p, long ps, float x) {
    __nv_bfloat16 h = __float2bfloat16(x);
    p[0]  = h;
    p[ps] = __float2bfloat16(x - __bfloat162float(h));
}
__device__ __forceinline__ unsigned pack2(__nv_bfloat16 a, __nv_bfloat16 b) {
    __nv_bfloat162 v = __halves2bfloat162(a, b);
    return *reinterpret_cast<unsigned*>(&v);
}
__device__ __forceinline__ void split4(float4 v, uint2& hi, uint2& lo) {
    __nv_bfloat16 h0 = __float2bfloat16(v.x), h1 = __float2bfloat16(v.y);
    __nv_bfloat16 h2 = __float2bfloat16(v.z), h3 = __float2bfloat16(v.w);
    hi.x = pack2(h0, h1); hi.y = pack2(h2, h3);
    lo.x = pack2(__float2bfloat16(v.x - __bfloat162float(h0)),
                 __float2bfloat16(v.y - __bfloat162float(h1)));
    lo.y = pack2(__float2bfloat16(v.z - __bfloat162float(h2)),
                 __float2bfloat16(v.w - __bfloat162float(h3)));
}

// -------------------- reductions -------------------------------------------
__device__ __forceinline__ float block_reduce_sum(float v) {
    __shared__ float red[32];
    __syncthreads();
    int lane = threadIdx.x & 31, wid = threadIdx.x >> 5;
    #pragma unroll
    for (int o = 16; o > 0; o >>= 1) v += __shfl_down_sync(0xffffffffu, v, o);
    if (lane == 0) red[wid] = v;
    __syncthreads();
    int nw = (blockDim.x + 31) >> 5;
    v = (threadIdx.x < (unsigned)nw) ? red[threadIdx.x] : 0.0f;
    if (wid == 0) {
        #pragma unroll
        for (int o = 16; o > 0; o >>= 1) v += __shfl_down_sync(0xffffffffu, v, o);
        if (lane == 0) red[0] = v;
    }
    __syncthreads();
    return red[0];
}
__device__ __forceinline__ float block_reduce_max(float v) {
    __shared__ float redm[32];
    __syncthreads();
    int lane = threadIdx.x & 31, wid = threadIdx.x >> 5;
    #pragma unroll
    for (int o = 16; o > 0; o >>= 1) v = fmaxf(v, __shfl_down_sync(0xffffffffu, v, o));
    if (lane == 0) redm[wid] = v;
    __syncthreads();
    int nw = (blockDim.x + 31) >> 5;
    v = (threadIdx.x < (unsigned)nw) ? redm[threadIdx.x] : -3.0e38f;
    if (wid == 0) {
        #pragma unroll
        for (int o = 16; o > 0; o >>= 1) v = fmaxf(v, __shfl_down_sync(0xffffffffu, v, o));
        if (lane == 0) redm[0] = v;
    }
    __syncthreads();
    return redm[0];
}

// -------------------- 3-term split bf16 GEMM (layers): C = A @ B^T ----------
// acc += Ah*Bh + Ah*Bl + Al*Bh.  BM=128, BN template, BK=32, 8 warps (4m x 2n).
template <int BN>
__global__ void __launch_bounds__(256) gemm3(
    const __nv_bfloat16* __restrict__ A, const __nv_bfloat16* __restrict__ B,
    float* __restrict__ Cf, __nv_bfloat16* __restrict__ Cs,
    int K, int lda, int ldb, long planeA, long planeB,
    int ldc, long planeC,
    long sA, long sB, long sC, int win, int kwin)
{
    constexpr int WN   = BN / 2;
    constexpr int PCNT = WN / 16;
    constexpr int NTC  = WN / 8;
    constexpr int STAGE = (256 + 2 * BN) * PADR;
    extern __shared__ __nv_bfloat16 sm[];

    A += (long)blockIdx.z * sA;
    B += (long)blockIdx.z * sB;
    if (Cf) Cf += (long)blockIdx.z * sC; else Cs += (long)blockIdx.z * sC;

    const int m0 = blockIdx.y << 7;
    const int n0 = blockIdx.x * BN;
    if (win > 0) {
        if (n0 > m0 + 127) return;
        if (n0 + BN - 1 < m0 - win + 1) return;
    }
    const int tid = threadIdx.x, lane = tid & 31, warp = tid >> 5;
    const int wm = warp >> 1, wn = warp & 1;
    const int gid = lane >> 2, tig = lane & 3;

    int kbeg = 0, kend = K;
    if (kwin > 0) {
        kbeg = m0 - kwin + 1; if (kbeg < 0) kbeg = 0; kbeg &= ~31;
        kend = m0 + 128; if (kend > K) kend = K;
    }
    const int nk = (kend - kbeg) >> 5;

    float acc[2][NTC][4];
    #pragma unroll
    for (int mt = 0; mt < 2; mt++)
        #pragma unroll
        for (int nt = 0; nt < NTC; nt++)
            #pragma unroll
            for (int i = 0; i < 4; i++) acc[mt][nt][i] = 0.0f;

    const __nv_bfloat16* Abase = A + (long)m0 * lda;
    const __nv_bfloat16* Bbase = B + (long)n0 * ldb;

    auto load_tile = [&](int s, int k0) {
        __nv_bfloat16* st = sm + s * STAGE;
        const __nv_bfloat16* Ab = Abase + k0;
        #pragma unroll
        for (int i = 0; i < 2; i++) {
            int idx = tid + (i << 8);
            int r = idx >> 2, c = (idx & 3) << 3;
            cp_async16(st + r * PADR + c, Ab + (long)r * lda + c);
            cp_async16(st + 128 * PADR + r * PADR + c, Ab + planeA + (long)r * lda + c);
        }
        const __nv_bfloat16* Bb = Bbase + k0;
        #pragma unroll
        for (int i = 0; i < BN / 64; i++) {
            int idx = tid + (i << 8);
            int r = idx >> 2, c = (idx & 3) << 3;
            cp_async16(st + 256 * PADR + r * PADR + c, Bb + (long)r * ldb + c);
            cp_async16(st + (256 + BN) * PADR + r * PADR + c, Bb + planeB + (long)r * ldb + c);
        }
        cp_commit();
    };

    load_tile(0, kbeg);

    const int arow = wm * 32 + (lane & 15);
    const int acol = (lane >> 4) << 3;
    const int brow = wn * WN + ((lane >> 4) << 3) + (lane & 7);
    const int bcol = ((lane >> 3) & 1) << 3;

    for (int kt = 0; kt < nk; kt++) {
        const bool pf = (kt + 1 < nk);
        if (pf) {
            load_tile((kt + 1) & 1, kbeg + ((kt + 1) << 5));
            cp_wait<1>();
        } else {
            cp_wait<0>();
        }
        __syncthreads();

        const __nv_bfloat16* Ahp = sm + (kt & 1) * STAGE;
        const __nv_bfloat16* Alp = Ahp + 128 * PADR;
        const __nv_bfloat16* Bhp = Ahp + 256 * PADR;
        const __nv_bfloat16* Blp = Ahp + (256 + BN) * PADR;

        #pragma unroll
        for (int kk = 0; kk < 2; kk++) {
            unsigned ah[2][4], al[2][4], bh[PCNT][4], bl[PCNT][4];
            #pragma unroll
            for (int mt = 0; mt < 2; mt++) {
                ldsm_x4(ah[mt], Ahp + (long)(arow + mt * 16) * PADR + kk * 16 + acol);
                ldsm_x4(al[mt], Alp + (long)(arow + mt * 16) * PADR + kk * 16 + acol);
            }
            #pragma unroll
            for (int p = 0; p < PCNT; p++) {
                ldsm_x4(bh[p], Bhp + (long)(brow + p * 16) * PADR + kk * 16 + bcol);
                ldsm_x4(bl[p], Blp + (long)(brow + p * 16) * PADR + kk * 16 + bcol);
            }
            #pragma unroll
            for (int mt = 0; mt < 2; mt++)
                #pragma unroll
                for (int nt = 0; nt < NTC; nt++) {
                    const unsigned* bhf = &bh[nt >> 1][(nt & 1) << 1];
                    const unsigned* blf = &bl[nt >> 1][(nt & 1) << 1];
                    mma_bf16(acc[mt][nt], ah[mt], bhf);
                    mma_bf16(acc[mt][nt], ah[mt], blf);
                    mma_bf16(acc[mt][nt], al[mt], bhf);
                }
        }
        __syncthreads();
    }

    #pragma unroll
    for (int mt = 0; mt < 2; mt++) {
        int r = m0 + wm * 32 + mt * 16 + gid;
        #pragma unroll
        for (int nt = 0; nt < NTC; nt++) {
            int cc = n0 + wn * WN + nt * 8 + tig * 2;
            if (Cf) {
                *reinterpret_cast<float2*>(Cf + (long)r * ldc + cc) =
                    make_float2(acc[mt][nt][0], acc[mt][nt][1]);
                *reinterpret_cast<float2*>(Cf + (long)(r + 8) * ldc + cc) =
                    make_float2(acc[mt][nt][2], acc[mt][nt][3]);
            } else {
                store_split_plane(Cs + (long)r * ldc + cc,           planeC, acc[mt][nt][0]);
                store_split_plane(Cs + (long)r * ldc + cc + 1,       planeC, acc[mt][nt][1]);
                store_split_plane(Cs + (long)(r + 8) * ldc + cc,     planeC, acc[mt][nt][2]);
                store_split_plane(Cs + (long)(r + 8) * ldc + cc + 1, planeC, acc[mt][nt][3]);
            }
        }
    }
}

// -------------------- fp16 single-term LM head: C = A @ B^T -----------------
// A: [1024][640] fp16, B: [VOCAB][640] fp16, C: [1024][VOCAB] fp32.
// BM=128, BN=128, BK=32; 8 warps (4m x 2n), warp tile 32x64.
// grid: (8 m-blocks fastest, 2048 n-blocks) -> B tiles shared in L2.
__global__ void __launch_bounds__(256) lmhead_h(
    const __half* __restrict__ A, const __half* __restrict__ B, float* __restrict__ C)
{
    constexpr int STAGE = 256 * PADR;     // A 128 rows + B 128 rows
    extern __shared__ __half smh[];

    const int m0 = blockIdx.x << 7;
    const int n0 = blockIdx.y << 7;
    const int tid = threadIdx.x, lane = tid & 31, warp = tid >> 5;
    const int wm = warp >> 1, wn = warp & 1;
    const int gid = lane >> 2, tig = lane & 3;

    float acc[2][8][4];
    #pragma unroll
    for (int mt = 0; mt < 2; mt++)
        #pragma unroll
        for (int nt = 0; nt < 8; nt++)
            #pragma unroll
            for (int i = 0; i < 4; i++) acc[mt][nt][i] = 0.0f;

    const __half* Abase = A + (long)m0 * D_MODEL;
    const __half* Bbase = B + (long)n0 * D_MODEL;

    auto load_tile = [&](int s, int k0) {
        __half* st = smh + s * STAGE;
        #pragma unroll
        for (int i = 0; i < 2; i++) {
            int idx = tid + (i << 8);
            int r = idx >> 2, c = (idx & 3) << 3;
            cp_async16(st + r * PADR + c, Abase + (long)r * D_MODEL + k0 + c);
            cp_async16(st + 128 * PADR + r * PADR + c, Bbase + (long)r * D_MODEL + k0 + c);
        }
        cp_commit();
    };

    const int nk = D_MODEL / 32;   // 20
    load_tile(0, 0);

    const int arow = wm * 32 + (lane & 15);
    const int acol = (lane >> 4) << 3;
    const int brow = wn * 64 + ((lane >> 4) << 3) + (lane & 7);
    const int bcol = ((lane >> 3) & 1) << 3;

    for (int kt = 0; kt < nk; kt++) {
        const bool pf = (kt + 1 < nk);
        if (pf) {
            load_tile((kt + 1) & 1, (kt + 1) << 5);
            cp_wait<1>();
        } else {
            cp_wait<0>();
        }
        __syncthreads();

        const __half* Ap = smh + (kt & 1) * STAGE;
        const __half* Bp = Ap + 128 * PADR;

        #pragma unroll
        for (int kk = 0; kk < 2; kk++) {
            unsigned a[2][4], b[4][4];
            #pragma unroll
            for (int mt = 0; mt < 2; mt++)
                ldsm_x4(a[mt], Ap + (long)(arow + mt * 16) * PADR + kk * 16 + acol);
            #pragma unroll
            for (int p = 0; p < 4; p++)
                ldsm_x4(b[p], Bp + (long)(brow + p * 16) * PADR + kk * 16 + bcol);
            #pragma unroll
            for (int mt = 0; mt < 2; mt++)
                #pragma unroll
                for (int nt = 0; nt < 8; nt++)
                    mma_fp16(acc[mt][nt], a[mt], &b[nt >> 1][(nt & 1) << 1]);
        }
        __syncthreads();
    }

    #pragma unroll
    for (int mt = 0; mt < 2; mt++) {
        int r = m0 + wm * 32 + mt * 16 + gid;
        #pragma unroll
        for (int nt = 0; nt < 8; nt++) {
            int cc = n0 + wn * 64 + nt * 8 + tig * 2;
            *reinterpret_cast<float2*>(C + (long)r * VOCAB + cc) =
                make_float2(acc[mt][nt][0], acc[mt][nt][1]);
            *reinterpret_cast<float2*>(C + (long)(r + 8) * VOCAB + cc) =
                make_float2(acc[mt][nt][2], acc[mt][nt][3]);
        }
    }
}

// -------------------- conversions -------------------------------------------
__global__ void conv_split(const float* __restrict__ src, __nv_bfloat16* __restrict__ dst,
                           long srcLS, long dstLS, long dstOff, long planeStride, int n) {
    src += (long)blockIdx.z * srcLS;
    dst += (long)blockIdx.z * dstLS + dstOff;
    int n8 = n >> 3;
    for (int i = blockIdx.x * blockDim.x + threadIdx.x; i < n8; i += gridDim.x * blockDim.x) {
        float4 a = reinterpret_cast<const float4*>(src)[2 * i];
        float4 b = reinterpret_cast<const float4*>(src)[2 * i + 1];
        uint2 h0, l0, h1, l1;
        split4(a, h0, l0); split4(b, h1, l1);
        uint4 hv; hv.x = h0.x; hv.y = h0.y; hv.z = h1.x; hv.w = h1.y;
        uint4 lv; lv.x = l0.x; lv.y = l0.y; lv.z = l1.x; lv.w = l1.y;
        *reinterpret_cast<uint4*>(dst + ((long)i << 3)) = hv;
        *reinterpret_cast<uint4*>(dst + planeStride + ((long)i << 3)) = lv;
    }
}

__global__ void conv_half(const float* __restrict__ src, __half* __restrict__ dst, long n8) {
    for (long i = blockIdx.x * (long)blockDim.x + threadIdx.x; i < n8;
         i += (long)gridDim.x * blockDim.x) {
        float4 a = reinterpret_cast<const float4*>(src)[2 * i];
        float4 b = reinterpret_cast<const float4*>(src)[2 * i + 1];
        __half2 p0 = __floats2half2_rn(a.x, a.y);
        __half2 p1 = __floats2half2_rn(a.z, a.w);
        __half2 p2 = __floats2half2_rn(b.x, b.y);
        __half2 p3 = __floats2half2_rn(b.z, b.w);
        uint4 v;
        v.x = *reinterpret_cast<unsigned*>(&p0);
        v.y = *reinterpret_cast<unsigned*>(&p1);
        v.z = *reinterpret_cast<unsigned*>(&p2);
        v.w = *reinterpret_cast<unsigned*>(&p3);
        *reinterpret_cast<uint4*>(dst + (i << 3)) = v;
    }
}

// -------------------- elementwise / norm kernels ----------------------------
__global__ void embed_kernel(const int* __restrict__ ids, const float* __restrict__ emb,
                             float* __restrict__ x) {
    int t = blockIdx.x;
    long id = (long)ids[t];
    for (int d = threadIdx.x; d < D_MODEL; d += blockDim.x)
        x[(long)t * D_MODEL + d] = emb[id * D_MODEL + d] * EMB_SCALE;
}

__global__ void rmsnorm_split_kernel(const float* __restrict__ x, const float* __restrict__ w,
                                     __nv_bfloat16* __restrict__ o2, long plane) {
    int t = blockIdx.x;
    const float* row = x + (long)t * D_MODEL;
    float ss = 0.0f;
    for (int d = threadIdx.x; d < D_MODEL; d += blockDim.x) { float v = row[d]; ss += v * v; }
    ss = block_reduce_sum(ss);
    float scale = rsqrtf(ss / (float)D_MODEL + 1e-6f);
    for (int d = threadIdx.x; d < D_MODEL; d += blockDim.x)
        store_split_plane(o2 + (long)t * D_MODEL + d, plane, row[d] * scale * (1.0f + w[d]));
}

// fused: x += rms(tmp, wa); o2 = split(rms(x, wn)); optional fp16 copy
__global__ void rmsadd_norm_split(float* __restrict__ x, const float* __restrict__ tmp,
                                  const float* __restrict__ wa, const float* __restrict__ wn,
                                  __nv_bfloat16* __restrict__ o2, long plane,
                                  __half* __restrict__ oh) {
    int t = blockIdx.x, tid = threadIdx.x;
    float* xr = x + (long)t * D_MODEL;
    const float* tr = tmp + (long)t * D_MODEL;
    float tv[3];
    float ss = 0.0f;
    #pragma unroll
    for (int i = 0; i < 3; i++) {
        int d = tid + (i << 8);
        if (d < D_MODEL) { tv[i] = tr[d]; ss += tv[i] * tv[i]; }
    }
    ss = block_reduce_sum(ss);
    float s1 = rsqrtf(ss / (float)D_MODEL + 1e-6f);
    float xv[3];
    ss = 0.0f;
    #pragma unroll
    for (int i = 0; i < 3; i++) {
        int d = tid + (i << 8);
        if (d < D_MODEL) {
            xv[i] = xr[d] + tv[i] * s1 * (1.0f + wa[d]);
            xr[d] = xv[i];
            ss += xv[i] * xv[i];
        }
    }
    ss = block_reduce_sum(ss);
    float s2 = rsqrtf(ss / (float)D_MODEL + 1e-6f);
    #pragma unroll
    for (int i = 0; i < 3; i++) {
        int d = tid + (i << 8);
        if (d < D_MODEL) {
            float v = xv[i] * s2 * (1.0f + wn[d]);
            store_split_plane(o2 + (long)t * D_MODEL + d, plane, v);
            if (oh) oh[(long)t * D_MODEL + d] = __float2half(v);
        }
    }
}

// fused q+k rms-norm + rope: grid (SEQ, 5); h<4 -> q head h, h==4 -> k.
__global__ void qknorm_rope_fused(const float* __restrict__ qkv,
                                  const float* __restrict__ qw, const float* __restrict__ kw,
                                  __nv_bfloat16* __restrict__ q2, __nv_bfloat16* __restrict__ k2,
                                  long pQ, long pK, float base) {
    int t = blockIdx.x, h = blockIdx.y, d = threadIdx.x;  // d in [0,128)
    const float* row;
    __nv_bfloat16* orow;
    const float* w;
    long plane;
    if (h < NHEADS) {
        row = qkv + (long)t * 1536 + h * HEADDIM;
        orow = q2 + (long)t * 1024 + h * HEADDIM;
        w = qw; plane = pQ;
    } else {
        row = qkv + (long)t * 1536 + 1024;
        orow = k2 + (long)t * 256;
        w = kw; plane = pK;
    }
    float v1 = row[d], v2 = row[d + 128];
    float ss = block_reduce_sum(v1 * v1 + v2 * v2);
    float scale = rsqrtf(ss / (float)HEADDIM + 1e-6f);
    float q1 = v1 * scale * (1.0f + w[d]);
    float q2v = v2 * scale * (1.0f + w[d + 128]);
    float invf = powf(base, -((float)d) / 128.0f);
    float s, c;
    sincosf((float)t * invf, &s, &c);
    store_split_plane(orow + d,       plane, q1 * c - q2v * s);
    store_split_plane(orow + d + 128, plane, q1 * s + q2v * c);
}

__global__ void transpose_split(const float* __restrict__ in, int rs,
                                __nv_bfloat16* __restrict__ out, long plane) {
    __shared__ float tile[32][33];
    int r0 = blockIdx.y << 5, c0 = blockIdx.x << 5;
    int x = threadIdx.x, y = threadIdx.y;
    #pragma unroll
    for (int i = 0; i < 32; i += 8)
        tile[y + i][x] = in[(long)(r0 + y + i) * rs + c0 + x];
    __syncthreads();
    #pragma unroll
    for (int i = 0; i < 32; i += 8)
        store_split_plane(out + (long)(c0 + y + i) * SEQ + r0 + x, plane, tile[x][y + i]);
}

__global__ void softmax_split_kernel(const float* __restrict__ S,
                                     __nv_bfloat16* __restrict__ P, int win) {
    int i = blockIdx.x, h = blockIdx.y;
    const float* row = S + ((long)h << 20) + ((long)i << 10);
    __nv_bfloat16* prow = P + (long)h * (2 << 20) + ((long)i << 10);
    const long plane = 1 << 20;
    int lo = i - win + 1; if (lo < 0) lo = 0;
    float mx = -3.0e38f;
    for (int j = lo + threadIdx.x; j <= i; j += blockDim.x)
        mx = fmaxf(mx, row[j] * 0.0625f);
    mx = block_reduce_max(mx);
    float sum = 0.0f;
    for (int j = lo + threadIdx.x; j <= i; j += blockDim.x)
        sum += expf(row[j] * 0.0625f - mx);
    sum = block_reduce_sum(sum);
    float inv = 1.0f / sum;
    int m0 = i & ~127;
    int jlo = m0 - win + 1; if (jlo < 0) jlo = 0; jlo &= ~31;
    int jhi = m0 + 128; if (jhi > SEQ) jhi = SEQ;
    for (int j = jlo + threadIdx.x; j < jhi; j += blockDim.x) {
        float v = 0.0f;
        if (j >= lo && j <= i) v = expf(row[j] * 0.0625f - mx) * inv;
        store_split_plane(prow + j, plane, v);
    }
}

__global__ void gelu_mul_split(const float* __restrict__ ggu,
                               __nv_bfloat16* __restrict__ out, long plane) {
    int i = blockIdx.x * blockDim.x + threadIdx.x;
    if (i >= SEQ * DFF) return;
    int t = i >> 11, c = i & 2047;
    float g = ggu[(long)t * 4096 + c];
    float u = ggu[(long)t * 4096 + 2048 + c];
    float th = tanhf(0.7978845608028654f * (g + 0.044715f * g * g * g));
    store_split_plane(out + (long)i, plane, 0.5f * g * (1.0f + th) * u);
}

// -------------------- launch ------------------------------------------------
extern "C" void kernel_launch(void* const* d_in, const int* in_sizes, int n_in,
                              void* d_out, int out_size) {
    const int*   input_ids = (const int*)  d_in[0];
    const float* embed     = (const float*)d_in[1];
    const float* ln_in     = (const float*)d_in[2];
    const float* wq        = (const float*)d_in[3];
    const float* wk        = (const float*)d_in[4];
    const float* wv        = (const float*)d_in[5];
    const float* qnw       = (const float*)d_in[6];
    const float* knw       = (const float*)d_in[7];
    const float* wo        = (const float*)d_in[8];
    const float* ln_pa     = (const float*)d_in[9];
    const float* ln_pf     = (const float*)d_in[10];
    const float* wg        = (const float*)d_in[11];
    const float* wu        = (const float*)d_in[12];
    const float* wd        = (const float*)d_in[13];
    const float* ln_ff     = (const float*)d_in[14];
    const float* norm_f    = (const float*)d_in[15];
    float* out = (float*)d_out;

    const int SMEM64  = 2 * (256 + 128) * PADR * 2;
    const int SMEM128 = 2 * (256 + 256) * PADR * 2;
    const int SMEMLMH = 2 * 256 * PADR * 2;
    cudaFuncSetAttribute(gemm3<64>,  cudaFuncAttributeMaxDynamicSharedMemorySize, SMEM64);
    cudaFuncSetAttribute(gemm3<128>, cudaFuncAttributeMaxDynamicSharedMemorySize, SMEM128);
    cudaFuncSetAttribute(lmhead_h,   cudaFuncAttributeMaxDynamicSharedMemorySize, SMEMLMH);

    float *x, *tmpd, *qkv, *sc, *ggu;
    __nv_bfloat16 *xn2, *q2, *k2, *vt2, *p2, *ctx2, *ga2;
    __nv_bfloat16 *wqkv2, *wo2, *wgu2, *wd2;
    __half *xnh, *embh;
    cudaGetSymbolAddress((void**)&x,     g_x);
    cudaGetSymbolAddress((void**)&tmpd,  g_tmpd);
    cudaGetSymbolAddress((void**)&xn2,   g_xn2);
    cudaGetSymbolAddress((void**)&xnh,   g_xnh);
    cudaGetSymbolAddress((void**)&qkv,   g_qkv);
    cudaGetSymbolAddress((void**)&q2,    g_q2);
    cudaGetSymbolAddress((void**)&k2,    g_k2);
    cudaGetSymbolAddress((void**)&vt2,   g_vt2);
    cudaGetSymbolAddress((void**)&sc,    g_sc);
    cudaGetSymbolAddress((void**)&p2,    g_p2);
    cudaGetSymbolAddress((void**)&ctx2,  g_ctx2);
    cudaGetSymbolAddress((void**)&ggu,   g_ggu);
    cudaGetSymbolAddress((void**)&ga2,   g_ga2);
    cudaGetSymbolAddress((void**)&wqkv2, g_wqkv2);
    cudaGetSymbolAddress((void**)&wo2,   g_wo2);
    cudaGetSymbolAddress((void**)&wgu2,  g_wgu2);
    cudaGetSymbolAddress((void**)&wd2,   g_wd2);
    cudaGetSymbolAddress((void**)&embh,  g_embh);

    const long pXN  = (long)SEQ * D_MODEL;
    const long pQ   = (long)SEQ * 1024;
    const long pK   = (long)SEQ * 256;
    const long pVT  = (long)HEADDIM * SEQ;
    const long pGA  = (long)SEQ * DFF;
    const long pQKV = (long)1536 * 640;
    const long pWO  = (long)640 * 1024;
    const long pWGU = (long)4096 * 640;
    const long pWD  = (long)640 * 2048;

    // ---- weight conversions (bf16 split planes) + embedding (fp16) ----
    conv_split<<<dim3(320, 1, NLAYERS), 256>>>(wq, wqkv2, 1024L*640, 2*pQKV, 0,         pQKV, 1024*640);
    conv_split<<<dim3(80,  1, NLAYERS), 256>>>(wk, wqkv2,  256L*640, 2*pQKV, 1024L*640, pQKV,  256*640);
    conv_split<<<dim3(80,  1, NLAYERS), 256>>>(wv, wqkv2,  256L*640, 2*pQKV, 1280L*640, pQKV,  256*640);
    conv_split<<<dim3(320, 1, NLAYERS), 256>>>(wo, wo2,    640L*1024, 2*pWO,  0,        pWO,   640*1024);
    conv_split<<<dim3(640, 1, NLAYERS), 256>>>(wg, wgu2,  2048L*640, 2*pWGU, 0,         pWGU, 2048*640);
    conv_split<<<dim3(640, 1, NLAYERS), 256>>>(wu, wgu2,  2048L*640, 2*pWGU, 2048L*640, pWGU, 2048*640);
    conv_split<<<dim3(640, 1, NLAYERS), 256>>>(wd, wd2,    640L*2048, 2*pWD,  0,        pWD,   640*2048);
    conv_half<<<32768, 256>>>(embed, embh, (long)VOCAB * 640 / 8);

    embed_kernel<<<SEQ, 256>>>(input_ids, embed, x);
    rmsnorm_split_kernel<<<SEQ, 256>>>(x, ln_in, xn2, pXN);

    for (int l = 0; l < NLAYERS; l++) {
        const float* qnw_l   = qnw + l * HEADDIM;
        const float* knw_l   = knw + l * HEADDIM;
        const float* ln_pa_l = ln_pa + l * D_MODEL;
        const float* ln_pf_l = ln_pf + l * D_MODEL;
        const float* ln_ff_l = ln_ff + l * D_MODEL;
        const float* next_w  = (l + 1 < NLAYERS) ? (ln_in + (l + 1) * D_MODEL) : norm_f;
        const __nv_bfloat16* wqkv_l = wqkv2 + (long)l * 2 * pQKV;
        const __nv_bfloat16* wo_l   = wo2   + (long)l * 2 * pWO;
        const __nv_bfloat16* wgu_l  = wgu2  + (long)l * 2 * pWGU;
        const __nv_bfloat16* wd_l   = wd2   + (long)l * 2 * pWD;

        bool is_global = ((l + 1) % 6) == 0;
        float base = is_global ? 1000000.0f : 10000.0f;
        int   win  = is_global ? 32768 : 512;

        gemm3<128><<<dim3(12, 8), 256, SMEM128>>>(xn2, wqkv_l, qkv, nullptr,
            640, 640, 640, pXN, pQKV, 1536, 0, 0, 0, 0, -1, -1);
        qknorm_rope_fused<<<dim3(SEQ, NHEADS + 1), 128>>>(qkv, qnw_l, knw_l,
            q2, k2, pQ, pK, base);
        transpose_split<<<dim3(8, 32), dim3(32, 8)>>>(qkv + 1280, 1536, vt2, pVT);
        gemm3<64><<<dim3(16, 8, NHEADS), 256, SMEM64>>>(q2, k2, sc, nullptr,
            256, 1024, 256, pQ, pK, 1024, 0, 256, 0, (long)1 << 20, win, -1);
        softmax_split_kernel<<<dim3(SEQ, NHEADS), 256>>>(sc, p2, win);
        gemm3<64><<<dim3(4, 8, NHEADS), 256, SMEM64>>>(p2, vt2, nullptr, ctx2,
            1024, 1024, 1024, pQ, pVT, 1024, pQ, (long)2 << 20, 0, 256, -1, win);
        gemm3<64><<<dim3(10, 8), 256, SMEM64>>>(ctx2, wo_l, tmpd, nullptr,
            1024, 1024, 1024, pQ, pWO, D_MODEL, 0, 0, 0, 0, -1, -1);
        rmsadd_norm_split<<<SEQ, 256>>>(x, tmpd, ln_pa_l, ln_pf_l, xn2, pXN, nullptr);
        gemm3<128><<<dim3(32, 8), 256, SMEM128>>>(xn2, wgu_l, ggu, nullptr,
            640, 640, 640, pXN, pWGU, 4096, 0, 0, 0, 0, -1, -1);
        gelu_mul_split<<<(SEQ * DFF + 255) / 256, 256>>>(ggu, ga2, pGA);
        gemm3<64><<<dim3(10, 8), 256, SMEM64>>>(ga2, wd_l, tmpd, nullptr,
            2048, 2048, 2048, pGA, pWD, D_MODEL, 0, 0, 0, 0, -1, -1);
        rmsadd_norm_split<<<SEQ, 256>>>(x, tmpd, ln_ff_l, next_w, xn2, pXN,
            (l + 1 == NLAYERS) ? xnh : nullptr);
    }

    // LM head: single fp16 mma pass; m-blocks fastest for B-tile L2 sharing
    lmhead_h<<<dim3(8, VOCAB / 128), 256, SMEMLMH>>>(xnh, embh, out);
    (void)in_sizes; (void)n_in; (void)out_size;
}

// round 9
// speedup vs baseline: 4.0995x; 1.0283x over previous
#include <cuda_runtime.h>
#include <cuda_bf16.h>
#include <cuda_fp16.h>
#include <cstdint>

#define D_MODEL 640
#define NHEADS  4
#define HEADDIM 256
#define DFF     2048
#define NLAYERS 18
#define SEQ     1024
#define VOCAB   262144
#define EMB_SCALE 25.298221281347036f

#define PADR 40   // smem row stride (bf16/fp16 elems): 80B, ldsm conflict-free

// -------------------- scratch (device globals) ------------------------------
__device__ __align__(256) float g_x[SEQ * D_MODEL];
__device__ __align__(256) float g_tmpd[2 * SEQ * D_MODEL];       // 2 split-K slices
__device__ __align__(256) __nv_bfloat16 g_xn2[2 * SEQ * D_MODEL];
__device__ __align__(256) __half g_xnh[SEQ * D_MODEL];
__device__ __align__(256) float g_qkv[2 * SEQ * 1536];           // 2 split-K slices
__device__ __align__(256) __nv_bfloat16 g_q2[2 * SEQ * 1024];
__device__ __align__(256) __nv_bfloat16 g_k2[2 * SEQ * 256];
__device__ __align__(256) __nv_bfloat16 g_vt2[2 * HEADDIM * SEQ];
__device__ __align__(256) float g_sc[NHEADS * SEQ * SEQ];
__device__ __align__(256) __nv_bfloat16 g_p2[(long)NHEADS * 2 * SEQ * SEQ];
__device__ __align__(256) __nv_bfloat16 g_ctx2[2 * SEQ * 1024];
__device__ __align__(256) __nv_bfloat16 g_ga2[2 * SEQ * DFF];
__device__ __align__(256) __nv_bfloat16 g_wqkv2[(long)NLAYERS * 2 * 1536 * 640];
__device__ __align__(256) __nv_bfloat16 g_wo2[(long)NLAYERS * 2 * 640 * 1024];
__device__ __align__(256) __nv_bfloat16 g_wgu2[(long)NLAYERS * 2 * 4096 * 640];  // g/u row-interleaved
__device__ __align__(256) __nv_bfloat16 g_wd2[(long)NLAYERS * 2 * 640 * 2048];

// -------------------- asm / pack helpers -------------------------------------
__device__ __forceinline__ unsigned smem_u32(const void* p) {
    return (unsigned)__cvta_generic_to_shared(p);
}
__device__ __forceinline__ void cp_async16(void* smem, const void* gmem) {
    asm volatile("cp.async.cg.shared.global [%0], [%1], 16;\n"
                 :: "r"(smem_u32(smem)), "l"(gmem));
}
__device__ __forceinline__ void cp_commit() { asm volatile("cp.async.commit_group;\n"); }
template <int N> __device__ __forceinline__ void cp_wait() {
    asm volatile("cp.async.wait_group %0;\n" :: "n"(N));
}
__device__ __forceinline__ void ldsm_x4(unsigned* r, const void* p) {
    asm volatile("ldmatrix.sync.aligned.m8n8.x4.shared.b16 {%0,%1,%2,%3}, [%4];"
                 : "=r"(r[0]), "=r"(r[1]), "=r"(r[2]), "=r"(r[3]) : "r"(smem_u32(p)));
}
__device__ __forceinline__ void mma_bf16(float* c, const unsigned* a, const unsigned* b) {
    asm volatile(
        "mma.sync.aligned.m16n8k16.row.col.f32.bf16.bf16.f32 "
        "{%0,%1,%2,%3}, {%4,%5,%6,%7}, {%8,%9}, {%0,%1,%2,%3};\n"
        : "+f"(c[0]), "+f"(c[1]), "+f"(c[2]), "+f"(c[3])
        : "r"(a[0]), "r"(a[1]), "r"(a[2]), "r"(a[3]), "r"(b[0]), "r"(b[1]));
}
__device__ __forceinline__ void mma_fp16(float* c, const unsigned* a, const unsigned* b) {
    asm volatile(
        "mma.sync.aligned.m16n8k16.row.col.f32.f16.f16.f32 "
        "{%0,%1,%2,%3}, {%4,%5,%6,%7}, {%8,%9}, {%0,%1,%2,%3};\n"
        : "+f"(c[0]), "+f"(c[1]), "+f"(c[2]), "+f"(c[3])
        : "r"(a[0]), "r"(a[1]), "r"(a[2]), "r"(a[3]), "r"(b[0]), "r"(b[1]));
}
__device__ __forceinline__ void store_split_plane(__nv_bfloat16* p, long ps, float x) {
    __nv_bfloat16 h = __float2bfloat16(x);
    p[0]  = h;
    p[ps] = __float2bfloat16(x - __bfloat162float(h));
}
__device__ __forceinline__ unsigned pack2(__nv_bfloat16 a, __nv_bfloat16 b) {
    __nv_bfloat162 v = __halves2bfloat162(a, b);
    return *reinterpret_cast<unsigned*>(&v);
}
__device__ __forceinline__ void split4(float4 v, uint2& hi, uint2& lo) {
    __nv_bfloat16 h0 = __float2bfloat16(v.x), h1 = __float2bfloat16(v.y);
    __nv_bfloat16 h2 = __float2bfloat16(v.z), h3 = __float2bfloat16(v.w);
    hi.x = pack2(h0, h1); hi.y = pack2(h2, h3);
    lo.x = pack2(__float2bfloat16(v.x - __bfloat162float(h0)),
                 __float2bfloat16(v.y - __bfloat162float(h1)));
    lo.y = pack2(__float2bfloat16(v.z - __bfloat162float(h2)),
                 __float2bfloat16(v.w - __bfloat162float(h3)));
}
__device__ __forceinline__ float gelu_tanh(float g) {
    float th = tanhf(0.7978845608028654f * (g + 0.044715f * g * g * g));
    return 0.5f * g * (1.0f + th);
}

// -------------------- reductions -------------------------------------------
__device__ __forceinline__ float block_reduce_sum(float v) {
    __shared__ float red[32];
    __syncthreads();
    int lane = threadIdx.x & 31, wid = threadIdx.x >> 5;
    #pragma unroll
    for (int o = 16; o > 0; o >>= 1) v += __shfl_down_sync(0xffffffffu, v, o);
    if (lane == 0) red[wid] = v;
    __syncthreads();
    int nw = (blockDim.x + 31) >> 5;
    v = (threadIdx.x < (unsigned)nw) ? red[threadIdx.x] : 0.0f;
    if (wid == 0) {
        #pragma unroll
        for (int o = 16; o > 0; o >>= 1) v += __shfl_down_sync(0xffffffffu, v, o);
        if (lane == 0) red[0] = v;
    }
    __syncthreads();
    return red[0];
}
__device__ __forceinline__ float block_reduce_max(float v) {
    __shared__ float redm[32];
    __syncthreads();
    int lane = threadIdx.x & 31, wid = threadIdx.x >> 5;
    #pragma unroll
    for (int o = 16; o > 0; o >>= 1) v = fmaxf(v, __shfl_down_sync(0xffffffffu, v, o));
    if (lane == 0) redm[wid] = v;
    __syncthreads();
    int nw = (blockDim.x + 31) >> 5;
    v = (threadIdx.x < (unsigned)nw) ? redm[threadIdx.x] : -3.0e38f;
    if (wid == 0) {
        #pragma unroll
        for (int o = 16; o > 0; o >>= 1) v = fmaxf(v, __shfl_down_sync(0xffffffffu, v, o));
        if (lane == 0) redm[0] = v;
    }
    __syncthreads();
    return redm[0];
}

// -------------------- 3-term split bf16 GEMM: C = A @ B^T -------------------
// EPI: 0 = fp32 out (Cf), 1 = split-bf16 out (Cs), 2 = fused gelu-mul split out
//      (B rows g/u interleaved; writes gelu(c_even)*c_odd at col n/2).
// kchunk>0: split-K over gridDim.z, slice z writes Cf/Cs + z*sC.
template <int BN, int EPI>
__global__ void __launch_bounds__(256) gemm3(
    const __nv_bfloat16* __restrict__ A, const __nv_bfloat16* __restrict__ B,
    float* __restrict__ Cf, __nv_bfloat16* __restrict__ Cs,
    int K, int lda, int ldb, long planeA, long planeB,
    int ldc, long planeC,
    long sA, long sB, long sC, int win, int kwin, int kchunk)
{
    constexpr int WN   = BN / 2;
    constexpr int PCNT = WN / 16;
    constexpr int NTC  = WN / 8;
    constexpr int STAGE = (256 + 2 * BN) * PADR;
    extern __shared__ __nv_bfloat16 sm[];

    A += (long)blockIdx.z * sA;
    B += (long)blockIdx.z * sB;
    if (EPI == 0) Cf += (long)blockIdx.z * sC; else Cs += (long)blockIdx.z * sC;

    const int m0 = blockIdx.y << 7;
    const int n0 = blockIdx.x * BN;
    if (win > 0) {
        if (n0 > m0 + 127) return;
        if (n0 + BN - 1 < m0 - win + 1) return;
    }
    const int tid = threadIdx.x, lane = tid & 31, warp = tid >> 5;
    const int wm = warp >> 1, wn = warp & 1;
    const int gid = lane >> 2, tig = lane & 3;

    int kbeg = 0, kend = K;
    if (kchunk > 0) {
        kbeg = blockIdx.z * kchunk; kend = kbeg + kchunk;
    } else if (kwin > 0) {
        kbeg = m0 - kwin + 1; if (kbeg < 0) kbeg = 0; kbeg &= ~31;
        kend = m0 + 128; if (kend > K) kend = K;
    }
    const int nk = (kend - kbeg) >> 5;

    float acc[2][NTC][4];
    #pragma unroll
    for (int mt = 0; mt < 2; mt++)
        #pragma unroll
        for (int nt = 0; nt < NTC; nt++)
            #pragma unroll
            for (int i = 0; i < 4; i++) acc[mt][nt][i] = 0.0f;

    const __nv_bfloat16* Abase = A + (long)m0 * lda;
    const __nv_bfloat16* Bbase = B + (long)n0 * ldb;

    auto load_tile = [&](int s, int k0) {
        __nv_bfloat16* st = sm + s * STAGE;
        const __nv_bfloat16* Ab = Abase + k0;
        #pragma unroll
        for (int i = 0; i < 2; i++) {
            int idx = tid + (i << 8);
            int r = idx >> 2, c = (idx & 3) << 3;
            cp_async16(st + r * PADR + c, Ab + (long)r * lda + c);
            cp_async16(st + 128 * PADR + r * PADR + c, Ab + planeA + (long)r * lda + c);
        }
        const __nv_bfloat16* Bb = Bbase + k0;
        #pragma unroll
        for (int i = 0; i < BN / 64; i++) {
            int idx = tid + (i << 8);
            int r = idx >> 2, c = (idx & 3) << 3;
            cp_async16(st + 256 * PADR + r * PADR + c, Bb + (long)r * ldb + c);
            cp_async16(st + (256 + BN) * PADR + r * PADR + c, Bb + planeB + (long)r * ldb + c);
        }
        cp_commit();
    };

    load_tile(0, kbeg);

    const int arow = wm * 32 + (lane & 15);
    const int acol = (lane >> 4) << 3;
    const int brow = wn * WN + ((lane >> 4) << 3) + (lane & 7);
    const int bcol = ((lane >> 3) & 1) << 3;

    for (int kt = 0; kt < nk; kt++) {
        const bool pf = (kt + 1 < nk);
        if (pf) {
            load_tile((kt + 1) & 1, kbeg + ((kt + 1) << 5));
            cp_wait<1>();
        } else {
            cp_wait<0>();
        }
        __syncthreads();

        const __nv_bfloat16* Ahp = sm + (kt & 1) * STAGE;
        const __nv_bfloat16* Alp = Ahp + 128 * PADR;
        const __nv_bfloat16* Bhp = Ahp + 256 * PADR;
        const __nv_bfloat16* Blp = Ahp + (256 + BN) * PADR;

        #pragma unroll
        for (int kk = 0; kk < 2; kk++) {
            unsigned ah[2][4], al[2][4], bh[PCNT][4], bl[PCNT][4];
            #pragma unroll
            for (int mt = 0; mt < 2; mt++) {
                ldsm_x4(ah[mt], Ahp + (long)(arow + mt * 16) * PADR + kk * 16 + acol);
                ldsm_x4(al[mt], Alp + (long)(arow + mt * 16) * PADR + kk * 16 + acol);
            }
            #pragma unroll
            for (int p = 0; p < PCNT; p++) {
                ldsm_x4(bh[p], Bhp + (long)(brow + p * 16) * PADR + kk * 16 + bcol);
                ldsm_x4(bl[p], Blp + (long)(brow + p * 16) * PADR + kk * 16 + bcol);
            }
            #pragma unroll
            for (int mt = 0; mt < 2; mt++)
                #pragma unroll
                for (int nt = 0; nt < NTC; nt++) {
                    const unsigned* bhf = &bh[nt >> 1][(nt & 1) << 1];
                    const unsigned* blf = &bl[nt >> 1][(nt & 1) << 1];
                    mma_bf16(acc[mt][nt], ah[mt], bhf);
                    mma_bf16(acc[mt][nt], ah[mt], blf);
                    mma_bf16(acc[mt][nt], al[mt], bhf);
                }
        }
        __syncthreads();
    }

    #pragma unroll
    for (int mt = 0; mt < 2; mt++) {
        int r = m0 + wm * 32 + mt * 16 + gid;
        #pragma unroll
        for (int nt = 0; nt < NTC; nt++) {
            int cc = n0 + wn * WN + nt * 8 + tig * 2;
            if (EPI == 0) {
                *reinterpret_cast<float2*>(Cf + (long)r * ldc + cc) =
                    make_float2(acc[mt][nt][0], acc[mt][nt][1]);
                *reinterpret_cast<float2*>(Cf + (long)(r + 8) * ldc + cc) =
                    make_float2(acc[mt][nt][2], acc[mt][nt][3]);
            } else if (EPI == 1) {
                store_split_plane(Cs + (long)r * ldc + cc,           planeC, acc[mt][nt][0]);
                store_split_plane(Cs + (long)r * ldc + cc + 1,       planeC, acc[mt][nt][1]);
                store_split_plane(Cs + (long)(r + 8) * ldc + cc,     planeC, acc[mt][nt][2]);
                store_split_plane(Cs + (long)(r + 8) * ldc + cc + 1, planeC, acc[mt][nt][3]);
            } else {
                int f = cc >> 1;  // interleaved (g,u) pair -> one output col
                store_split_plane(Cs + (long)r * ldc + f, planeC,
                                  gelu_tanh(acc[mt][nt][0]) * acc[mt][nt][1]);
                store_split_plane(Cs + (long)(r + 8) * ldc + f, planeC,
                                  gelu_tanh(acc[mt][nt][2]) * acc[mt][nt][3]);
            }
        }
    }
}

// -------------------- fp16 LM head: C = A @ B^T, B fp32 converted in-kernel --
// A: [1024][640] fp16, B: [VOCAB][640] fp32, C: [1024][VOCAB] fp32.
// BM=128, BN=128, BK=32; 8 warps (4m x 2n), warp tile 32x64.
__global__ void __launch_bounds__(256) lmhead_h(
    const __half* __restrict__ A, const float* __restrict__ Bf, float* __restrict__ C)
{
    constexpr int STAGE = 256 * PADR;     // A 128 rows + B 128 rows
    extern __shared__ __half smh[];

    const int m0 = blockIdx.x << 7;
    const int n0 = blockIdx.y << 7;
    const int tid = threadIdx.x, lane = tid & 31, warp = tid >> 5;
    const int wm = warp >> 1, wn = warp & 1;
    const int gid = lane >> 2, tig = lane & 3;

    float acc[2][8][4];
    #pragma unroll
    for (int mt = 0; mt < 2; mt++)
        #pragma unroll
        for (int nt = 0; nt < 8; nt++)
            #pragma unroll
            for (int i = 0; i < 4; i++) acc[mt][nt][i] = 0.0f;

    const __half* Abase = A + (long)m0 * D_MODEL;

    auto load_tileA = [&](int s, int k0) {
        __half* st = smh + s * STAGE;
        #pragma unroll
        for (int i = 0; i < 2; i++) {
            int idx = tid + (i << 8);
            int r = idx >> 2, c = (idx & 3) << 3;
            cp_async16(st + r * PADR + c, Abase + (long)r * D_MODEL + k0 + c);
        }
        cp_commit();
    };

    // B fp32 -> regs (issued a tile early) -> fp16 smem after MMA block.
    float4 breg[4];
    const int br = tid >> 1, bc16 = (tid & 1) << 4;
    auto ldgB = [&](int k0) {
        const float4* bp = reinterpret_cast<const float4*>(
            Bf + (long)(n0 + br) * D_MODEL + k0 + bc16);
        breg[0] = bp[0]; breg[1] = bp[1]; breg[2] = bp[2]; breg[3] = bp[3];
    };
    auto stsB = [&](int s) {
        __half* Bh = smh + s * STAGE + 128 * PADR + br * PADR + bc16;
        #pragma unroll
        for (int q = 0; q < 4; q++) {
            __half2 p0 = __floats2half2_rn(breg[q].x, breg[q].y);
            __half2 p1 = __floats2half2_rn(breg[q].z, breg[q].w);
            uint2 v;
            v.x = *reinterpret_cast<unsigned*>(&p0);
            v.y = *reinterpret_cast<unsigned*>(&p1);
            *reinterpret_cast<uint2*>(Bh + q * 4) = v;
        }
    };

    const int nk = D_MODEL / 32;   // 20
    ldgB(0);
    load_tileA(0, 0);
    stsB(0);

    const int arow = wm * 32 + (lane & 15);
    const int acol = (lane >> 4) << 3;
    const int brow = wn * 64 + ((lane >> 4) << 3) + (lane & 7);
    const int bcol = ((lane >> 3) & 1) << 3;

    for (int kt = 0; kt < nk; kt++) {
        const bool pf = (kt + 1 < nk);
        if (pf) {
            ldgB((kt + 1) << 5);
            load_tileA((kt + 1) & 1, (kt + 1) << 5);
            cp_wait<1>();
        } else {
            cp_wait<0>();
        }
        __syncthreads();

        const __half* Ap = smh + (kt & 1) * STAGE;
        const __half* Bp = Ap + 128 * PADR;

        #pragma unroll
        for (int kk = 0; kk < 2; kk++) {
            unsigned a[2][4], b[4][4];
            #pragma unroll
            for (int mt = 0; mt < 2; mt++)
                ldsm_x4(a[mt], Ap + (long)(arow + mt * 16) * PADR + kk * 16 + acol);
            #pragma unroll
            for (int p = 0; p < 4; p++)
                ldsm_x4(b[p], Bp + (long)(brow + p * 16) * PADR + kk * 16 + bcol);
            #pragma unroll
            for (int mt = 0; mt < 2; mt++)
                #pragma unroll
                for (int nt = 0; nt < 8; nt++)
                    mma_fp16(acc[mt][nt], a[mt], &b[nt >> 1][(nt & 1) << 1]);
        }
        if (pf) stsB((kt + 1) & 1);
        __syncthreads();
    }

    #pragma unroll
    for (int mt = 0; mt < 2; mt++) {
        int r = m0 + wm * 32 + mt * 16 + gid;
        #pragma unroll
        for (int nt = 0; nt < 8; nt++) {
            int cc = n0 + wn * 64 + nt * 8 + tig * 2;
            *reinterpret_cast<float2*>(C + (long)r * VOCAB + cc) =
                make_float2(acc[mt][nt][0], acc[mt][nt][1]);
            *reinterpret_cast<float2*>(C + (long)(r + 8) * VOCAB + cc) =
                make_float2(acc[mt][nt][2], acc[mt][nt][3]);
        }
    }
}

// -------------------- conversions -------------------------------------------
__global__ void conv_split(const float* __restrict__ src, __nv_bfloat16* __restrict__ dst,
                           long srcLS, long dstLS, long dstOff, long planeStride, int n) {
    src += (long)blockIdx.z * srcLS;
    dst += (long)blockIdx.z * dstLS + dstOff;
    int n8 = n >> 3;
    for (int i = blockIdx.x * blockDim.x + threadIdx.x; i < n8; i += gridDim.x * blockDim.x) {
        float4 a = reinterpret_cast<const float4*>(src)[2 * i];
        float4 b = reinterpret_cast<const float4*>(src)[2 * i + 1];
        uint2 h0, l0, h1, l1;
        split4(a, h0, l0); split4(b, h1, l1);
        uint4 hv; hv.x = h0.x; hv.y = h0.y; hv.z = h1.x; hv.w = h1.y;
        uint4 lv; lv.x = l0.x; lv.y = l0.y; lv.z = l1.x; lv.w = l1.y;
        *reinterpret_cast<uint4*>(dst + ((long)i << 3)) = hv;
        *reinterpret_cast<uint4*>(dst + planeStride + ((long)i << 3)) = lv;
    }
}

// row-interleaved conversion for wg/wu: src row f -> dst row 2f+ro (rowLen 640)
__global__ void conv_split_il(const float* __restrict__ src, __nv_bfloat16* __restrict__ dst,
                              long srcLS, long dstLS, int ro, long planeStride, int nRows) {
    src += (long)blockIdx.z * srcLS;
    dst += (long)blockIdx.z * dstLS;
    int total = nRows * 80;   // 80 chunks of 8 elems per 640-row
    for (int i = blockIdx.x * blockDim.x + threadIdx.x; i < total; i += gridDim.x * blockDim.x) {
        int row = i / 80, c8 = i % 80;
        const float4* s = reinterpret_cast<const float4*>(src + (long)row * 640 + c8 * 8);
        float4 a = s[0], b = s[1];
        uint2 h0, l0, h1, l1;
        split4(a, h0, l0); split4(b, h1, l1);
        uint4 hv; hv.x = h0.x; hv.y = h0.y; hv.z = h1.x; hv.w = h1.y;
        uint4 lv; lv.x = l0.x; lv.y = l0.y; lv.z = l1.x; lv.w = l1.y;
        __nv_bfloat16* d = dst + (long)(2 * row + ro) * 640 + c8 * 8;
        *reinterpret_cast<uint4*>(d) = hv;
        *reinterpret_cast<uint4*>(d + planeStride) = lv;
    }
}

// -------------------- elementwise / norm kernels ----------------------------
__global__ void embed_kernel(const int* __restrict__ ids, const float* __restrict__ emb,
                             float* __restrict__ x) {
    int t = blockIdx.x;
    long id = (long)ids[t];
    for (int d = threadIdx.x; d < D_MODEL; d += blockDim.x)
        x[(long)t * D_MODEL + d] = emb[id * D_MODEL + d] * EMB_SCALE;
}

__global__ void rmsnorm_split_kernel(const float* __restrict__ x, const float* __restrict__ w,
                                     __nv_bfloat16* __restrict__ o2, long plane) {
    int t = blockIdx.x;
    const float* row = x + (long)t * D_MODEL;
    float ss = 0.0f;
    for (int d = threadIdx.x; d < D_MODEL; d += blockDim.x) { float v = row[d]; ss += v * v; }
    ss = block_reduce_sum(ss);
    float scale = rsqrtf(ss / (float)D_MODEL + 1e-6f);
    for (int d = threadIdx.x; d < D_MODEL; d += blockDim.x)
        store_split_plane(o2 + (long)t * D_MODEL + d, plane, row[d] * scale * (1.0f + w[d]));
}

// fused: x += rms(tmp0+tmp1, wa); o2 = split(rms(x, wn)); optional fp16 copy
__global__ void rmsadd_norm_split(float* __restrict__ x, const float* __restrict__ tmp,
                                  long tmpSlice,
                                  const float* __restrict__ wa, const float* __restrict__ wn,
                                  __nv_bfloat16* __restrict__ o2, long plane,
                                  __half* __restrict__ oh) {
    int t = blockIdx.x, tid = threadIdx.x;
    float* xr = x + (long)t * D_MODEL;
    const float* tr  = tmp + (long)t * D_MODEL;
    const float* tr2 = tr + tmpSlice;
    float tv[3];
    float ss = 0.0f;
    #pragma unroll
    for (int i = 0; i < 3; i++) {
        int d = tid + (i << 8);
        if (d < D_MODEL) { tv[i] = tr[d] + tr2[d]; ss += tv[i] * tv[i]; }
    }
    ss = block_reduce_sum(ss);
    float s1 = rsqrtf(ss / (float)D_MODEL + 1e-6f);
    float xv[3];
    ss = 0.0f;
    #pragma unroll
    for (int i = 0; i < 3; i++) {
        int d = tid + (i << 8);
        if (d < D_MODEL) {
            xv[i] = xr[d] + tv[i] * s1 * (1.0f + wa[d]);
            xr[d] = xv[i];
            ss += xv[i] * xv[i];
        }
    }
    ss = block_reduce_sum(ss);
    float s2 = rsqrtf(ss / (float)D_MODEL + 1e-6f);
    #pragma unroll
    for (int i = 0; i < 3; i++) {
        int d = tid + (i << 8);
        if (d < D_MODEL) {
            float v = xv[i] * s2 * (1.0f + wn[d]);
            store_split_plane(o2 + (long)t * D_MODEL + d, plane, v);
            if (oh) oh[(long)t * D_MODEL + d] = __float2half(v);
        }
    }
}

// fused q+k rms-norm + rope over split-K qkv slices: grid (SEQ, 5)
__global__ void qknorm_rope_fused(const float* __restrict__ qkv, long dup,
                                  const float* __restrict__ qw, const float* __restrict__ kw,
                                  __nv_bfloat16* __restrict__ q2, __nv_bfloat16* __restrict__ k2,
                                  long pQ, long pK, float base) {
    int t = blockIdx.x, h = blockIdx.y, d = threadIdx.x;  // d in [0,128)
    const float* row;
    __nv_bfloat16* orow;
    const float* w;
    long plane;
    if (h < NHEADS) {
        row = qkv + (long)t * 1536 + h * HEADDIM;
        orow = q2 + (long)t * 1024 + h * HEADDIM;
        w = qw; plane = pQ;
    } else {
        row = qkv + (long)t * 1536 + 1024;
        orow = k2 + (long)t * 256;
        w = kw; plane = pK;
    }
    float v1 = row[d] + row[d + dup];
    float v2 = row[d + 128] + row[d + 128 + dup];
    float ss = block_reduce_sum(v1 * v1 + v2 * v2);
    float scale = rsqrtf(ss / (float)HEADDIM + 1e-6f);
    float q1 = v1 * scale * (1.0f + w[d]);
    float q2v = v2 * scale * (1.0f + w[d + 128]);
    float invf = powf(base, -((float)d) / 128.0f);
    float s, c;
    sincosf((float)t * invf, &s, &c);
    store_split_plane(orow + d,       plane, q1 * c - q2v * s);
    store_split_plane(orow + d + 128, plane, q1 * s + q2v * c);
}

__global__ void transpose_split(const float* __restrict__ in, int rs, long dup,
                                __nv_bfloat16* __restrict__ out, long plane) {
    __shared__ float tile[32][33];
    int r0 = blockIdx.y << 5, c0 = blockIdx.x << 5;
    int x = threadIdx.x, y = threadIdx.y;
    #pragma unroll
    for (int i = 0; i < 32; i += 8) {
        long idx = (long)(r0 + y + i) * rs + c0 + x;
        tile[y + i][x] = in[idx] + in[idx + dup];
    }
    __syncthreads();
    #pragma unroll
    for (int i = 0; i < 32; i += 8)
        store_split_plane(out + (long)(c0 + y + i) * SEQ + r0 + x, plane, tile[x][y + i]);
}

__global__ void softmax_split_kernel(const float* __restrict__ S,
                                     __nv_bfloat16* __restrict__ P, int win) {
    int i = blockIdx.x, h = blockIdx.y;
    const float* row = S + ((long)h << 20) + ((long)i << 10);
    __nv_bfloat16* prow = P + (long)h * (2 << 20) + ((long)i << 10);
    const long plane = 1 << 20;
    int lo = i - win + 1; if (lo < 0) lo = 0;
    float mx = -3.0e38f;
    for (int j = lo + threadIdx.x; j <= i; j += blockDim.x)
        mx = fmaxf(mx, row[j] * 0.0625f);
    mx = block_reduce_max(mx);
    float sum = 0.0f;
    for (int j = lo + threadIdx.x; j <= i; j += blockDim.x)
        sum += expf(row[j] * 0.0625f - mx);
    sum = block_reduce_sum(sum);
    float inv = 1.0f / sum;
    int m0 = i & ~127;
    int jlo = m0 - win + 1; if (jlo < 0) jlo = 0; jlo &= ~31;
    int jhi = m0 + 128; if (jhi > SEQ) jhi = SEQ;
    for (int j = jlo + threadIdx.x; j < jhi; j += blockDim.x) {
        float v = 0.0f;
        if (j >= lo && j <= i) v = expf(row[j] * 0.0625f - mx) * inv;
        store_split_plane(prow + j, plane, v);
    }
}

// -------------------- launch ------------------------------------------------
extern "C" void kernel_launch(void* const* d_in, const int* in_sizes, int n_in,
                              void* d_out, int out_size) {
    const int*   input_ids = (const int*)  d_in[0];
    const float* embed     = (const float*)d_in[1];
    const float* ln_in     = (const float*)d_in[2];
    const float* wq        = (const float*)d_in[3];
    const float* wk        = (const float*)d_in[4];
    const float* wv        = (const float*)d_in[5];
    const float* qnw       = (const float*)d_in[6];
    const float* knw       = (const float*)d_in[7];
    const float* wo        = (const float*)d_in[8];
    const float* ln_pa     = (const float*)d_in[9];
    const float* ln_pf     = (const float*)d_in[10];
    const float* wg        = (const float*)d_in[11];
    const float* wu        = (const float*)d_in[12];
    const float* wd        = (const float*)d_in[13];
    const float* ln_ff     = (const float*)d_in[14];
    const float* norm_f    = (const float*)d_in[15];
    float* out = (float*)d_out;

    const int SMEM64  = 2 * (256 + 128) * PADR * 2;
    const int SMEM128 = 2 * (256 + 256) * PADR * 2;
    const int SMEMLMH = 2 * 256 * PADR * 2;
    cudaFuncSetAttribute(gemm3<64, 0>,  cudaFuncAttributeMaxDynamicSharedMemorySize, SMEM64);
    cudaFuncSetAttribute(gemm3<64, 1>,  cudaFuncAttributeMaxDynamicSharedMemorySize, SMEM64);
    cudaFuncSetAttribute(gemm3<128, 0>, cudaFuncAttributeMaxDynamicSharedMemorySize, SMEM128);
    cudaFuncSetAttribute(gemm3<128, 2>, cudaFuncAttributeMaxDynamicSharedMemorySize, SMEM128);
    cudaFuncSetAttribute(lmhead_h,      cudaFuncAttributeMaxDynamicSharedMemorySize, SMEMLMH);

    float *x, *tmpd, *qkv, *sc;
    __nv_bfloat16 *xn2, *q2, *k2, *vt2, *p2, *ctx2, *ga2;
    __nv_bfloat16 *wqkv2, *wo2, *wgu2, *wd2;
    __half *xnh;
    cudaGetSymbolAddress((void**)&x,     g_x);
    cudaGetSymbolAddress((void**)&tmpd,  g_tmpd);
    cudaGetSymbolAddress((void**)&xn2,   g_xn2);
    cudaGetSymbolAddress((void**)&xnh,   g_xnh);
    cudaGetSymbolAddress((void**)&qkv,   g_qkv);
    cudaGetSymbolAddress((void**)&q2,    g_q2);
    cudaGetSymbolAddress((void**)&k2,    g_k2);
    cudaGetSymbolAddress((void**)&vt2,   g_vt2);
    cudaGetSymbolAddress((void**)&sc,    g_sc);
    cudaGetSymbolAddress((void**)&p2,    g_p2);
    cudaGetSymbolAddress((void**)&ctx2,  g_ctx2);
    cudaGetSymbolAddress((void**)&ga2,   g_ga2);
    cudaGetSymbolAddress((void**)&wqkv2, g_wqkv2);
    cudaGetSymbolAddress((void**)&wo2,   g_wo2);
    cudaGetSymbolAddress((void**)&wgu2,  g_wgu2);
    cudaGetSymbolAddress((void**)&wd2,   g_wd2);

    const long pXN  = (long)SEQ * D_MODEL;
    const long pQ   = (long)SEQ * 1024;
    const long pK   = (long)SEQ * 256;
    const long pVT  = (long)HEADDIM * SEQ;
    const long pGA  = (long)SEQ * DFF;
    const long pQKV = (long)1536 * 640;
    const long pWO  = (long)640 * 1024;
    const long pWGU = (long)4096 * 640;
    const long pWD  = (long)640 * 2048;
    const long QKV_SLICE = (long)SEQ * 1536;

    // ---- weight conversions (bf16 split planes; wg/wu row-interleaved) ----
    conv_split<<<dim3(320, 1, NLAYERS), 256>>>(wq, wqkv2, 1024L*640, 2*pQKV, 0,         pQKV, 1024*640);
    conv_split<<<dim3(80,  1, NLAYERS), 256>>>(wk, wqkv2,  256L*640, 2*pQKV, 1024L*640, pQKV,  256*640);
    conv_split<<<dim3(80,  1, NLAYERS), 256>>>(wv, wqkv2,  256L*640, 2*pQKV, 1280L*640, pQKV,  256*640);
    conv_split<<<dim3(320, 1, NLAYERS), 256>>>(wo, wo2,    640L*1024, 2*pWO,  0,        pWO,   640*1024);
    conv_split_il<<<dim3(640, 1, NLAYERS), 256>>>(wg, wgu2, 2048L*640, 2*pWGU, 0, pWGU, 2048);
    conv_split_il<<<dim3(640, 1, NLAYERS), 256>>>(wu, wgu2, 2048L*640, 2*pWGU, 1, pWGU, 2048);
    conv_split<<<dim3(640, 1, NLAYERS), 256>>>(wd, wd2,    640L*2048, 2*pWD,  0,        pWD,   640*2048);

    embed_kernel<<<SEQ, 256>>>(input_ids, embed, x);
    rmsnorm_split_kernel<<<SEQ, 256>>>(x, ln_in, xn2, pXN);

    for (int l = 0; l < NLAYERS; l++) {
        const float* qnw_l   = qnw + l * HEADDIM;
        const float* knw_l   = knw + l * HEADDIM;
        const float* ln_pa_l = ln_pa + l * D_MODEL;
        const float* ln_pf_l = ln_pf + l * D_MODEL;
        const float* ln_ff_l = ln_ff + l * D_MODEL;
        const float* next_w  = (l + 1 < NLAYERS) ? (ln_in + (l + 1) * D_MODEL) : norm_f;
        const __nv_bfloat16* wqkv_l = wqkv2 + (long)l * 2 * pQKV;
        const __nv_bfloat16* wo_l   = wo2   + (long)l * 2 * pWO;
        const __nv_bfloat16* wgu_l  = wgu2  + (long)l * 2 * pWGU;
        const __nv_bfloat16* wd_l   = wd2   + (long)l * 2 * pWD;

        bool is_global = ((l + 1) % 6) == 0;
        float base = is_global ? 1000000.0f : 10000.0f;
        int   win  = is_global ? 32768 : 512;

        // qkv, split-K x2 (slices summed by rope/transpose consumers)
        gemm3<128, 0><<<dim3(12, 8, 2), 256, SMEM128>>>(xn2, wqkv_l, qkv, nullptr,
            640, 640, 640, pXN, pQKV, 1536, 0, 0, 0, QKV_SLICE, -1, -1, 320);
        qknorm_rope_fused<<<dim3(SEQ, NHEADS + 1), 128>>>(qkv, QKV_SLICE, qnw_l, knw_l,
            q2, k2, pQ, pK, base);
        transpose_split<<<dim3(8, 32), dim3(32, 8)>>>(qkv + 1280, 1536, QKV_SLICE, vt2, pVT);
        // scores (banded-causal skip), batched over heads
        gemm3<64, 0><<<dim3(16, 8, NHEADS), 256, SMEM64>>>(q2, k2, sc, nullptr,
            256, 1024, 256, pQ, pK, 1024, 0, 256, 0, (long)1 << 20, win, -1, 0);
        softmax_split_kernel<<<dim3(SEQ, NHEADS), 256>>>(sc, p2, win);
        // ctx (k-band), split-bf16 output
        gemm3<64, 1><<<dim3(4, 8, NHEADS), 256, SMEM64>>>(p2, vt2, nullptr, ctx2,
            1024, 1024, 1024, pQ, pVT, 1024, pQ, (long)2 << 20, 0, 256, -1, win, 0);
        // out projection, split-K x2
        gemm3<64, 0><<<dim3(10, 8, 2), 256, SMEM64>>>(ctx2, wo_l, tmpd, nullptr,
            1024, 1024, 1024, pQ, pWO, D_MODEL, 0, 0, 0, pXN, -1, -1, 512);
        rmsadd_norm_split<<<SEQ, 256>>>(x, tmpd, pXN, ln_pa_l, ln_pf_l, xn2, pXN, nullptr);
        // fused gate+up GEMM with gelu-mul epilogue (interleaved weights)
        gemm3<128, 2><<<dim3(32, 8), 256, SMEM128>>>(xn2, wgu_l, nullptr, ga2,
            640, 640, 640, pXN, pWGU, DFF, pGA, 0, 0, 0, -1, -1, 0);
        // down projection, split-K x2
        gemm3<64, 0><<<dim3(10, 8, 2), 256, SMEM64>>>(ga2, wd_l, tmpd, nullptr,
            2048, 2048, 2048, pGA, pWD, D_MODEL, 0, 0, 0, pXN, -1, -1, 1024);
        rmsadd_norm_split<<<SEQ, 256>>>(x, tmpd, pXN, ln_ff_l, next_w, xn2, pXN,
            (l + 1 == NLAYERS) ? xnh : nullptr);
    }

    // LM head: fp16 single-pass, B = fp32 embedding converted in-register
    lmhead_h<<<dim3(8, VOCAB / 128), 256, SMEMLMH>>>(xnh, embed, out);
    (void)in_sizes; (void)n_in; (void)out_size;
}

// round 10
// speedup vs baseline: 4.1353x; 1.0087x over previous
#include <cuda_runtime.h>
#include <cuda_bf16.h>
#include <cuda_fp16.h>
#include <cstdint>

#define D_MODEL 640
#define NHEADS  4
#define HEADDIM 256
#define DFF     2048
#define NLAYERS 18
#define SEQ     1024
#define VOCAB   262144
#define EMB_SCALE 25.298221281347036f

#define PADR 40   // smem row stride (bf16/fp16 elems): 80B, ldsm conflict-free

// -------------------- scratch (device globals) ------------------------------
__device__ __align__(256) float g_x[SEQ * D_MODEL];
__device__ __align__(256) float g_tmpd[2 * SEQ * D_MODEL];       // 2 split-K slices
__device__ __align__(256) __nv_bfloat16 g_xn2[2 * SEQ * D_MODEL];
__device__ __align__(256) __half g_xnh[SEQ * D_MODEL];
__device__ __align__(256) float g_qkv[2 * SEQ * 1536];           // 2 split-K slices
__device__ __align__(256) __nv_bfloat16 g_q2[2 * SEQ * 1024];
__device__ __align__(256) __nv_bfloat16 g_k2[2 * SEQ * 256];
__device__ __align__(256) __nv_bfloat16 g_vt2[2 * HEADDIM * SEQ];
__device__ __align__(256) float g_sc[NHEADS * SEQ * SEQ];
__device__ __align__(256) __nv_bfloat16 g_p2[(long)NHEADS * 2 * SEQ * SEQ];
__device__ __align__(256) __nv_bfloat16 g_ctx2[2 * SEQ * 1024];
__device__ __align__(256) __nv_bfloat16 g_ga2[2 * SEQ * DFF];
__device__ __align__(256) __nv_bfloat16 g_wqkv2[(long)NLAYERS * 2 * 1536 * 640];
__device__ __align__(256) __nv_bfloat16 g_wo2[(long)NLAYERS * 2 * 640 * 1024];
__device__ __align__(256) __nv_bfloat16 g_wgu2[(long)NLAYERS * 2 * 4096 * 640];  // g/u row-interleaved
__device__ __align__(256) __nv_bfloat16 g_wd2[(long)NLAYERS * 2 * 640 * 2048];
__device__ __align__(256) float g_ropec[2 * SEQ * 128];
__device__ __align__(256) float g_ropes[2 * SEQ * 128];

// -------------------- asm / pack helpers -------------------------------------
__device__ __forceinline__ unsigned smem_u32(const void* p) {
    return (unsigned)__cvta_generic_to_shared(p);
}
__device__ __forceinline__ void cp_async16(void* smem, const void* gmem) {
    asm volatile("cp.async.cg.shared.global [%0], [%1], 16;\n"
                 :: "r"(smem_u32(smem)), "l"(gmem));
}
__device__ __forceinline__ void cp_commit() { asm volatile("cp.async.commit_group;\n"); }
template <int N> __device__ __forceinline__ void cp_wait() {
    asm volatile("cp.async.wait_group %0;\n" :: "n"(N));
}
__device__ __forceinline__ void ldsm_x4(unsigned* r, const void* p) {
    asm volatile("ldmatrix.sync.aligned.m8n8.x4.shared.b16 {%0,%1,%2,%3}, [%4];"
                 : "=r"(r[0]), "=r"(r[1]), "=r"(r[2]), "=r"(r[3]) : "r"(smem_u32(p)));
}
__device__ __forceinline__ void mma_bf16(float* c, const unsigned* a, const unsigned* b) {
    asm volatile(
        "mma.sync.aligned.m16n8k16.row.col.f32.bf16.bf16.f32 "
        "{%0,%1,%2,%3}, {%4,%5,%6,%7}, {%8,%9}, {%0,%1,%2,%3};\n"
        : "+f"(c[0]), "+f"(c[1]), "+f"(c[2]), "+f"(c[3])
        : "r"(a[0]), "r"(a[1]), "r"(a[2]), "r"(a[3]), "r"(b[0]), "r"(b[1]));
}
__device__ __forceinline__ void mma_fp16(float* c, const unsigned* a, const unsigned* b) {
    asm volatile(
        "mma.sync.aligned.m16n8k16.row.col.f32.f16.f16.f32 "
        "{%0,%1,%2,%3}, {%4,%5,%6,%7}, {%8,%9}, {%0,%1,%2,%3};\n"
        : "+f"(c[0]), "+f"(c[1]), "+f"(c[2]), "+f"(c[3])
        : "r"(a[0]), "r"(a[1]), "r"(a[2]), "r"(a[3]), "r"(b[0]), "r"(b[1]));
}
__device__ __forceinline__ void store_split_plane(__nv_bfloat16* p, long ps, float x) {
    __nv_bfloat16 h = __float2bfloat16(x);
    p[0]  = h;
    p[ps] = __float2bfloat16(x - __bfloat162float(h));
}
__device__ __forceinline__ unsigned pack2(__nv_bfloat16 a, __nv_bfloat16 b) {
    __nv_bfloat162 v = __halves2bfloat162(a, b);
    return *reinterpret_cast<unsigned*>(&v);
}
__device__ __forceinline__ void split4(float4 v, uint2& hi, uint2& lo) {
    __nv_bfloat16 h0 = __float2bfloat16(v.x), h1 = __float2bfloat16(v.y);
    __nv_bfloat16 h2 = __float2bfloat16(v.z), h3 = __float2bfloat16(v.w);
    hi.x = pack2(h0, h1); hi.y = pack2(h2, h3);
    lo.x = pack2(__float2bfloat16(v.x - __bfloat162float(h0)),
                 __float2bfloat16(v.y - __bfloat162float(h1)));
    lo.y = pack2(__float2bfloat16(v.z - __bfloat162float(h2)),
                 __float2bfloat16(v.w - __bfloat162float(h3)));
}
// tanh-gelu via __expf; 1 - 2/(e+1) is saturation-safe (e->inf => 1, e->0 => -1)
__device__ __forceinline__ float gelu_tanh(float g) {
    float u = 0.7978845608028654f * (g + 0.044715f * g * g * g);
    float e = __expf(2.0f * u);
    float th = 1.0f - 2.0f / (e + 1.0f);
    return 0.5f * g * (1.0f + th);
}

// -------------------- reductions -------------------------------------------
__device__ __forceinline__ float block_reduce_sum(float v) {
    __shared__ float red[32];
    __syncthreads();
    int lane = threadIdx.x & 31, wid = threadIdx.x >> 5;
    #pragma unroll
    for (int o = 16; o > 0; o >>= 1) v += __shfl_down_sync(0xffffffffu, v, o);
    if (lane == 0) red[wid] = v;
    __syncthreads();
    int nw = (blockDim.x + 31) >> 5;
    v = (threadIdx.x < (unsigned)nw) ? red[threadIdx.x] : 0.0f;
    if (wid == 0) {
        #pragma unroll
        for (int o = 16; o > 0; o >>= 1) v += __shfl_down_sync(0xffffffffu, v, o);
        if (lane == 0) red[0] = v;
    }
    __syncthreads();
    return red[0];
}
__device__ __forceinline__ float block_reduce_max(float v) {
    __shared__ float redm[32];
    __syncthreads();
    int lane = threadIdx.x & 31, wid = threadIdx.x >> 5;
    #pragma unroll
    for (int o = 16; o > 0; o >>= 1) v = fmaxf(v, __shfl_down_sync(0xffffffffu, v, o));
    if (lane == 0) redm[wid] = v;
    __syncthreads();
    int nw = (blockDim.x + 31) >> 5;
    v = (threadIdx.x < (unsigned)nw) ? redm[threadIdx.x] : -3.0e38f;
    if (wid == 0) {
        #pragma unroll
        for (int o = 16; o > 0; o >>= 1) v = fmaxf(v, __shfl_down_sync(0xffffffffu, v, o));
        if (lane == 0) redm[0] = v;
    }
    __syncthreads();
    return redm[0];
}

// -------------------- 3-term split bf16 GEMM: C = A @ B^T -------------------
// EPI: 0 = fp32 out (Cf), 1 = split-bf16 out (Cs), 2 = fused gelu-mul split out.
template <int BN, int EPI>
__global__ void __launch_bounds__(256) gemm3(
    const __nv_bfloat16* __restrict__ A, const __nv_bfloat16* __restrict__ B,
    float* __restrict__ Cf, __nv_bfloat16* __restrict__ Cs,
    int K, int lda, int ldb, long planeA, long planeB,
    int ldc, long planeC,
    long sA, long sB, long sC, int win, int kwin, int kchunk)
{
    constexpr int WN   = BN / 2;
    constexpr int PCNT = WN / 16;
    constexpr int NTC  = WN / 8;
    constexpr int STAGE = (256 + 2 * BN) * PADR;
    extern __shared__ __nv_bfloat16 sm[];

    A += (long)blockIdx.z * sA;
    B += (long)blockIdx.z * sB;
    if (EPI == 0) Cf += (long)blockIdx.z * sC; else Cs += (long)blockIdx.z * sC;

    const int m0 = blockIdx.y << 7;
    const int n0 = blockIdx.x * BN;
    if (win > 0) {
        if (n0 > m0 + 127) return;
        if (n0 + BN - 1 < m0 - win + 1) return;
    }
    const int tid = threadIdx.x, lane = tid & 31, warp = tid >> 5;
    const int wm = warp >> 1, wn = warp & 1;
    const int gid = lane >> 2, tig = lane & 3;

    int kbeg = 0, kend = K;
    if (kchunk > 0) {
        kbeg = blockIdx.z * kchunk; kend = kbeg + kchunk;
    } else if (kwin > 0) {
        kbeg = m0 - kwin + 1; if (kbeg < 0) kbeg = 0; kbeg &= ~31;
        kend = m0 + 128; if (kend > K) kend = K;
    }
    const int nk = (kend - kbeg) >> 5;

    float acc[2][NTC][4];
    #pragma unroll
    for (int mt = 0; mt < 2; mt++)
        #pragma unroll
        for (int nt = 0; nt < NTC; nt++)
            #pragma unroll
            for (int i = 0; i < 4; i++) acc[mt][nt][i] = 0.0f;

    const __nv_bfloat16* Abase = A + (long)m0 * lda;
    const __nv_bfloat16* Bbase = B + (long)n0 * ldb;

    auto load_tile = [&](int s, int k0) {
        __nv_bfloat16* st = sm + s * STAGE;
        const __nv_bfloat16* Ab = Abase + k0;
        #pragma unroll
        for (int i = 0; i < 2; i++) {
            int idx = tid + (i << 8);
            int r = idx >> 2, c = (idx & 3) << 3;
            cp_async16(st + r * PADR + c, Ab + (long)r * lda + c);
            cp_async16(st + 128 * PADR + r * PADR + c, Ab + planeA + (long)r * lda + c);
        }
        const __nv_bfloat16* Bb = Bbase + k0;
        #pragma unroll
        for (int i = 0; i < BN / 64; i++) {
            int idx = tid + (i << 8);
            int r = idx >> 2, c = (idx & 3) << 3;
            cp_async16(st + 256 * PADR + r * PADR + c, Bb + (long)r * ldb + c);
            cp_async16(st + (256 + BN) * PADR + r * PADR + c, Bb + planeB + (long)r * ldb + c);
        }
        cp_commit();
    };

    load_tile(0, kbeg);

    const int arow = wm * 32 + (lane & 15);
    const int acol = (lane >> 4) << 3;
    const int brow = wn * WN + ((lane >> 4) << 3) + (lane & 7);
    const int bcol = ((lane >> 3) & 1) << 3;

    for (int kt = 0; kt < nk; kt++) {
        const bool pf = (kt + 1 < nk);
        if (pf) {
            load_tile((kt + 1) & 1, kbeg + ((kt + 1) << 5));
            cp_wait<1>();
        } else {
            cp_wait<0>();
        }
        __syncthreads();

        const __nv_bfloat16* Ahp = sm + (kt & 1) * STAGE;
        const __nv_bfloat16* Alp = Ahp + 128 * PADR;
        const __nv_bfloat16* Bhp = Ahp + 256 * PADR;
        const __nv_bfloat16* Blp = Ahp + (256 + BN) * PADR;

        #pragma unroll
        for (int kk = 0; kk < 2; kk++) {
            unsigned ah[2][4], al[2][4], bh[PCNT][4], bl[PCNT][4];
            #pragma unroll
            for (int mt = 0; mt < 2; mt++) {
                ldsm_x4(ah[mt], Ahp + (long)(arow + mt * 16) * PADR + kk * 16 + acol);
                ldsm_x4(al[mt], Alp + (long)(arow + mt * 16) * PADR + kk * 16 + acol);
            }
            #pragma unroll
            for (int p = 0; p < PCNT; p++) {
                ldsm_x4(bh[p], Bhp + (long)(brow + p * 16) * PADR + kk * 16 + bcol);
                ldsm_x4(bl[p], Blp + (long)(brow + p * 16) * PADR + kk * 16 + bcol);
            }
            #pragma unroll
            for (int mt = 0; mt < 2; mt++)
                #pragma unroll
                for (int nt = 0; nt < NTC; nt++) {
                    const unsigned* bhf = &bh[nt >> 1][(nt & 1) << 1];
                    const unsigned* blf = &bl[nt >> 1][(nt & 1) << 1];
                    mma_bf16(acc[mt][nt], ah[mt], bhf);
                    mma_bf16(acc[mt][nt], ah[mt], blf);
                    mma_bf16(acc[mt][nt], al[mt], bhf);
                }
        }
        __syncthreads();
    }

    #pragma unroll
    for (int mt = 0; mt < 2; mt++) {
        int r = m0 + wm * 32 + mt * 16 + gid;
        #pragma unroll
        for (int nt = 0; nt < NTC; nt++) {
            int cc = n0 + wn * WN + nt * 8 + tig * 2;
            if (EPI == 0) {
                *reinterpret_cast<float2*>(Cf + (long)r * ldc + cc) =
                    make_float2(acc[mt][nt][0], acc[mt][nt][1]);
                *reinterpret_cast<float2*>(Cf + (long)(r + 8) * ldc + cc) =
                    make_float2(acc[mt][nt][2], acc[mt][nt][3]);
            } else if (EPI == 1) {
                store_split_plane(Cs + (long)r * ldc + cc,           planeC, acc[mt][nt][0]);
                store_split_plane(Cs + (long)r * ldc + cc + 1,       planeC, acc[mt][nt][1]);
                store_split_plane(Cs + (long)(r + 8) * ldc + cc,     planeC, acc[mt][nt][2]);
                store_split_plane(Cs + (long)(r + 8) * ldc + cc + 1, planeC, acc[mt][nt][3]);
            } else {
                int f = cc >> 1;  // interleaved (g,u) pair -> one output col
                store_split_plane(Cs + (long)r * ldc + f, planeC,
                                  gelu_tanh(acc[mt][nt][0]) * acc[mt][nt][1]);
                store_split_plane(Cs + (long)(r + 8) * ldc + f, planeC,
                                  gelu_tanh(acc[mt][nt][2]) * acc[mt][nt][3]);
            }
        }
    }
}

// -------------------- fp16 LM head: C = A @ B^T, B fp32 converted in-kernel --
__global__ void __launch_bounds__(256) lmhead_h(
    const __half* __restrict__ A, const float* __restrict__ Bf, float* __restrict__ C)
{
    constexpr int STAGE = 256 * PADR;
    extern __shared__ __half smh[];

    const int m0 = blockIdx.x << 7;
    const int n0 = blockIdx.y << 7;
    const int tid = threadIdx.x, lane = tid & 31, warp = tid >> 5;
    const int wm = warp >> 1, wn = warp & 1;
    const int gid = lane >> 2, tig = lane & 3;

    float acc[2][8][4];
    #pragma unroll
    for (int mt = 0; mt < 2; mt++)
        #pragma unroll
        for (int nt = 0; nt < 8; nt++)
            #pragma unroll
            for (int i = 0; i < 4; i++) acc[mt][nt][i] = 0.0f;

    const __half* Abase = A + (long)m0 * D_MODEL;

    auto load_tileA = [&](int s, int k0) {
        __half* st = smh + s * STAGE;
        #pragma unroll
        for (int i = 0; i < 2; i++) {
            int idx = tid + (i << 8);
            int r = idx >> 2, c = (idx & 3) << 3;
            cp_async16(st + r * PADR + c, Abase + (long)r * D_MODEL + k0 + c);
        }
        cp_commit();
    };

    float4 breg[4];
    const int br = tid >> 1, bc16 = (tid & 1) << 4;
    auto ldgB = [&](int k0) {
        const float4* bp = reinterpret_cast<const float4*>(
            Bf + (long)(n0 + br) * D_MODEL + k0 + bc16);
        breg[0] = bp[0]; breg[1] = bp[1]; breg[2] = bp[2]; breg[3] = bp[3];
    };
    auto stsB = [&](int s) {
        __half* Bh = smh + s * STAGE + 128 * PADR + br * PADR + bc16;
        #pragma unroll
        for (int q = 0; q < 4; q++) {
            __half2 p0 = __floats2half2_rn(breg[q].x, breg[q].y);
            __half2 p1 = __floats2half2_rn(breg[q].z, breg[q].w);
            uint2 v;
            v.x = *reinterpret_cast<unsigned*>(&p0);
            v.y = *reinterpret_cast<unsigned*>(&p1);
            *reinterpret_cast<uint2*>(Bh + q * 4) = v;
        }
    };

    const int nk = D_MODEL / 32;   // 20
    ldgB(0);
    load_tileA(0, 0);
    stsB(0);

    const int arow = wm * 32 + (lane & 15);
    const int acol = (lane >> 4) << 3;
    const int brow = wn * 64 + ((lane >> 4) << 3) + (lane & 7);
    const int bcol = ((lane >> 3) & 1) << 3;

    for (int kt = 0; kt < nk; kt++) {
        const bool pf = (kt + 1 < nk);
        if (pf) {
            ldgB((kt + 1) << 5);
            load_tileA((kt + 1) & 1, (kt + 1) << 5);
            cp_wait<1>();
        } else {
            cp_wait<0>();
        }
        __syncthreads();

        const __half* Ap = smh + (kt & 1) * STAGE;
        const __half* Bp = Ap + 128 * PADR;

        #pragma unroll
        for (int kk = 0; kk < 2; kk++) {
            unsigned a[2][4], b[4][4];
            #pragma unroll
            for (int mt = 0; mt < 2; mt++)
                ldsm_x4(a[mt], Ap + (long)(arow + mt * 16) * PADR + kk * 16 + acol);
            #pragma unroll
            for (int p = 0; p < 4; p++)
                ldsm_x4(b[p], Bp + (long)(brow + p * 16) * PADR + kk * 16 + bcol);
            #pragma unroll
            for (int mt = 0; mt < 2; mt++)
                #pragma unroll
                for (int nt = 0; nt < 8; nt++)
                    mma_fp16(acc[mt][nt], a[mt], &b[nt >> 1][(nt & 1) << 1]);
        }
        if (pf) stsB((kt + 1) & 1);
        __syncthreads();
    }

    #pragma unroll
    for (int mt = 0; mt < 2; mt++) {
        int r = m0 + wm * 32 + mt * 16 + gid;
        #pragma unroll
        for (int nt = 0; nt < 8; nt++) {
            int cc = n0 + wn * 64 + nt * 8 + tig * 2;
            *reinterpret_cast<float2*>(C + (long)r * VOCAB + cc) =
                make_float2(acc[mt][nt][0], acc[mt][nt][1]);
            *reinterpret_cast<float2*>(C + (long)(r + 8) * VOCAB + cc) =
                make_float2(acc[mt][nt][2], acc[mt][nt][3]);
        }
    }
}

// -------------------- conversions -------------------------------------------
__global__ void conv_split(const float* __restrict__ src, __nv_bfloat16* __restrict__ dst,
                           long srcLS, long dstLS, long dstOff, long planeStride, int n) {
    src += (long)blockIdx.z * srcLS;
    dst += (long)blockIdx.z * dstLS + dstOff;
    int n8 = n >> 3;
    for (int i = blockIdx.x * blockDim.x + threadIdx.x; i < n8; i += gridDim.x * blockDim.x) {
        float4 a = reinterpret_cast<const float4*>(src)[2 * i];
        float4 b = reinterpret_cast<const float4*>(src)[2 * i + 1];
        uint2 h0, l0, h1, l1;
        split4(a, h0, l0); split4(b, h1, l1);
        uint4 hv; hv.x = h0.x; hv.y = h0.y; hv.z = h1.x; hv.w = h1.y;
        uint4 lv; lv.x = l0.x; lv.y = l0.y; lv.z = l1.x; lv.w = l1.y;
        *reinterpret_cast<uint4*>(dst + ((long)i << 3)) = hv;
        *reinterpret_cast<uint4*>(dst + planeStride + ((long)i << 3)) = lv;
    }
}

__global__ void conv_split_il(const float* __restrict__ src, __nv_bfloat16* __restrict__ dst,
                              long srcLS, long dstLS, int ro, long planeStride, int nRows) {
    src += (long)blockIdx.z * srcLS;
    dst += (long)blockIdx.z * dstLS;
    int total = nRows * 80;
    for (int i = blockIdx.x * blockDim.x + threadIdx.x; i < total; i += gridDim.x * blockDim.x) {
        int row = i / 80, c8 = i % 80;
        const float4* s = reinterpret_cast<const float4*>(src + (long)row * 640 + c8 * 8);
        float4 a = s[0], b = s[1];
        uint2 h0, l0, h1, l1;
        split4(a, h0, l0); split4(b, h1, l1);
        uint4 hv; hv.x = h0.x; hv.y = h0.y; hv.z = h1.x; hv.w = h1.y;
        uint4 lv; lv.x = l0.x; lv.y = l0.y; lv.z = l1.x; lv.w = l1.y;
        __nv_bfloat16* d = dst + (long)(2 * row + ro) * 640 + c8 * 8;
        *reinterpret_cast<uint4*>(d) = hv;
        *reinterpret_cast<uint4*>(d + planeStride) = lv;
    }
}

// -------------------- rope tables (once per call, full precision) -----------
__global__ void rope_table_kernel() {
    int t = blockIdx.x, b = blockIdx.y, d = threadIdx.x;
    float base = b ? 1000000.0f : 10000.0f;
    float invf = powf(base, -((float)d) / 128.0f);
    float s, c;
    sincosf((float)t * invf, &s, &c);
    long idx = ((long)b * SEQ + t) * 128 + d;
    g_ropec[idx] = c;
    g_ropes[idx] = s;
}

// -------------------- elementwise / norm kernels ----------------------------
__global__ void embed_kernel(const int* __restrict__ ids, const float* __restrict__ emb,
                             float* __restrict__ x) {
    int t = blockIdx.x;
    long id = (long)ids[t];
    for (int d = threadIdx.x; d < D_MODEL; d += blockDim.x)
        x[(long)t * D_MODEL + d] = emb[id * D_MODEL + d] * EMB_SCALE;
}

__global__ void rmsnorm_split_kernel(const float* __restrict__ x, const float* __restrict__ w,
                                     __nv_bfloat16* __restrict__ o2, long plane) {
    int t = blockIdx.x;
    const float* row = x + (long)t * D_MODEL;
    float ss = 0.0f;
    for (int d = threadIdx.x; d < D_MODEL; d += blockDim.x) { float v = row[d]; ss += v * v; }
    ss = block_reduce_sum(ss);
    float scale = rsqrtf(ss / (float)D_MODEL + 1e-6f);
    for (int d = threadIdx.x; d < D_MODEL; d += blockDim.x)
        store_split_plane(o2 + (long)t * D_MODEL + d, plane, row[d] * scale * (1.0f + w[d]));
}

__global__ void rmsadd_norm_split(float* __restrict__ x, const float* __restrict__ tmp,
                                  long tmpSlice,
                                  const float* __restrict__ wa, const float* __restrict__ wn,
                                  __nv_bfloat16* __restrict__ o2, long plane,
                                  __half* __restrict__ oh) {
    int t = blockIdx.x, tid = threadIdx.x;
    float* xr = x + (long)t * D_MODEL;
    const float* tr  = tmp + (long)t * D_MODEL;
    const float* tr2 = tr + tmpSlice;
    float tv[3];
    float ss = 0.0f;
    #pragma unroll
    for (int i = 0; i < 3; i++) {
        int d = tid + (i << 8);
        if (d < D_MODEL) { tv[i] = tr[d] + tr2[d]; ss += tv[i] * tv[i]; }
    }
    ss = block_reduce_sum(ss);
    float s1 = rsqrtf(ss / (float)D_MODEL + 1e-6f);
    float xv[3];
    ss = 0.0f;
    #pragma unroll
    for (int i = 0; i < 3; i++) {
        int d = tid + (i << 8);
        if (d < D_MODEL) {
            xv[i] = xr[d] + tv[i] * s1 * (1.0f + wa[d]);
            xr[d] = xv[i];
            ss += xv[i] * xv[i];
        }
    }
    ss = block_reduce_sum(ss);
    float s2 = rsqrtf(ss / (float)D_MODEL + 1e-6f);
    #pragma unroll
    for (int i = 0; i < 3; i++) {
        int d = tid + (i << 8);
        if (d < D_MODEL) {
            float v = xv[i] * s2 * (1.0f + wn[d]);
            store_split_plane(o2 + (long)t * D_MODEL + d, plane, v);
            if (oh) oh[(long)t * D_MODEL + d] = __float2half(v);
        }
    }
}

// fused q+k rms-norm + rope (table-based): grid (SEQ, 5)
__global__ void qknorm_rope_fused(const float* __restrict__ qkv, long dup,
                                  const float* __restrict__ qw, const float* __restrict__ kw,
                                  __nv_bfloat16* __restrict__ q2, __nv_bfloat16* __restrict__ k2,
                                  long pQ, long pK, int bsel) {
    int t = blockIdx.x, h = blockIdx.y, d = threadIdx.x;  // d in [0,128)
    const float* row;
    __nv_bfloat16* orow;
    const float* w;
    long plane;
    if (h < NHEADS) {
        row = qkv + (long)t * 1536 + h * HEADDIM;
        orow = q2 + (long)t * 1024 + h * HEADDIM;
        w = qw; plane = pQ;
    } else {
        row = qkv + (long)t * 1536 + 1024;
        orow = k2 + (long)t * 256;
        w = kw; plane = pK;
    }
    float v1 = row[d] + row[d + dup];
    float v2 = row[d + 128] + row[d + 128 + dup];
    float ss = block_reduce_sum(v1 * v1 + v2 * v2);
    float scale = rsqrtf(ss / (float)HEADDIM + 1e-6f);
    float q1 = v1 * scale * (1.0f + w[d]);
    float q2v = v2 * scale * (1.0f + w[d + 128]);
    long ridx = ((long)bsel * SEQ + t) * 128 + d;
    float c = g_ropec[ridx], s = g_ropes[ridx];
    store_split_plane(orow + d,       plane, q1 * c - q2v * s);
    store_split_plane(orow + d + 128, plane, q1 * s + q2v * c);
}

__global__ void transpose_split(const float* __restrict__ in, int rs, long dup,
                                __nv_bfloat16* __restrict__ out, long plane) {
    __shared__ float tile[32][33];
    int r0 = blockIdx.y << 5, c0 = blockIdx.x << 5;
    int x = threadIdx.x, y = threadIdx.y;
    #pragma unroll
    for (int i = 0; i < 32; i += 8) {
        long idx = (long)(r0 + y + i) * rs + c0 + x;
        tile[y + i][x] = in[idx] + in[idx + dup];
    }
    __syncthreads();
    #pragma unroll
    for (int i = 0; i < 32; i += 8)
        store_split_plane(out + (long)(c0 + y + i) * SEQ + r0 + x, plane, tile[x][y + i]);
}

// banded softmax: smem-cached scores, single __expf pass
__global__ void softmax_split_kernel(const float* __restrict__ S,
                                     __nv_bfloat16* __restrict__ P, int win) {
    __shared__ float buf[1024];
    int i = blockIdx.x, h = blockIdx.y;
    const float* row = S + ((long)h << 20) + ((long)i << 10);
    __nv_bfloat16* prow = P + (long)h * (2 << 20) + ((long)i << 10);
    const long plane = 1 << 20;
    int lo = i - win + 1; if (lo < 0) lo = 0;
    int m0 = i & ~127;
    int jlo = m0 - win + 1; if (jlo < 0) jlo = 0; jlo &= ~31;
    int jhi = m0 + 128; if (jhi > SEQ) jhi = SEQ;

    float mx = -3.0e38f;
    for (int j = lo + threadIdx.x; j <= i; j += blockDim.x) {
        float v = row[j] * 0.0625f;
        buf[j - jlo] = v;
        mx = fmaxf(mx, v);
    }
    mx = block_reduce_max(mx);
    float sum = 0.0f;
    for (int j = lo + threadIdx.x; j <= i; j += blockDim.x) {
        float e = __expf(buf[j - jlo] - mx);
        buf[j - jlo] = e;
        sum += e;
    }
    sum = block_reduce_sum(sum);   // starts+ends with __syncthreads: buf writes visible after
    float inv = 1.0f / sum;
    for (int j = jlo + threadIdx.x; j < jhi; j += blockDim.x) {
        float v = (j >= lo && j <= i) ? buf[j - jlo] * inv : 0.0f;
        store_split_plane(prow + j, plane, v);
    }
}

// -------------------- launch ------------------------------------------------
extern "C" void kernel_launch(void* const* d_in, const int* in_sizes, int n_in,
                              void* d_out, int out_size) {
    const int*   input_ids = (const int*)  d_in[0];
    const float* embed     = (const float*)d_in[1];
    const float* ln_in     = (const float*)d_in[2];
    const float* wq        = (const float*)d_in[3];
    const float* wk        = (const float*)d_in[4];
    const float* wv        = (const float*)d_in[5];
    const float* qnw       = (const float*)d_in[6];
    const float* knw       = (const float*)d_in[7];
    const float* wo        = (const float*)d_in[8];
    const float* ln_pa     = (const float*)d_in[9];
    const float* ln_pf     = (const float*)d_in[10];
    const float* wg        = (const float*)d_in[11];
    const float* wu        = (const float*)d_in[12];
    const float* wd        = (const float*)d_in[13];
    const float* ln_ff     = (const float*)d_in[14];
    const float* norm_f    = (const float*)d_in[15];
    float* out = (float*)d_out;

    const int SMEM64  = 2 * (256 + 128) * PADR * 2;
    const int SMEM128 = 2 * (256 + 256) * PADR * 2;
    const int SMEMLMH = 2 * 256 * PADR * 2;
    cudaFuncSetAttribute(gemm3<64, 0>,  cudaFuncAttributeMaxDynamicSharedMemorySize, SMEM64);
    cudaFuncSetAttribute(gemm3<64, 1>,  cudaFuncAttributeMaxDynamicSharedMemorySize, SMEM64);
    cudaFuncSetAttribute(gemm3<128, 0>, cudaFuncAttributeMaxDynamicSharedMemorySize, SMEM128);
    cudaFuncSetAttribute(gemm3<128, 2>, cudaFuncAttributeMaxDynamicSharedMemorySize, SMEM128);
    cudaFuncSetAttribute(lmhead_h,      cudaFuncAttributeMaxDynamicSharedMemorySize, SMEMLMH);

    float *x, *tmpd, *qkv, *sc;
    __nv_bfloat16 *xn2, *q2, *k2, *vt2, *p2, *ctx2, *ga2;
    __nv_bfloat16 *wqkv2, *wo2, *wgu2, *wd2;
    __half *xnh;
    cudaGetSymbolAddress((void**)&x,     g_x);
    cudaGetSymbolAddress((void**)&tmpd,  g_tmpd);
    cudaGetSymbolAddress((void**)&xn2,   g_xn2);
    cudaGetSymbolAddress((void**)&xnh,   g_xnh);
    cudaGetSymbolAddress((void**)&qkv,   g_qkv);
    cudaGetSymbolAddress((void**)&q2,    g_q2);
    cudaGetSymbolAddress((void**)&k2,    g_k2);
    cudaGetSymbolAddress((void**)&vt2,   g_vt2);
    cudaGetSymbolAddress((void**)&sc,    g_sc);
    cudaGetSymbolAddress((void**)&p2,    g_p2);
    cudaGetSymbolAddress((void**)&ctx2,  g_ctx2);
    cudaGetSymbolAddress((void**)&ga2,   g_ga2);
    cudaGetSymbolAddress((void**)&wqkv2, g_wqkv2);
    cudaGetSymbolAddress((void**)&wo2,   g_wo2);
    cudaGetSymbolAddress((void**)&wgu2,  g_wgu2);
    cudaGetSymbolAddress((void**)&wd2,   g_wd2);

    const long pXN  = (long)SEQ * D_MODEL;
    const long pQ   = (long)SEQ * 1024;
    const long pK   = (long)SEQ * 256;
    const long pVT  = (long)HEADDIM * SEQ;
    const long pGA  = (long)SEQ * DFF;
    const long pQKV = (long)1536 * 640;
    const long pWO  = (long)640 * 1024;
    const long pWGU = (long)4096 * 640;
    const long pWD  = (long)640 * 2048;
    const long QKV_SLICE = (long)SEQ * 1536;

    // ---- one-time conversions + rope tables ----
    conv_split<<<dim3(320, 1, NLAYERS), 256>>>(wq, wqkv2, 1024L*640, 2*pQKV, 0,         pQKV, 1024*640);
    conv_split<<<dim3(80,  1, NLAYERS), 256>>>(wk, wqkv2,  256L*640, 2*pQKV, 1024L*640, pQKV,  256*640);
    conv_split<<<dim3(80,  1, NLAYERS), 256>>>(wv, wqkv2,  256L*640, 2*pQKV, 1280L*640, pQKV,  256*640);
    conv_split<<<dim3(320, 1, NLAYERS), 256>>>(wo, wo2,    640L*1024, 2*pWO,  0,        pWO,   640*1024);
    conv_split_il<<<dim3(640, 1, NLAYERS), 256>>>(wg, wgu2, 2048L*640, 2*pWGU, 0, pWGU, 2048);
    conv_split_il<<<dim3(640, 1, NLAYERS), 256>>>(wu, wgu2, 2048L*640, 2*pWGU, 1, pWGU, 2048);
    conv_split<<<dim3(640, 1, NLAYERS), 256>>>(wd, wd2,    640L*2048, 2*pWD,  0,        pWD,   640*2048);
    rope_table_kernel<<<dim3(SEQ, 2), 128>>>();

    embed_kernel<<<SEQ, 256>>>(input_ids, embed, x);
    rmsnorm_split_kernel<<<SEQ, 256>>>(x, ln_in, xn2, pXN);

    for (int l = 0; l < NLAYERS; l++) {
        const float* qnw_l   = qnw + l * HEADDIM;
        const float* knw_l   = knw + l * HEADDIM;
        const float* ln_pa_l = ln_pa + l * D_MODEL;
        const float* ln_pf_l = ln_pf + l * D_MODEL;
        const float* ln_ff_l = ln_ff + l * D_MODEL;
        const float* next_w  = (l + 1 < NLAYERS) ? (ln_in + (l + 1) * D_MODEL) : norm_f;
        const __nv_bfloat16* wqkv_l = wqkv2 + (long)l * 2 * pQKV;
        const __nv_bfloat16* wo_l   = wo2   + (long)l * 2 * pWO;
        const __nv_bfloat16* wgu_l  = wgu2  + (long)l * 2 * pWGU;
        const __nv_bfloat16* wd_l   = wd2   + (long)l * 2 * pWD;

        bool is_global = ((l + 1) % 6) == 0;
        int   win  = is_global ? 32768 : 512;
        int   bsel = is_global ? 1 : 0;

        gemm3<128, 0><<<dim3(12, 8, 2), 256, SMEM128>>>(xn2, wqkv_l, qkv, nullptr,
            640, 640, 640, pXN, pQKV, 1536, 0, 0, 0, QKV_SLICE, -1, -1, 320);
        qknorm_rope_fused<<<dim3(SEQ, NHEADS + 1), 128>>>(qkv, QKV_SLICE, qnw_l, knw_l,
            q2, k2, pQ, pK, bsel);
        transpose_split<<<dim3(8, 32), dim3(32, 8)>>>(qkv + 1280, 1536, QKV_SLICE, vt2, pVT);
        gemm3<64, 0><<<dim3(16, 8, NHEADS), 256, SMEM64>>>(q2, k2, sc, nullptr,
            256, 1024, 256, pQ, pK, 1024, 0, 256, 0, (long)1 << 20, win, -1, 0);
        softmax_split_kernel<<<dim3(SEQ, NHEADS), 256>>>(sc, p2, win);
        gemm3<64, 1><<<dim3(4, 8, NHEADS), 256, SMEM64>>>(p2, vt2, nullptr, ctx2,
            1024, 1024, 1024, pQ, pVT, 1024, pQ, (long)2 << 20, 0, 256, -1, win, 0);
        gemm3<64, 0><<<dim3(10, 8, 2), 256, SMEM64>>>(ctx2, wo_l, tmpd, nullptr,
            1024, 1024, 1024, pQ, pWO, D_MODEL, 0, 0, 0, pXN, -1, -1, 512);
        rmsadd_norm_split<<<SEQ, 256>>>(x, tmpd, pXN, ln_pa_l, ln_pf_l, xn2, pXN, nullptr);
        gemm3<128, 2><<<dim3(32, 8), 256, SMEM128>>>(xn2, wgu_l, nullptr, ga2,
            640, 640, 640, pXN, pWGU, DFF, pGA, 0, 0, 0, -1, -1, 0);
        gemm3<64, 0><<<dim3(10, 8, 2), 256, SMEM64>>>(ga2, wd_l, tmpd, nullptr,
            2048, 2048, 2048, pGA, pWD, D_MODEL, 0, 0, 0, pXN, -1, -1, 1024);
        rmsadd_norm_split<<<SEQ, 256>>>(x, tmpd, pXN, ln_ff_l, next_w, xn2, pXN,
            (l + 1 == NLAYERS) ? xnh : nullptr);
    }

    // LM head: fp16 single-pass, B = fp32 embedding converted in-register
    lmhead_h<<<dim3(8, VOCAB / 128), 256, SMEMLMH>>>(xnh, embed, out);
    (void)in_sizes; (void)n_in; (void)out_size;
}

// round 11
// speedup vs baseline: 4.2617x; 1.0306x over previous
#include <cuda_runtime.h>
#include <cuda_bf16.h>
#include <cuda_fp16.h>
#include <cstdint>

#define D_MODEL 640
#define NHEADS  4
#define HEADDIM 256
#define DFF     2048
#define NLAYERS 18
#define SEQ     1024
#define VOCAB   262144
#define EMB_SCALE 25.298221281347036f

#define PADR 40   // smem row stride (bf16/fp16 elems): 80B, ldsm conflict-free

// -------------------- scratch (device globals) ------------------------------
__device__ __align__(256) float g_x[SEQ * D_MODEL];
__device__ __align__(256) float g_tmpd[2 * SEQ * D_MODEL];
__device__ __align__(256) __nv_bfloat16 g_xn2[2 * SEQ * D_MODEL];
__device__ __align__(256) __half g_xnh[SEQ * D_MODEL];
__device__ __align__(256) float g_qkv[2 * SEQ * 1536];
__device__ __align__(256) __nv_bfloat16 g_q2[2 * SEQ * 1024];
__device__ __align__(256) __nv_bfloat16 g_k2[2 * SEQ * 256];
__device__ __align__(256) __nv_bfloat16 g_vt2[2 * HEADDIM * SEQ];
__device__ __align__(256) float g_sc[NHEADS * SEQ * SEQ];
__device__ __align__(256) __nv_bfloat16 g_p2[(long)NHEADS * 2 * SEQ * SEQ];
__device__ __align__(256) __nv_bfloat16 g_ctx2[2 * SEQ * 1024];
__device__ __align__(256) __nv_bfloat16 g_ga2[2 * SEQ * DFF];
__device__ __align__(256) __nv_bfloat16 g_wqkv2[(long)NLAYERS * 2 * 1536 * 640];
__device__ __align__(256) __nv_bfloat16 g_wo2[(long)NLAYERS * 2 * 640 * 1024];
__device__ __align__(256) __nv_bfloat16 g_wgu2[(long)NLAYERS * 2 * 4096 * 640];
__device__ __align__(256) __nv_bfloat16 g_wd2[(long)NLAYERS * 2 * 640 * 2048];
__device__ __align__(256) float g_ropec[2 * SEQ * 128];
__device__ __align__(256) float g_ropes[2 * SEQ * 128];

// -------------------- asm / pack helpers -------------------------------------
__device__ __forceinline__ unsigned smem_u32(const void* p) {
    return (unsigned)__cvta_generic_to_shared(p);
}
__device__ __forceinline__ void cp_async16(void* smem, const void* gmem) {
    asm volatile("cp.async.cg.shared.global [%0], [%1], 16;\n"
                 :: "r"(smem_u32(smem)), "l"(gmem));
}
__device__ __forceinline__ void cp_commit() { asm volatile("cp.async.commit_group;\n"); }
template <int N> __device__ __forceinline__ void cp_wait() {
    asm volatile("cp.async.wait_group %0;\n" :: "n"(N));
}
__device__ __forceinline__ void ldsm_x4(unsigned* r, const void* p) {
    asm volatile("ldmatrix.sync.aligned.m8n8.x4.shared.b16 {%0,%1,%2,%3}, [%4];"
                 : "=r"(r[0]), "=r"(r[1]), "=r"(r[2]), "=r"(r[3]) : "r"(smem_u32(p)));
}
__device__ __forceinline__ void mma_bf16(float* c, const unsigned* a, const unsigned* b) {
    asm volatile(
        "mma.sync.aligned.m16n8k16.row.col.f32.bf16.bf16.f32 "
        "{%0,%1,%2,%3}, {%4,%5,%6,%7}, {%8,%9}, {%0,%1,%2,%3};\n"
        : "+f"(c[0]), "+f"(c[1]), "+f"(c[2]), "+f"(c[3])
        : "r"(a[0]), "r"(a[1]), "r"(a[2]), "r"(a[3]), "r"(b[0]), "r"(b[1]));
}
__device__ __forceinline__ void mma_fp16(float* c, const unsigned* a, const unsigned* b) {
    asm volatile(
        "mma.sync.aligned.m16n8k16.row.col.f32.f16.f16.f32 "
        "{%0,%1,%2,%3}, {%4,%5,%6,%7}, {%8,%9}, {%0,%1,%2,%3};\n"
        : "+f"(c[0]), "+f"(c[1]), "+f"(c[2]), "+f"(c[3])
        : "r"(a[0]), "r"(a[1]), "r"(a[2]), "r"(a[3]), "r"(b[0]), "r"(b[1]));
}
__device__ __forceinline__ void store_split_plane(__nv_bfloat16* p, long ps, float x) {
    __nv_bfloat16 h = __float2bfloat16(x);
    p[0]  = h;
    p[ps] = __float2bfloat16(x - __bfloat162float(h));
}
__device__ __forceinline__ unsigned pack2(__nv_bfloat16 a, __nv_bfloat16 b) {
    __nv_bfloat162 v = __halves2bfloat162(a, b);
    return *reinterpret_cast<unsigned*>(&v);
}
__device__ __forceinline__ void split4(float4 v, uint2& hi, uint2& lo) {
    __nv_bfloat16 h0 = __float2bfloat16(v.x), h1 = __float2bfloat16(v.y);
    __nv_bfloat16 h2 = __float2bfloat16(v.z), h3 = __float2bfloat16(v.w);
    hi.x = pack2(h0, h1); hi.y = pack2(h2, h3);
    lo.x = pack2(__float2bfloat16(v.x - __bfloat162float(h0)),
                 __float2bfloat16(v.y - __bfloat162float(h1)));
    lo.y = pack2(__float2bfloat16(v.z - __bfloat162float(h2)),
                 __float2bfloat16(v.w - __bfloat162float(h3)));
}
__device__ __forceinline__ float gelu_tanh(float g) {
    float u = 0.7978845608028654f * (g + 0.044715f * g * g * g);
    float e = __expf(2.0f * u);
    float th = 1.0f - 2.0f / (e + 1.0f);
    return 0.5f * g * (1.0f + th);
}

// -------------------- reductions -------------------------------------------
__device__ __forceinline__ float block_reduce_sum(float v) {
    __shared__ float red[32];
    __syncthreads();
    int lane = threadIdx.x & 31, wid = threadIdx.x >> 5;
    #pragma unroll
    for (int o = 16; o > 0; o >>= 1) v += __shfl_down_sync(0xffffffffu, v, o);
    if (lane == 0) red[wid] = v;
    __syncthreads();
    int nw = (blockDim.x + 31) >> 5;
    v = (threadIdx.x < (unsigned)nw) ? red[threadIdx.x] : 0.0f;
    if (wid == 0) {
        #pragma unroll
        for (int o = 16; o > 0; o >>= 1) v += __shfl_down_sync(0xffffffffu, v, o);
        if (lane == 0) red[0] = v;
    }
    __syncthreads();
    return red[0];
}
__device__ __forceinline__ float block_reduce_max(float v) {
    __shared__ float redm[32];
    __syncthreads();
    int lane = threadIdx.x & 31, wid = threadIdx.x >> 5;
    #pragma unroll
    for (int o = 16; o > 0; o >>= 1) v = fmaxf(v, __shfl_down_sync(0xffffffffu, v, o));
    if (lane == 0) redm[wid] = v;
    __syncthreads();
    int nw = (blockDim.x + 31) >> 5;
    v = (threadIdx.x < (unsigned)nw) ? redm[threadIdx.x] : -3.0e38f;
    if (wid == 0) {
        #pragma unroll
        for (int o = 16; o > 0; o >>= 1) v = fmaxf(v, __shfl_down_sync(0xffffffffu, v, o));
        if (lane == 0) redm[0] = v;
    }
    __syncthreads();
    return redm[0];
}

// -------------------- 3-term split bf16 GEMM (BN=64, 3-stage, 1 sync) -------
// EPI: 0 = fp32 out, 1 = split-bf16 out, 2 = fused gelu-mul split out.
template <int EPI>
__global__ void __launch_bounds__(256, 2) gemm3(
    const __nv_bfloat16* __restrict__ A, const __nv_bfloat16* __restrict__ B,
    float* __restrict__ Cf, __nv_bfloat16* __restrict__ Cs,
    int K, int lda, int ldb, long planeA, long planeB,
    int ldc, long planeC,
    long sA, long sB, long sC, int win, int kwin, int kchunk)
{
    constexpr int BN = 64;
    constexpr int STAGE = (256 + 2 * BN) * PADR;   // 15360 elems / 30720 B
    extern __shared__ __nv_bfloat16 sm[];

    A += (long)blockIdx.z * sA;
    B += (long)blockIdx.z * sB;
    if (EPI == 0) Cf += (long)blockIdx.z * sC; else Cs += (long)blockIdx.z * sC;

    const int m0 = blockIdx.y << 7;
    const int n0 = blockIdx.x * BN;
    if (win > 0) {
        if (n0 > m0 + 127) return;
        if (n0 + BN - 1 < m0 - win + 1) return;
    }
    const int tid = threadIdx.x, lane = tid & 31, warp = tid >> 5;
    const int wm = warp >> 1, wn = warp & 1;
    const int gid = lane >> 2, tig = lane & 3;

    int kbeg = 0, kend = K;
    if (kchunk > 0) {
        kbeg = blockIdx.z * kchunk; kend = kbeg + kchunk;
    } else if (kwin > 0) {
        kbeg = m0 - kwin + 1; if (kbeg < 0) kbeg = 0; kbeg &= ~31;
        kend = m0 + 128; if (kend > K) kend = K;
    }
    const int nk = (kend - kbeg) >> 5;

    float acc[2][4][4];
    #pragma unroll
    for (int mt = 0; mt < 2; mt++)
        #pragma unroll
        for (int nt = 0; nt < 4; nt++)
            #pragma unroll
            for (int i = 0; i < 4; i++) acc[mt][nt][i] = 0.0f;

    const __nv_bfloat16* Abase = A + (long)m0 * lda;
    const __nv_bfloat16* Bbase = B + (long)n0 * ldb;

    auto load_tile = [&](int s, int k0) {
        __nv_bfloat16* st = sm + s * STAGE;
        const __nv_bfloat16* Ab = Abase + k0;
        #pragma unroll
        for (int i = 0; i < 2; i++) {
            int idx = tid + (i << 8);
            int r = idx >> 2, c = (idx & 3) << 3;
            cp_async16(st + r * PADR + c, Ab + (long)r * lda + c);
            cp_async16(st + 128 * PADR + r * PADR + c, Ab + planeA + (long)r * lda + c);
        }
        const __nv_bfloat16* Bb = Bbase + k0;
        {
            int r = tid >> 2, c = (tid & 3) << 3;
            cp_async16(st + 256 * PADR + r * PADR + c, Bb + (long)r * ldb + c);
            cp_async16(st + (256 + BN) * PADR + r * PADR + c, Bb + planeB + (long)r * ldb + c);
        }
        cp_commit();
    };

    load_tile(0, kbeg);
    if (nk > 1) load_tile(1, kbeg + 32);

    const int arow = wm * 32 + (lane & 15);
    const int acol = (lane >> 4) << 3;
    const int brow = wn * 32 + ((lane >> 4) << 3) + (lane & 7);
    const int bcol = ((lane >> 3) & 1) << 3;

    for (int kt = 0; kt < nk; kt++) {
        if (kt + 1 < nk) cp_wait<1>(); else cp_wait<0>();
        __syncthreads();    // all warps done with compute(kt-1); stage (kt+2)%3 free
        if (kt + 2 < nk) load_tile((kt + 2) % 3, kbeg + ((kt + 2) << 5));

        const __nv_bfloat16* Ahp = sm + (kt % 3) * STAGE;
        const __nv_bfloat16* Alp = Ahp + 128 * PADR;
        const __nv_bfloat16* Bhp = Ahp + 256 * PADR;
        const __nv_bfloat16* Blp = Ahp + (256 + BN) * PADR;

        #pragma unroll
        for (int kk = 0; kk < 2; kk++) {
            unsigned ah[2][4], al[2][4], bh[2][4], bl[2][4];
            #pragma unroll
            for (int mt = 0; mt < 2; mt++) {
                ldsm_x4(ah[mt], Ahp + (long)(arow + mt * 16) * PADR + kk * 16 + acol);
                ldsm_x4(al[mt], Alp + (long)(arow + mt * 16) * PADR + kk * 16 + acol);
            }
            #pragma unroll
            for (int p = 0; p < 2; p++) {
                ldsm_x4(bh[p], Bhp + (long)(brow + p * 16) * PADR + kk * 16 + bcol);
                ldsm_x4(bl[p], Blp + (long)(brow + p * 16) * PADR + kk * 16 + bcol);
            }
            #pragma unroll
            for (int mt = 0; mt < 2; mt++)
                #pragma unroll
                for (int nt = 0; nt < 4; nt++) {
                    const unsigned* bhf = &bh[nt >> 1][(nt & 1) << 1];
                    const unsigned* blf = &bl[nt >> 1][(nt & 1) << 1];
                    mma_bf16(acc[mt][nt], ah[mt], bhf);
                    mma_bf16(acc[mt][nt], ah[mt], blf);
                    mma_bf16(acc[mt][nt], al[mt], bhf);
                }
        }
    }

    #pragma unroll
    for (int mt = 0; mt < 2; mt++) {
        int r = m0 + wm * 32 + mt * 16 + gid;
        #pragma unroll
        for (int nt = 0; nt < 4; nt++) {
            int cc = n0 + wn * 32 + nt * 8 + tig * 2;
            if (EPI == 0) {
                *reinterpret_cast<float2*>(Cf + (long)r * ldc + cc) =
                    make_float2(acc[mt][nt][0], acc[mt][nt][1]);
                *reinterpret_cast<float2*>(Cf + (long)(r + 8) * ldc + cc) =
                    make_float2(acc[mt][nt][2], acc[mt][nt][3]);
            } else if (EPI == 1) {
                store_split_plane(Cs + (long)r * ldc + cc,           planeC, acc[mt][nt][0]);
                store_split_plane(Cs + (long)r * ldc + cc + 1,       planeC, acc[mt][nt][1]);
                store_split_plane(Cs + (long)(r + 8) * ldc + cc,     planeC, acc[mt][nt][2]);
                store_split_plane(Cs + (long)(r + 8) * ldc + cc + 1, planeC, acc[mt][nt][3]);
            } else {
                int f = cc >> 1;
                store_split_plane(Cs + (long)r * ldc + f, planeC,
                                  gelu_tanh(acc[mt][nt][0]) * acc[mt][nt][1]);
                store_split_plane(Cs + (long)(r + 8) * ldc + f, planeC,
                                  gelu_tanh(acc[mt][nt][2]) * acc[mt][nt][3]);
            }
        }
    }
}

// -------------------- fp16 LM head: C = A @ B^T, B fp32 converted in-kernel --
__global__ void __launch_bounds__(256, 2) lmhead_h(
    const __half* __restrict__ A, const float* __restrict__ Bf, float* __restrict__ C)
{
    constexpr int STAGE = 256 * PADR;
    extern __shared__ __half smh[];

    const int m0 = blockIdx.x << 7;
    const int n0 = blockIdx.y << 7;
    const int tid = threadIdx.x, lane = tid & 31, warp = tid >> 5;
    const int wm = warp >> 1, wn = warp & 1;
    const int gid = lane >> 2, tig = lane & 3;

    float acc[2][8][4];
    #pragma unroll
    for (int mt = 0; mt < 2; mt++)
        #pragma unroll
        for (int nt = 0; nt < 8; nt++)
            #pragma unroll
            for (int i = 0; i < 4; i++) acc[mt][nt][i] = 0.0f;

    const __half* Abase = A + (long)m0 * D_MODEL;

    auto load_tileA = [&](int s, int k0) {
        __half* st = smh + s * STAGE;
        #pragma unroll
        for (int i = 0; i < 2; i++) {
            int idx = tid + (i << 8);
            int r = idx >> 2, c = (idx & 3) << 3;
            cp_async16(st + r * PADR + c, Abase + (long)r * D_MODEL + k0 + c);
        }
        cp_commit();
    };

    float4 breg[4];
    const int br = tid >> 1, bc16 = (tid & 1) << 4;
    auto ldgB = [&](int k0) {
        const float4* bp = reinterpret_cast<const float4*>(
            Bf + (long)(n0 + br) * D_MODEL + k0 + bc16);
        breg[0] = bp[0]; breg[1] = bp[1]; breg[2] = bp[2]; breg[3] = bp[3];
    };
    auto stsB = [&](int s) {
        __half* Bh = smh + s * STAGE + 128 * PADR + br * PADR + bc16;
        #pragma unroll
        for (int q = 0; q < 4; q++) {
            __half2 p0 = __floats2half2_rn(breg[q].x, breg[q].y);
            __half2 p1 = __floats2half2_rn(breg[q].z, breg[q].w);
            uint2 v;
            v.x = *reinterpret_cast<unsigned*>(&p0);
            v.y = *reinterpret_cast<unsigned*>(&p1);
            *reinterpret_cast<uint2*>(Bh + q * 4) = v;
        }
    };

    const int nk = D_MODEL / 32;   // 20
    ldgB(0);
    load_tileA(0, 0);
    stsB(0);

    const int arow = wm * 32 + (lane & 15);
    const int acol = (lane >> 4) << 3;
    const int brow = wn * 64 + ((lane >> 4) << 3) + (lane & 7);
    const int bcol = ((lane >> 3) & 1) << 3;

    for (int kt = 0; kt < nk; kt++) {
        const bool pf = (kt + 1 < nk);
        if (pf) {
            ldgB((kt + 1) << 5);
            load_tileA((kt + 1) & 1, (kt + 1) << 5);
            cp_wait<1>();
        } else {
            cp_wait<0>();
        }
        __syncthreads();

        const __half* Ap = smh + (kt & 1) * STAGE;
        const __half* Bp = Ap + 128 * PADR;

        #pragma unroll
        for (int kk = 0; kk < 2; kk++) {
            unsigned a[2][4], b[4][4];
            #pragma unroll
            for (int mt = 0; mt < 2; mt++)
                ldsm_x4(a[mt], Ap + (long)(arow + mt * 16) * PADR + kk * 16 + acol);
            #pragma unroll
            for (int p = 0; p < 4; p++)
                ldsm_x4(b[p], Bp + (long)(brow + p * 16) * PADR + kk * 16 + bcol);
            #pragma unroll
            for (int mt = 0; mt < 2; mt++)
                #pragma unroll
                for (int nt = 0; nt < 8; nt++)
                    mma_fp16(acc[mt][nt], a[mt], &b[nt >> 1][(nt & 1) << 1]);
        }
        if (pf) stsB((kt + 1) & 1);
        __syncthreads();
    }

    #pragma unroll
    for (int mt = 0; mt < 2; mt++) {
        int r = m0 + wm * 32 + mt * 16 + gid;
        #pragma unroll
        for (int nt = 0; nt < 8; nt++) {
            int cc = n0 + wn * 64 + nt * 8 + tig * 2;
            *reinterpret_cast<float2*>(C + (long)r * VOCAB + cc) =
                make_float2(acc[mt][nt][0], acc[mt][nt][1]);
            *reinterpret_cast<float2*>(C + (long)(r + 8) * VOCAB + cc) =
                make_float2(acc[mt][nt][2], acc[mt][nt][3]);
        }
    }
}

// -------------------- conversions -------------------------------------------
__global__ void conv_split(const float* __restrict__ src, __nv_bfloat16* __restrict__ dst,
                           long srcLS, long dstLS, long dstOff, long planeStride, int n) {
    src += (long)blockIdx.z * srcLS;
    dst += (long)blockIdx.z * dstLS + dstOff;
    int n8 = n >> 3;
    for (int i = blockIdx.x * blockDim.x + threadIdx.x; i < n8; i += gridDim.x * blockDim.x) {
        float4 a = reinterpret_cast<const float4*>(src)[2 * i];
        float4 b = reinterpret_cast<const float4*>(src)[2 * i + 1];
        uint2 h0, l0, h1, l1;
        split4(a, h0, l0); split4(b, h1, l1);
        uint4 hv; hv.x = h0.x; hv.y = h0.y; hv.z = h1.x; hv.w = h1.y;
        uint4 lv; lv.x = l0.x; lv.y = l0.y; lv.z = l1.x; lv.w = l1.y;
        *reinterpret_cast<uint4*>(dst + ((long)i << 3)) = hv;
        *reinterpret_cast<uint4*>(dst + planeStride + ((long)i << 3)) = lv;
    }
}

__global__ void conv_split_il(const float* __restrict__ src, __nv_bfloat16* __restrict__ dst,
                              long srcLS, long dstLS, int ro, long planeStride, int nRows) {
    src += (long)blockIdx.z * srcLS;
    dst += (long)blockIdx.z * dstLS;
    int total = nRows * 80;
    for (int i = blockIdx.x * blockDim.x + threadIdx.x; i < total; i += gridDim.x * blockDim.x) {
        int row = i / 80, c8 = i % 80;
        const float4* s = reinterpret_cast<const float4*>(src + (long)row * 640 + c8 * 8);
        float4 a = s[0], b = s[1];
        uint2 h0, l0, h1, l1;
        split4(a, h0, l0); split4(b, h1, l1);
        uint4 hv; hv.x = h0.x; hv.y = h0.y; hv.z = h1.x; hv.w = h1.y;
        uint4 lv; lv.x = l0.x; lv.y = l0.y; lv.z = l1.x; lv.w = l1.y;
        __nv_bfloat16* d = dst + (long)(2 * row + ro) * 640 + c8 * 8;
        *reinterpret_cast<uint4*>(d) = hv;
        *reinterpret_cast<uint4*>(d + planeStride) = lv;
    }
}

// -------------------- rope tables -------------------------------------------
__global__ void rope_table_kernel() {
    int t = blockIdx.x, b = blockIdx.y, d = threadIdx.x;
    float base = b ? 1000000.0f : 10000.0f;
    float invf = powf(base, -((float)d) / 128.0f);
    float s, c;
    sincosf((float)t * invf, &s, &c);
    long idx = ((long)b * SEQ + t) * 128 + d;
    g_ropec[idx] = c;
    g_ropes[idx] = s;
}

// -------------------- elementwise / norm kernels ----------------------------
__global__ void embed_kernel(const int* __restrict__ ids, const float* __restrict__ emb,
                             float* __restrict__ x) {
    int t = blockIdx.x;
    long id = (long)ids[t];
    for (int d = threadIdx.x; d < D_MODEL; d += blockDim.x)
        x[(long)t * D_MODEL + d] = emb[id * D_MODEL + d] * EMB_SCALE;
}

__global__ void rmsnorm_split_kernel(const float* __restrict__ x, const float* __restrict__ w,
                                     __nv_bfloat16* __restrict__ o2, long plane) {
    int t = blockIdx.x;
    const float* row = x + (long)t * D_MODEL;
    float ss = 0.0f;
    for (int d = threadIdx.x; d < D_MODEL; d += blockDim.x) { float v = row[d]; ss += v * v; }
    ss = block_reduce_sum(ss);
    float scale = rsqrtf(ss / (float)D_MODEL + 1e-6f);
    for (int d = threadIdx.x; d < D_MODEL; d += blockDim.x)
        store_split_plane(o2 + (long)t * D_MODEL + d, plane, row[d] * scale * (1.0f + w[d]));
}

__global__ void rmsadd_norm_split(float* __restrict__ x, const float* __restrict__ tmp,
                                  long tmpSlice,
                                  const float* __restrict__ wa, const float* __restrict__ wn,
                                  __nv_bfloat16* __restrict__ o2, long plane,
                                  __half* __restrict__ oh) {
    int t = blockIdx.x, tid = threadIdx.x;
    float* xr = x + (long)t * D_MODEL;
    const float* tr  = tmp + (long)t * D_MODEL;
    const float* tr2 = tr + tmpSlice;
    float tv[3];
    float ss = 0.0f;
    #pragma unroll
    for (int i = 0; i < 3; i++) {
        int d = tid + (i << 8);
        if (d < D_MODEL) { tv[i] = tr[d] + tr2[d]; ss += tv[i] * tv[i]; }
    }
    ss = block_reduce_sum(ss);
    float s1 = rsqrtf(ss / (float)D_MODEL + 1e-6f);
    float xv[3];
    ss = 0.0f;
    #pragma unroll
    for (int i = 0; i < 3; i++) {
        int d = tid + (i << 8);
        if (d < D_MODEL) {
            xv[i] = xr[d] + tv[i] * s1 * (1.0f + wa[d]);
            xr[d] = xv[i];
            ss += xv[i] * xv[i];
        }
    }
    ss = block_reduce_sum(ss);
    float s2 = rsqrtf(ss / (float)D_MODEL + 1e-6f);
    #pragma unroll
    for (int i = 0; i < 3; i++) {
        int d = tid + (i << 8);
        if (d < D_MODEL) {
            float v = xv[i] * s2 * (1.0f + wn[d]);
            store_split_plane(o2 + (long)t * D_MODEL + d, plane, v);
            if (oh) oh[(long)t * D_MODEL + d] = __float2half(v);
        }
    }
}

__global__ void qknorm_rope_fused(const float* __restrict__ qkv, long dup,
                                  const float* __restrict__ qw, const float* __restrict__ kw,
                                  __nv_bfloat16* __restrict__ q2, __nv_bfloat16* __restrict__ k2,
                                  long pQ, long pK, int bsel) {
    int t = blockIdx.x, h = blockIdx.y, d = threadIdx.x;
    const float* row;
    __nv_bfloat16* orow;
    const float* w;
    long plane;
    if (h < NHEADS) {
        row = qkv + (long)t * 1536 + h * HEADDIM;
        orow = q2 + (long)t * 1024 + h * HEADDIM;
        w = qw; plane = pQ;
    } else {
        row = qkv + (long)t * 1536 + 1024;
        orow = k2 + (long)t * 256;
        w = kw; plane = pK;
    }
    float v1 = row[d] + row[d + dup];
    float v2 = row[d + 128] + row[d + 128 + dup];
    float ss = block_reduce_sum(v1 * v1 + v2 * v2);
    float scale = rsqrtf(ss / (float)HEADDIM + 1e-6f);
    float q1 = v1 * scale * (1.0f + w[d]);
    float q2v = v2 * scale * (1.0f + w[d + 128]);
    long ridx = ((long)bsel * SEQ + t) * 128 + d;
    float c = g_ropec[ridx], s = g_ropes[ridx];
    store_split_plane(orow + d,       plane, q1 * c - q2v * s);
    store_split_plane(orow + d + 128, plane, q1 * s + q2v * c);
}

__global__ void transpose_split(const float* __restrict__ in, int rs, long dup,
                                __nv_bfloat16* __restrict__ out, long plane) {
    __shared__ float tile[32][33];
    int r0 = blockIdx.y << 5, c0 = blockIdx.x << 5;
    int x = threadIdx.x, y = threadIdx.y;
    #pragma unroll
    for (int i = 0; i < 32; i += 8) {
        long idx = (long)(r0 + y + i) * rs + c0 + x;
        tile[y + i][x] = in[idx] + in[idx + dup];
    }
    __syncthreads();
    #pragma unroll
    for (int i = 0; i < 32; i += 8)
        store_split_plane(out + (long)(c0 + y + i) * SEQ + r0 + x, plane, tile[x][y + i]);
}

__global__ void softmax_split_kernel(const float* __restrict__ S,
                                     __nv_bfloat16* __restrict__ P, int win) {
    __shared__ float buf[1024];
    int i = blockIdx.x, h = blockIdx.y;
    const float* row = S + ((long)h << 20) + ((long)i << 10);
    __nv_bfloat16* prow = P + (long)h * (2 << 20) + ((long)i << 10);
    const long plane = 1 << 20;
    int lo = i - win + 1; if (lo < 0) lo = 0;
    int m0 = i & ~127;
    int jlo = m0 - win + 1; if (jlo < 0) jlo = 0; jlo &= ~31;
    int jhi = m0 + 128; if (jhi > SEQ) jhi = SEQ;

    float mx = -3.0e38f;
    for (int j = lo + threadIdx.x; j <= i; j += blockDim.x) {
        float v = row[j] * 0.0625f;
        buf[j - jlo] = v;
        mx = fmaxf(mx, v);
    }
    mx = block_reduce_max(mx);
    float sum = 0.0f;
    for (int j = lo + threadIdx.x; j <= i; j += blockDim.x) {
        float e = __expf(buf[j - jlo] - mx);
        buf[j - jlo] = e;
        sum += e;
    }
    sum = block_reduce_sum(sum);
    float inv = 1.0f / sum;
    for (int j = jlo + threadIdx.x; j < jhi; j += blockDim.x) {
        float v = (j >= lo && j <= i) ? buf[j - jlo] * inv : 0.0f;
        store_split_plane(prow + j, plane, v);
    }
}

// -------------------- launch ------------------------------------------------
extern "C" void kernel_launch(void* const* d_in, const int* in_sizes, int n_in,
                              void* d_out, int out_size) {
    const int*   input_ids = (const int*)  d_in[0];
    const float* embed     = (const float*)d_in[1];
    const float* ln_in     = (const float*)d_in[2];
    const float* wq        = (const float*)d_in[3];
    const float* wk        = (const float*)d_in[4];
    const float* wv        = (const float*)d_in[5];
    const float* qnw       = (const float*)d_in[6];
    const float* knw       = (const float*)d_in[7];
    const float* wo        = (const float*)d_in[8];
    const float* ln_pa     = (const float*)d_in[9];
    const float* ln_pf     = (const float*)d_in[10];
    const float* wg        = (const float*)d_in[11];
    const float* wu        = (const float*)d_in[12];
    const float* wd        = (const float*)d_in[13];
    const float* ln_ff     = (const float*)d_in[14];
    const float* norm_f    = (const float*)d_in[15];
    float* out = (float*)d_out;

    const int SMEM64  = 3 * (256 + 128) * PADR * 2;   // 92160 (3 stages)
    const int SMEMLMH = 2 * 256 * PADR * 2;
    cudaFuncSetAttribute(gemm3<0>, cudaFuncAttributeMaxDynamicSharedMemorySize, SMEM64);
    cudaFuncSetAttribute(gemm3<1>, cudaFuncAttributeMaxDynamicSharedMemorySize, SMEM64);
    cudaFuncSetAttribute(gemm3<2>, cudaFuncAttributeMaxDynamicSharedMemorySize, SMEM64);
    cudaFuncSetAttribute(lmhead_h, cudaFuncAttributeMaxDynamicSharedMemorySize, SMEMLMH);

    float *x, *tmpd, *qkv, *sc;
    __nv_bfloat16 *xn2, *q2, *k2, *vt2, *p2, *ctx2, *ga2;
    __nv_bfloat16 *wqkv2, *wo2, *wgu2, *wd2;
    __half *xnh;
    cudaGetSymbolAddress((void**)&x,     g_x);
    cudaGetSymbolAddress((void**)&tmpd,  g_tmpd);
    cudaGetSymbolAddress((void**)&xn2,   g_xn2);
    cudaGetSymbolAddress((void**)&xnh,   g_xnh);
    cudaGetSymbolAddress((void**)&qkv,   g_qkv);
    cudaGetSymbolAddress((void**)&q2,    g_q2);
    cudaGetSymbolAddress((void**)&k2,    g_k2);
    cudaGetSymbolAddress((void**)&vt2,   g_vt2);
    cudaGetSymbolAddress((void**)&sc,    g_sc);
    cudaGetSymbolAddress((void**)&p2,    g_p2);
    cudaGetSymbolAddress((void**)&ctx2,  g_ctx2);
    cudaGetSymbolAddress((void**)&ga2,   g_ga2);
    cudaGetSymbolAddress((void**)&wqkv2, g_wqkv2);
    cudaGetSymbolAddress((void**)&wo2,   g_wo2);
    cudaGetSymbolAddress((void**)&wgu2,  g_wgu2);
    cudaGetSymbolAddress((void**)&wd2,   g_wd2);

    const long pXN  = (long)SEQ * D_MODEL;
    const long pQ   = (long)SEQ * 1024;
    const long pK   = (long)SEQ * 256;
    const long pVT  = (long)HEADDIM * SEQ;
    const long pGA  = (long)SEQ * DFF;
    const long pQKV = (long)1536 * 640;
    const long pWO  = (long)640 * 1024;
    const long pWGU = (long)4096 * 640;
    const long pWD  = (long)640 * 2048;
    const long QKV_SLICE = (long)SEQ * 1536;

    conv_split<<<dim3(320, 1, NLAYERS), 256>>>(wq, wqkv2, 1024L*640, 2*pQKV, 0,         pQKV, 1024*640);
    conv_split<<<dim3(80,  1, NLAYERS), 256>>>(wk, wqkv2,  256L*640, 2*pQKV, 1024L*640, pQKV,  256*640);
    conv_split<<<dim3(80,  1, NLAYERS), 256>>>(wv, wqkv2,  256L*640, 2*pQKV, 1280L*640, pQKV,  256*640);
    conv_split<<<dim3(320, 1, NLAYERS), 256>>>(wo, wo2,    640L*1024, 2*pWO,  0,        pWO,   640*1024);
    conv_split_il<<<dim3(640, 1, NLAYERS), 256>>>(wg, wgu2, 2048L*640, 2*pWGU, 0, pWGU, 2048);
    conv_split_il<<<dim3(640, 1, NLAYERS), 256>>>(wu, wgu2, 2048L*640, 2*pWGU, 1, pWGU, 2048);
    conv_split<<<dim3(640, 1, NLAYERS), 256>>>(wd, wd2,    640L*2048, 2*pWD,  0,        pWD,   640*2048);
    rope_table_kernel<<<dim3(SEQ, 2), 128>>>();

    embed_kernel<<<SEQ, 256>>>(input_ids, embed, x);
    rmsnorm_split_kernel<<<SEQ, 256>>>(x, ln_in, xn2, pXN);

    for (int l = 0; l < NLAYERS; l++) {
        const float* qnw_l   = qnw + l * HEADDIM;
        const float* knw_l   = knw + l * HEADDIM;
        const float* ln_pa_l = ln_pa + l * D_MODEL;
        const float* ln_pf_l = ln_pf + l * D_MODEL;
        const float* ln_ff_l = ln_ff + l * D_MODEL;
        const float* next_w  = (l + 1 < NLAYERS) ? (ln_in + (l + 1) * D_MODEL) : norm_f;
        const __nv_bfloat16* wqkv_l = wqkv2 + (long)l * 2 * pQKV;
        const __nv_bfloat16* wo_l   = wo2   + (long)l * 2 * pWO;
        const __nv_bfloat16* wgu_l  = wgu2  + (long)l * 2 * pWGU;
        const __nv_bfloat16* wd_l   = wd2   + (long)l * 2 * pWD;

        bool is_global = ((l + 1) % 6) == 0;
        int   win  = is_global ? 32768 : 512;
        int   bsel = is_global ? 1 : 0;

        // qkv, split-K x2, BN=64 grid (24 x 8 x 2 = 384 CTAs)
        gemm3<0><<<dim3(24, 8, 2), 256, SMEM64>>>(xn2, wqkv_l, qkv, nullptr,
            640, 640, 640, pXN, pQKV, 1536, 0, 0, 0, QKV_SLICE, -1, -1, 320);
        qknorm_rope_fused<<<dim3(SEQ, NHEADS + 1), 128>>>(qkv, QKV_SLICE, qnw_l, knw_l,
            q2, k2, pQ, pK, bsel);
        transpose_split<<<dim3(8, 32), dim3(32, 8)>>>(qkv + 1280, 1536, QKV_SLICE, vt2, pVT);
        gemm3<0><<<dim3(16, 8, NHEADS), 256, SMEM64>>>(q2, k2, sc, nullptr,
            256, 1024, 256, pQ, pK, 1024, 0, 256, 0, (long)1 << 20, win, -1, 0);
        softmax_split_kernel<<<dim3(SEQ, NHEADS), 256>>>(sc, p2, win);
        gemm3<1><<<dim3(4, 8, NHEADS), 256, SMEM64>>>(p2, vt2, nullptr, ctx2,
            1024, 1024, 1024, pQ, pVT, 1024, pQ, (long)2 << 20, 0, 256, -1, win, 0);
        gemm3<0><<<dim3(10, 8, 2), 256, SMEM64>>>(ctx2, wo_l, tmpd, nullptr,
            1024, 1024, 1024, pQ, pWO, D_MODEL, 0, 0, 0, pXN, -1, -1, 512);
        rmsadd_norm_split<<<SEQ, 256>>>(x, tmpd, pXN, ln_pa_l, ln_pf_l, xn2, pXN, nullptr);
        // fused gate+up, BN=64 grid (64 x 8 = 512 CTAs)
        gemm3<2><<<dim3(64, 8), 256, SMEM64>>>(xn2, wgu_l, nullptr, ga2,
            640, 640, 640, pXN, pWGU, DFF, pGA, 0, 0, 0, -1, -1, 0);
        gemm3<0><<<dim3(10, 8, 2), 256, SMEM64>>>(ga2, wd_l, tmpd, nullptr,
            2048, 2048, 2048, pGA, pWD, D_MODEL, 0, 0, 0, pXN, -1, -1, 1024);
        rmsadd_norm_split<<<SEQ, 256>>>(x, tmpd, pXN, ln_ff_l, next_w, xn2, pXN,
            (l + 1 == NLAYERS) ? xnh : nullptr);
    }

    lmhead_h<<<dim3(8, VOCAB / 128), 256, SMEMLMH>>>(xnh, embed, out);
    (void)in_sizes; (void)n_in; (void)out_size;
}

// round 12
// speedup vs baseline: 4.5939x; 1.0780x over previous
#include <cuda_runtime.h>
#include <cuda_bf16.h>
#include <cuda_fp16.h>
#include <cstdint>

#define D_MODEL 640
#define NHEADS  4
#define HEADDIM 256
#define DFF     2048
#define NLAYERS 18
#define SEQ     1024
#define VOCAB   262144
#define EMB_SCALE 25.298221281347036f

#define PADR 40

// -------------------- scratch (device globals) ------------------------------
__device__ __align__(256) float g_x[SEQ * D_MODEL];
__device__ __align__(256) float g_tmpd[3 * SEQ * D_MODEL];       // 3 split-K slices
__device__ __align__(256) __nv_bfloat16 g_xn2[2 * SEQ * D_MODEL];
__device__ __align__(256) __half g_xnh[SEQ * D_MODEL];
__device__ __align__(256) float g_qkv[3 * SEQ * 1536];           // 3 split-K slices
__device__ __align__(256) __nv_bfloat16 g_q2[2 * SEQ * 1024];
__device__ __align__(256) __nv_bfloat16 g_k2[2 * SEQ * 256];
__device__ __align__(256) __nv_bfloat16 g_vt2[2 * HEADDIM * SEQ];
__device__ __align__(256) float g_sc[NHEADS * SEQ * SEQ];
__device__ __align__(256) __nv_bfloat16 g_p2[(long)NHEADS * 2 * SEQ * SEQ];
__device__ __align__(256) __nv_bfloat16 g_ctx2[2 * SEQ * 1024];
__device__ __align__(256) __nv_bfloat16 g_ga2[2 * SEQ * DFF];
__device__ __align__(256) __nv_bfloat16 g_wqkv2[(long)NLAYERS * 2 * 1536 * 640];
__device__ __align__(256) __nv_bfloat16 g_wo2[(long)NLAYERS * 2 * 640 * 1024];
__device__ __align__(256) __nv_bfloat16 g_wgu2[(long)NLAYERS * 2 * 4096 * 640];
__device__ __align__(256) __nv_bfloat16 g_wd2[(long)NLAYERS * 2 * 640 * 2048];
__device__ __align__(256) float g_ropec[2 * SEQ * 128];
__device__ __align__(256) float g_ropes[2 * SEQ * 128];

// -------------------- asm / pack helpers -------------------------------------
__device__ __forceinline__ unsigned smem_u32(const void* p) {
    return (unsigned)__cvta_generic_to_shared(p);
}
__device__ __forceinline__ void cp_async16(void* smem, const void* gmem) {
    asm volatile("cp.async.cg.shared.global [%0], [%1], 16;\n"
                 :: "r"(smem_u32(smem)), "l"(gmem));
}
__device__ __forceinline__ void cp_commit() { asm volatile("cp.async.commit_group;\n"); }
template <int N> __device__ __forceinline__ void cp_wait() {
    asm volatile("cp.async.wait_group %0;\n" :: "n"(N));
}
__device__ __forceinline__ void ldsm_x4(unsigned* r, const void* p) {
    asm volatile("ldmatrix.sync.aligned.m8n8.x4.shared.b16 {%0,%1,%2,%3}, [%4];"
                 : "=r"(r[0]), "=r"(r[1]), "=r"(r[2]), "=r"(r[3]) : "r"(smem_u32(p)));
}
__device__ __forceinline__ void mma_bf16(float* c, const unsigned* a, const unsigned* b) {
    asm volatile(
        "mma.sync.aligned.m16n8k16.row.col.f32.bf16.bf16.f32 "
        "{%0,%1,%2,%3}, {%4,%5,%6,%7}, {%8,%9}, {%0,%1,%2,%3};\n"
        : "+f"(c[0]), "+f"(c[1]), "+f"(c[2]), "+f"(c[3])
        : "r"(a[0]), "r"(a[1]), "r"(a[2]), "r"(a[3]), "r"(b[0]), "r"(b[1]));
}
__device__ __forceinline__ void mma_fp16(float* c, const unsigned* a, const unsigned* b) {
    asm volatile(
        "mma.sync.aligned.m16n8k16.row.col.f32.f16.f16.f32 "
        "{%0,%1,%2,%3}, {%4,%5,%6,%7}, {%8,%9}, {%0,%1,%2,%3};\n"
        : "+f"(c[0]), "+f"(c[1]), "+f"(c[2]), "+f"(c[3])
        : "r"(a[0]), "r"(a[1]), "r"(a[2]), "r"(a[3]), "r"(b[0]), "r"(b[1]));
}
__device__ __forceinline__ void store_split_plane(__nv_bfloat16* p, long ps, float x) {
    __nv_bfloat16 h = __float2bfloat16(x);
    p[0]  = h;
    p[ps] = __float2bfloat16(x - __bfloat162float(h));
}
__device__ __forceinline__ unsigned pack2(__nv_bfloat16 a, __nv_bfloat16 b) {
    __nv_bfloat162 v = __halves2bfloat162(a, b);
    return *reinterpret_cast<unsigned*>(&v);
}
__device__ __forceinline__ void split4(float4 v, uint2& hi, uint2& lo) {
    __nv_bfloat16 h0 = __float2bfloat16(v.x), h1 = __float2bfloat16(v.y);
    __nv_bfloat16 h2 = __float2bfloat16(v.z), h3 = __float2bfloat16(v.w);
    hi.x = pack2(h0, h1); hi.y = pack2(h2, h3);
    lo.x = pack2(__float2bfloat16(v.x - __bfloat162float(h0)),
                 __float2bfloat16(v.y - __bfloat162float(h1)));
    lo.y = pack2(__float2bfloat16(v.z - __bfloat162float(h2)),
                 __float2bfloat16(v.w - __bfloat162float(h3)));
}
__device__ __forceinline__ float gelu_tanh(float g) {
    float u = 0.7978845608028654f * (g + 0.044715f * g * g * g);
    float e = __expf(2.0f * u);
    float th = 1.0f - 2.0f / (e + 1.0f);
    return 0.5f * g * (1.0f + th);
}

// -------------------- reductions -------------------------------------------
__device__ __forceinline__ float block_reduce_sum(float v) {
    __shared__ float red[32];
    __syncthreads();
    int lane = threadIdx.x & 31, wid = threadIdx.x >> 5;
    #pragma unroll
    for (int o = 16; o > 0; o >>= 1) v += __shfl_down_sync(0xffffffffu, v, o);
    if (lane == 0) red[wid] = v;
    __syncthreads();
    int nw = (blockDim.x + 31) >> 5;
    v = (threadIdx.x < (unsigned)nw) ? red[threadIdx.x] : 0.0f;
    if (wid == 0) {
        #pragma unroll
        for (int o = 16; o > 0; o >>= 1) v += __shfl_down_sync(0xffffffffu, v, o);
        if (lane == 0) red[0] = v;
    }
    __syncthreads();
    return red[0];
}
__device__ __forceinline__ float block_reduce_max(float v) {
    __shared__ float redm[32];
    __syncthreads();
    int lane = threadIdx.x & 31, wid = threadIdx.x >> 5;
    #pragma unroll
    for (int o = 16; o > 0; o >>= 1) v = fmaxf(v, __shfl_down_sync(0xffffffffu, v, o));
    if (lane == 0) redm[wid] = v;
    __syncthreads();
    int nw = (blockDim.x + 31) >> 5;
    v = (threadIdx.x < (unsigned)nw) ? redm[threadIdx.x] : -3.0e38f;
    if (wid == 0) {
        #pragma unroll
        for (int o = 16; o > 0; o >>= 1) v = fmaxf(v, __shfl_down_sync(0xffffffffu, v, o));
        if (lane == 0) redm[0] = v;
    }
    __syncthreads();
    return redm[0];
}

// -------------------- 3-term split bf16 GEMM (BN=64, 3-stage, 1 sync) -------
template <int EPI>
__global__ void __launch_bounds__(256, 2) gemm3(
    const __nv_bfloat16* __restrict__ A, const __nv_bfloat16* __restrict__ B,
    float* __restrict__ Cf, __nv_bfloat16* __restrict__ Cs,
    int K, int lda, int ldb, long planeA, long planeB,
    int ldc, long planeC,
    long sA, long sB, long sC, int win, int kwin, int kchunk)
{
    constexpr int BN = 64;
    constexpr int STAGE = (256 + 2 * BN) * PADR;
    extern __shared__ __nv_bfloat16 sm[];

    A += (long)blockIdx.z * sA;
    B += (long)blockIdx.z * sB;
    if (EPI == 0) Cf += (long)blockIdx.z * sC; else Cs += (long)blockIdx.z * sC;

    const int m0 = blockIdx.y << 7;
    const int n0 = blockIdx.x * BN;
    if (win > 0) {
        if (n0 > m0 + 127) return;
        if (n0 + BN - 1 < m0 - win + 1) return;
    }
    const int tid = threadIdx.x, lane = tid & 31, warp = tid >> 5;
    const int wm = warp >> 1, wn = warp & 1;
    const int gid = lane >> 2, tig = lane & 3;

    int kbeg = 0, kend = K;
    if (kchunk > 0) {
        kbeg = blockIdx.z * kchunk;
        kend = kbeg + kchunk; if (kend > K) kend = K;
    } else if (kwin > 0) {
        kbeg = m0 - kwin + 1; if (kbeg < 0) kbeg = 0; kbeg &= ~31;
        kend = m0 + 128; if (kend > K) kend = K;
    }
    const int nk = (kend - kbeg) >> 5;

    float acc[2][4][4];
    #pragma unroll
    for (int mt = 0; mt < 2; mt++)
        #pragma unroll
        for (int nt = 0; nt < 4; nt++)
            #pragma unroll
            for (int i = 0; i < 4; i++) acc[mt][nt][i] = 0.0f;

    const __nv_bfloat16* Abase = A + (long)m0 * lda;
    const __nv_bfloat16* Bbase = B + (long)n0 * ldb;

    auto load_tile = [&](int s, int k0) {
        __nv_bfloat16* st = sm + s * STAGE;
        const __nv_bfloat16* Ab = Abase + k0;
        #pragma unroll
        for (int i = 0; i < 2; i++) {
            int idx = tid + (i << 8);
            int r = idx >> 2, c = (idx & 3) << 3;
            cp_async16(st + r * PADR + c, Ab + (long)r * lda + c);
            cp_async16(st + 128 * PADR + r * PADR + c, Ab + planeA + (long)r * lda + c);
        }
        const __nv_bfloat16* Bb = Bbase + k0;
        {
            int r = tid >> 2, c = (tid & 3) << 3;
            cp_async16(st + 256 * PADR + r * PADR + c, Bb + (long)r * ldb + c);
            cp_async16(st + (256 + BN) * PADR + r * PADR + c, Bb + planeB + (long)r * ldb + c);
        }
        cp_commit();
    };

    load_tile(0, kbeg);
    if (nk > 1) load_tile(1, kbeg + 32);

    const int arow = wm * 32 + (lane & 15);
    const int acol = (lane >> 4) << 3;
    const int brow = wn * 32 + ((lane >> 4) << 3) + (lane & 7);
    const int bcol = ((lane >> 3) & 1) << 3;

    for (int kt = 0; kt < nk; kt++) {
        if (kt + 1 < nk) cp_wait<1>(); else cp_wait<0>();
        __syncthreads();
        if (kt + 2 < nk) load_tile((kt + 2) % 3, kbeg + ((kt + 2) << 5));

        const __nv_bfloat16* Ahp = sm + (kt % 3) * STAGE;
        const __nv_bfloat16* Alp = Ahp + 128 * PADR;
        const __nv_bfloat16* Bhp = Ahp + 256 * PADR;
        const __nv_bfloat16* Blp = Ahp + (256 + BN) * PADR;

        #pragma unroll
        for (int kk = 0; kk < 2; kk++) {
            unsigned ah[2][4], al[2][4], bh[2][4], bl[2][4];
            #pragma unroll
            for (int mt = 0; mt < 2; mt++) {
                ldsm_x4(ah[mt], Ahp + (long)(arow + mt * 16) * PADR + kk * 16 + acol);
                ldsm_x4(al[mt], Alp + (long)(arow + mt * 16) * PADR + kk * 16 + acol);
            }
            #pragma unroll
            for (int p = 0; p < 2; p++) {
                ldsm_x4(bh[p], Bhp + (long)(brow + p * 16) * PADR + kk * 16 + bcol);
                ldsm_x4(bl[p], Blp + (long)(brow + p * 16) * PADR + kk * 16 + bcol);
            }
            #pragma unroll
            for (int mt = 0; mt < 2; mt++)
                #pragma unroll
                for (int nt = 0; nt < 4; nt++) {
                    const unsigned* bhf = &bh[nt >> 1][(nt & 1) << 1];
                    const unsigned* blf = &bl[nt >> 1][(nt & 1) << 1];
                    mma_bf16(acc[mt][nt], ah[mt], bhf);
                    mma_bf16(acc[mt][nt], ah[mt], blf);
                    mma_bf16(acc[mt][nt], al[mt], bhf);
                }
        }
    }

    #pragma unroll
    for (int mt = 0; mt < 2; mt++) {
        int r = m0 + wm * 32 + mt * 16 + gid;
        #pragma unroll
        for (int nt = 0; nt < 4; nt++) {
            int cc = n0 + wn * 32 + nt * 8 + tig * 2;
            if (EPI == 0) {
                *reinterpret_cast<float2*>(Cf + (long)r * ldc + cc) =
                    make_float2(acc[mt][nt][0], acc[mt][nt][1]);
                *reinterpret_cast<float2*>(Cf + (long)(r + 8) * ldc + cc) =
                    make_float2(acc[mt][nt][2], acc[mt][nt][3]);
            } else if (EPI == 1) {
                store_split_plane(Cs + (long)r * ldc + cc,           planeC, acc[mt][nt][0]);
                store_split_plane(Cs + (long)r * ldc + cc + 1,       planeC, acc[mt][nt][1]);
                store_split_plane(Cs + (long)(r + 8) * ldc + cc,     planeC, acc[mt][nt][2]);
                store_split_plane(Cs + (long)(r + 8) * ldc + cc + 1, planeC, acc[mt][nt][3]);
            } else {
                int f = cc >> 1;
                store_split_plane(Cs + (long)r * ldc + f, planeC,
                                  gelu_tanh(acc[mt][nt][0]) * acc[mt][nt][1]);
                store_split_plane(Cs + (long)(r + 8) * ldc + f, planeC,
                                  gelu_tanh(acc[mt][nt][2]) * acc[mt][nt][3]);
            }
        }
    }
}

// -------------------- fp16 LM head: C = A @ B^T, B fp32 converted in-kernel --
__global__ void __launch_bounds__(256, 2) lmhead_h(
    const __half* __restrict__ A, const float* __restrict__ Bf, float* __restrict__ C)
{
    constexpr int STAGE = 256 * PADR;
    extern __shared__ __half smh[];

    const int m0 = blockIdx.x << 7;
    const int n0 = blockIdx.y << 7;
    const int tid = threadIdx.x, lane = tid & 31, warp = tid >> 5;
    const int wm = warp >> 1, wn = warp & 1;
    const int gid = lane >> 2, tig = lane & 3;

    float acc[2][8][4];
    #pragma unroll
    for (int mt = 0; mt < 2; mt++)
        #pragma unroll
        for (int nt = 0; nt < 8; nt++)
            #pragma unroll
            for (int i = 0; i < 4; i++) acc[mt][nt][i] = 0.0f;

    const __half* Abase = A + (long)m0 * D_MODEL;

    auto load_tileA = [&](int s, int k0) {
        __half* st = smh + s * STAGE;
        #pragma unroll
        for (int i = 0; i < 2; i++) {
            int idx = tid + (i << 8);
            int r = idx >> 2, c = (idx & 3) << 3;
            cp_async16(st + r * PADR + c, Abase + (long)r * D_MODEL + k0 + c);
        }
        cp_commit();
    };

    float4 breg[4];
    const int br = tid >> 1, bc16 = (tid & 1) << 4;
    auto ldgB = [&](int k0) {
        const float4* bp = reinterpret_cast<const float4*>(
            Bf + (long)(n0 + br) * D_MODEL + k0 + bc16);
        breg[0] = bp[0]; breg[1] = bp[1]; breg[2] = bp[2]; breg[3] = bp[3];
    };
    auto stsB = [&](int s) {
        __half* Bh = smh + s * STAGE + 128 * PADR + br * PADR + bc16;
        #pragma unroll
        for (int q = 0; q < 4; q++) {
            __half2 p0 = __floats2half2_rn(breg[q].x, breg[q].y);
            __half2 p1 = __floats2half2_rn(breg[q].z, breg[q].w);
            uint2 v;
            v.x = *reinterpret_cast<unsigned*>(&p0);
            v.y = *reinterpret_cast<unsigned*>(&p1);
            *reinterpret_cast<uint2*>(Bh + q * 4) = v;
        }
    };

    const int nk = D_MODEL / 32;
    ldgB(0);
    load_tileA(0, 0);
    stsB(0);

    const int arow = wm * 32 + (lane & 15);
    const int acol = (lane >> 4) << 3;
    const int brow = wn * 64 + ((lane >> 4) << 3) + (lane & 7);
    const int bcol = ((lane >> 3) & 1) << 3;

    for (int kt = 0; kt < nk; kt++) {
        const bool pf = (kt + 1 < nk);
        if (pf) {
            ldgB((kt + 1) << 5);
            load_tileA((kt + 1) & 1, (kt + 1) << 5);
            cp_wait<1>();
        } else {
            cp_wait<0>();
        }
        __syncthreads();

        const __half* Ap = smh + (kt & 1) * STAGE;
        const __half* Bp = Ap + 128 * PADR;

        #pragma unroll
        for (int kk = 0; kk < 2; kk++) {
            unsigned a[2][4], b[4][4];
            #pragma unroll
            for (int mt = 0; mt < 2; mt++)
                ldsm_x4(a[mt], Ap + (long)(arow + mt * 16) * PADR + kk * 16 + acol);
            #pragma unroll
            for (int p = 0; p < 4; p++)
                ldsm_x4(b[p], Bp + (long)(brow + p * 16) * PADR + kk * 16 + bcol);
            #pragma unroll
            for (int mt = 0; mt < 2; mt++)
                #pragma unroll
                for (int nt = 0; nt < 8; nt++)
                    mma_fp16(acc[mt][nt], a[mt], &b[nt >> 1][(nt & 1) << 1]);
        }
        if (pf) stsB((kt + 1) & 1);
        __syncthreads();
    }

    #pragma unroll
    for (int mt = 0; mt < 2; mt++) {
        int r = m0 + wm * 32 + mt * 16 + gid;
        #pragma unroll
        for (int nt = 0; nt < 8; nt++) {
            int cc = n0 + wn * 64 + nt * 8 + tig * 2;
            *reinterpret_cast<float2*>(C + (long)r * VOCAB + cc) =
                make_float2(acc[mt][nt][0], acc[mt][nt][1]);
            *reinterpret_cast<float2*>(C + (long)(r + 8) * VOCAB + cc) =
                make_float2(acc[mt][nt][2], acc[mt][nt][3]);
        }
    }
}

// -------------------- conversions -------------------------------------------
__global__ void conv_split(const float* __restrict__ src, __nv_bfloat16* __restrict__ dst,
                           long srcLS, long dstLS, long dstOff, long planeStride, int n) {
    src += (long)blockIdx.z * srcLS;
    dst += (long)blockIdx.z * dstLS + dstOff;
    int n8 = n >> 3;
    for (int i = blockIdx.x * blockDim.x + threadIdx.x; i < n8; i += gridDim.x * blockDim.x) {
        float4 a = reinterpret_cast<const float4*>(src)[2 * i];
        float4 b = reinterpret_cast<const float4*>(src)[2 * i + 1];
        uint2 h0, l0, h1, l1;
        split4(a, h0, l0); split4(b, h1, l1);
        uint4 hv; hv.x = h0.x; hv.y = h0.y; hv.z = h1.x; hv.w = h1.y;
        uint4 lv; lv.x = l0.x; lv.y = l0.y; lv.z = l1.x; lv.w = l1.y;
        *reinterpret_cast<uint4*>(dst + ((long)i << 3)) = hv;
        *reinterpret_cast<uint4*>(dst + planeStride + ((long)i << 3)) = lv;
    }
}

__global__ void conv_split_il(const float* __restrict__ src, __nv_bfloat16* __restrict__ dst,
                              long srcLS, long dstLS, int ro, long planeStride, int nRows) {
    src += (long)blockIdx.z * srcLS;
    dst += (long)blockIdx.z * dstLS;
    int total = nRows * 80;
    for (int i = blockIdx.x * blockDim.x + threadIdx.x; i < total; i += gridDim.x * blockDim.x) {
        int row = i / 80, c8 = i % 80;
        const float4* s = reinterpret_cast<const float4*>(src + (long)row * 640 + c8 * 8);
        float4 a = s[0], b = s[1];
        uint2 h0, l0, h1, l1;
        split4(a, h0, l0); split4(b, h1, l1);
        uint4 hv; hv.x = h0.x; hv.y = h0.y; hv.z = h1.x; hv.w = h1.y;
        uint4 lv; lv.x = l0.x; lv.y = l0.y; lv.z = l1.x; lv.w = l1.y;
        __nv_bfloat16* d = dst + (long)(2 * row + ro) * 640 + c8 * 8;
        *reinterpret_cast<uint4*>(d) = hv;
        *reinterpret_cast<uint4*>(d + planeStride) = lv;
    }
}

// -------------------- rope tables -------------------------------------------
__global__ void rope_table_kernel() {
    int t = blockIdx.x, b = blockIdx.y, d = threadIdx.x;
    float base = b ? 1000000.0f : 10000.0f;
    float invf = powf(base, -((float)d) / 128.0f);
    float s, c;
    sincosf((float)t * invf, &s, &c);
    long idx = ((long)b * SEQ + t) * 128 + d;
    g_ropec[idx] = c;
    g_ropes[idx] = s;
}

// -------------------- elementwise / norm kernels ----------------------------
__global__ void embed_kernel(const int* __restrict__ ids, const float* __restrict__ emb,
                             float* __restrict__ x) {
    int t = blockIdx.x;
    long id = (long)ids[t];
    for (int d = threadIdx.x; d < D_MODEL; d += blockDim.x)
        x[(long)t * D_MODEL + d] = emb[id * D_MODEL + d] * EMB_SCALE;
}

__global__ void rmsnorm_split_kernel(const float* __restrict__ x, const float* __restrict__ w,
                                     __nv_bfloat16* __restrict__ o2, long plane) {
    int t = blockIdx.x;
    const float* row = x + (long)t * D_MODEL;
    float ss = 0.0f;
    for (int d = threadIdx.x; d < D_MODEL; d += blockDim.x) { float v = row[d]; ss += v * v; }
    ss = block_reduce_sum(ss);
    float scale = rsqrtf(ss / (float)D_MODEL + 1e-6f);
    for (int d = threadIdx.x; d < D_MODEL; d += blockDim.x)
        store_split_plane(o2 + (long)t * D_MODEL + d, plane, row[d] * scale * (1.0f + w[d]));
}

// fused: x += rms(sum of 3 tmp slices, wa); o2 = split(rms(x, wn)); opt fp16 copy
__global__ void rmsadd_norm_split(float* __restrict__ x, const float* __restrict__ tmp,
                                  long tmpSlice,
                                  const float* __restrict__ wa, const float* __restrict__ wn,
                                  __nv_bfloat16* __restrict__ o2, long plane,
                                  __half* __restrict__ oh) {
    int t = blockIdx.x, tid = threadIdx.x;
    float* xr = x + (long)t * D_MODEL;
    const float* tr  = tmp + (long)t * D_MODEL;
    float tv[3];
    float ss = 0.0f;
    #pragma unroll
    for (int i = 0; i < 3; i++) {
        int d = tid + (i << 8);
        if (d < D_MODEL) {
            tv[i] = tr[d] + tr[d + tmpSlice] + tr[d + 2 * tmpSlice];
            ss += tv[i] * tv[i];
        }
    }
    ss = block_reduce_sum(ss);
    float s1 = rsqrtf(ss / (float)D_MODEL + 1e-6f);
    float xv[3];
    ss = 0.0f;
    #pragma unroll
    for (int i = 0; i < 3; i++) {
        int d = tid + (i << 8);
        if (d < D_MODEL) {
            xv[i] = xr[d] + tv[i] * s1 * (1.0f + wa[d]);
            xr[d] = xv[i];
            ss += xv[i] * xv[i];
        }
    }
    ss = block_reduce_sum(ss);
    float s2 = rsqrtf(ss / (float)D_MODEL + 1e-6f);
    #pragma unroll
    for (int i = 0; i < 3; i++) {
        int d = tid + (i << 8);
        if (d < D_MODEL) {
            float v = xv[i] * s2 * (1.0f + wn[d]);
            store_split_plane(o2 + (long)t * D_MODEL + d, plane, v);
            if (oh) oh[(long)t * D_MODEL + d] = __float2half(v);
        }
    }
}

// fused q+k rms-norm + rope over 3 split-K qkv slices
__global__ void qknorm_rope_fused(const float* __restrict__ qkv, long dup,
                                  const float* __restrict__ qw, const float* __restrict__ kw,
                                  __nv_bfloat16* __restrict__ q2, __nv_bfloat16* __restrict__ k2,
                                  long pQ, long pK, int bsel) {
    int t = blockIdx.x, h = blockIdx.y, d = threadIdx.x;
    const float* row;
    __nv_bfloat16* orow;
    const float* w;
    long plane;
    if (h < NHEADS) {
        row = qkv + (long)t * 1536 + h * HEADDIM;
        orow = q2 + (long)t * 1024 + h * HEADDIM;
        w = qw; plane = pQ;
    } else {
        row = qkv + (long)t * 1536 + 1024;
        orow = k2 + (long)t * 256;
        w = kw; plane = pK;
    }
    float v1 = row[d] + row[d + dup] + row[d + 2 * dup];
    float v2 = row[d + 128] + row[d + 128 + dup] + row[d + 128 + 2 * dup];
    float ss = block_reduce_sum(v1 * v1 + v2 * v2);
    float scale = rsqrtf(ss / (float)HEADDIM + 1e-6f);
    float q1 = v1 * scale * (1.0f + w[d]);
    float q2v = v2 * scale * (1.0f + w[d + 128]);
    long ridx = ((long)bsel * SEQ + t) * 128 + d;
    float c = g_ropec[ridx], s = g_ropes[ridx];
    store_split_plane(orow + d,       plane, q1 * c - q2v * s);
    store_split_plane(orow + d + 128, plane, q1 * s + q2v * c);
}

__global__ void transpose_split(const float* __restrict__ in, int rs, long dup,
                                __nv_bfloat16* __restrict__ out, long plane) {
    __shared__ float tile[32][33];
    int r0 = blockIdx.y << 5, c0 = blockIdx.x << 5;
    int x = threadIdx.x, y = threadIdx.y;
    #pragma unroll
    for (int i = 0; i < 32; i += 8) {
        long idx = (long)(r0 + y + i) * rs + c0 + x;
        tile[y + i][x] = in[idx] + in[idx + dup] + in[idx + 2 * dup];
    }
    __syncthreads();
    #pragma unroll
    for (int i = 0; i < 32; i += 8)
        store_split_plane(out + (long)(c0 + y + i) * SEQ + r0 + x, plane, tile[x][y + i]);
}

__global__ void softmax_split_kernel(const float* __restrict__ S,
                                     __nv_bfloat16* __restrict__ P, int win) {
    __shared__ float buf[1024];
    int i = blockIdx.x, h = blockIdx.y;
    const float* row = S + ((long)h << 20) + ((long)i << 10);
    __nv_bfloat16* prow = P + (long)h * (2 << 20) + ((long)i << 10);
    const long plane = 1 << 20;
    int lo = i - win + 1; if (lo < 0) lo = 0;
    int m0 = i & ~127;
    int jlo = m0 - win + 1; if (jlo < 0) jlo = 0; jlo &= ~31;
    int jhi = m0 + 128; if (jhi > SEQ) jhi = SEQ;

    float mx = -3.0e38f;
    for (int j = lo + threadIdx.x; j <= i; j += blockDim.x) {
        float v = row[j] * 0.0625f;
        buf[j - jlo] = v;
        mx = fmaxf(mx, v);
    }
    mx = block_reduce_max(mx);
    float sum = 0.0f;
    for (int j = lo + threadIdx.x; j <= i; j += blockDim.x) {
        float e = __expf(buf[j - jlo] - mx);
        buf[j - jlo] = e;
        sum += e;
    }
    sum = block_reduce_sum(sum);
    float inv = 1.0f / sum;
    for (int j = jlo + threadIdx.x; j < jhi; j += blockDim.x) {
        float v = (j >= lo && j <= i) ? buf[j - jlo] * inv : 0.0f;
        store_split_plane(prow + j, plane, v);
    }
}

// -------------------- launch ------------------------------------------------
extern "C" void kernel_launch(void* const* d_in, const int* in_sizes, int n_in,
                              void* d_out, int out_size) {
    const int*   input_ids = (const int*)  d_in[0];
    const float* embed     = (const float*)d_in[1];
    const float* ln_in     = (const float*)d_in[2];
    const float* wq        = (const float*)d_in[3];
    const float* wk        = (const float*)d_in[4];
    const float* wv        = (const float*)d_in[5];
    const float* qnw       = (const float*)d_in[6];
    const float* knw       = (const float*)d_in[7];
    const float* wo        = (const float*)d_in[8];
    const float* ln_pa     = (const float*)d_in[9];
    const float* ln_pf     = (const float*)d_in[10];
    const float* wg        = (const float*)d_in[11];
    const float* wu        = (const float*)d_in[12];
    const float* wd        = (const float*)d_in[13];
    const float* ln_ff     = (const float*)d_in[14];
    const float* norm_f    = (const float*)d_in[15];
    float* out = (float*)d_out;

    const int SMEM64  = 3 * (256 + 128) * PADR * 2;
    const int SMEMLMH = 2 * 256 * PADR * 2;
    cudaFuncSetAttribute(gemm3<0>, cudaFuncAttributeMaxDynamicSharedMemorySize, SMEM64);
    cudaFuncSetAttribute(gemm3<1>, cudaFuncAttributeMaxDynamicSharedMemorySize, SMEM64);
    cudaFuncSetAttribute(gemm3<2>, cudaFuncAttributeMaxDynamicSharedMemorySize, SMEM64);
    cudaFuncSetAttribute(lmhead_h, cudaFuncAttributeMaxDynamicSharedMemorySize, SMEMLMH);

    float *x, *tmpd, *qkv, *sc;
    __nv_bfloat16 *xn2, *q2, *k2, *vt2, *p2, *ctx2, *ga2;
    __nv_bfloat16 *wqkv2, *wo2, *wgu2, *wd2;
    __half *xnh;
    cudaGetSymbolAddress((void**)&x,     g_x);
    cudaGetSymbolAddress((void**)&tmpd,  g_tmpd);
    cudaGetSymbolAddress((void**)&xn2,   g_xn2);
    cudaGetSymbolAddress((void**)&xnh,   g_xnh);
    cudaGetSymbolAddress((void**)&qkv,   g_qkv);
    cudaGetSymbolAddress((void**)&q2,    g_q2);
    cudaGetSymbolAddress((void**)&k2,    g_k2);
    cudaGetSymbolAddress((void**)&vt2,   g_vt2);
    cudaGetSymbolAddress((void**)&sc,    g_sc);
    cudaGetSymbolAddress((void**)&p2,    g_p2);
    cudaGetSymbolAddress((void**)&ctx2,  g_ctx2);
    cudaGetSymbolAddress((void**)&ga2,   g_ga2);
    cudaGetSymbolAddress((void**)&wqkv2, g_wqkv2);
    cudaGetSymbolAddress((void**)&wo2,   g_wo2);
    cudaGetSymbolAddress((void**)&wgu2,  g_wgu2);
    cudaGetSymbolAddress((void**)&wd2,   g_wd2);

    const long pXN  = (long)SEQ * D_MODEL;
    const long pQ   = (long)SEQ * 1024;
    const long pK   = (long)SEQ * 256;
    const long pVT  = (long)HEADDIM * SEQ;
    const long pGA  = (long)SEQ * DFF;
    const long pQKV = (long)1536 * 640;
    const long pWO  = (long)640 * 1024;
    const long pWGU = (long)4096 * 640;
    const long pWD  = (long)640 * 2048;
    const long QKV_SLICE = (long)SEQ * 1536;

    conv_split<<<dim3(320, 1, NLAYERS), 256>>>(wq, wqkv2, 1024L*640, 2*pQKV, 0,         pQKV, 1024*640);
    conv_split<<<dim3(80,  1, NLAYERS), 256>>>(wk, wqkv2,  256L*640, 2*pQKV, 1024L*640, pQKV,  256*640);
    conv_split<<<dim3(80,  1, NLAYERS), 256>>>(wv, wqkv2,  256L*640, 2*pQKV, 1280L*640, pQKV,  256*640);
    conv_split<<<dim3(320, 1, NLAYERS), 256>>>(wo, wo2,    640L*1024, 2*pWO,  0,        pWO,   640*1024);
    conv_split_il<<<dim3(640, 1, NLAYERS), 256>>>(wg, wgu2, 2048L*640, 2*pWGU, 0, pWGU, 2048);
    conv_split_il<<<dim3(640, 1, NLAYERS), 256>>>(wu, wgu2, 2048L*640, 2*pWGU, 1, pWGU, 2048);
    conv_split<<<dim3(640, 1, NLAYERS), 256>>>(wd, wd2,    640L*2048, 2*pWD,  0,        pWD,   640*2048);
    rope_table_kernel<<<dim3(SEQ, 2), 128>>>();

    embed_kernel<<<SEQ, 256>>>(input_ids, embed, x);
    rmsnorm_split_kernel<<<SEQ, 256>>>(x, ln_in, xn2, pXN);

    for (int l = 0; l < NLAYERS; l++) {
        const float* qnw_l   = qnw + l * HEADDIM;
        const float* knw_l   = knw + l * HEADDIM;
        const float* ln_pa_l = ln_pa + l * D_MODEL;
        const float* ln_pf_l = ln_pf + l * D_MODEL;
        const float* ln_ff_l = ln_ff + l * D_MODEL;
        const float* next_w  = (l + 1 < NLAYERS) ? (ln_in + (l + 1) * D_MODEL) : norm_f;
        const __nv_bfloat16* wqkv_l = wqkv2 + (long)l * 2 * pQKV;
        const __nv_bfloat16* wo_l   = wo2   + (long)l * 2 * pWO;
        const __nv_bfloat16* wgu_l  = wgu2  + (long)l * 2 * pWGU;
        const __nv_bfloat16* wd_l   = wd2   + (long)l * 2 * pWD;

        bool is_global = ((l + 1) % 6) == 0;
        int   win  = is_global ? 32768 : 512;
        int   bsel = is_global ? 1 : 0;

        // qkv: split-K x3 (224/224/192) -> 576 CTAs
        gemm3<0><<<dim3(24, 8, 3), 256, SMEM64>>>(xn2, wqkv_l, qkv, nullptr,
            640, 640, 640, pXN, pQKV, 1536, 0, 0, 0, QKV_SLICE, -1, -1, 224);
        qknorm_rope_fused<<<dim3(SEQ, NHEADS + 1), 128>>>(qkv, QKV_SLICE, qnw_l, knw_l,
            q2, k2, pQ, pK, bsel);
        transpose_split<<<dim3(8, 32), dim3(32, 8)>>>(qkv + 1280, 1536, QKV_SLICE, vt2, pVT);
        gemm3<0><<<dim3(16, 8, NHEADS), 256, SMEM64>>>(q2, k2, sc, nullptr,
            256, 1024, 256, pQ, pK, 1024, 0, 256, 0, (long)1 << 20, win, -1, 0);
        softmax_split_kernel<<<dim3(SEQ, NHEADS), 256>>>(sc, p2, win);
        gemm3<1><<<dim3(4, 8, NHEADS), 256, SMEM64>>>(p2, vt2, nullptr, ctx2,
            1024, 1024, 1024, pQ, pVT, 1024, pQ, (long)2 << 20, 0, 256, -1, win, 0);
        // wo: split-K x3 (352/352/320) -> 240 CTAs, single wave
        gemm3<0><<<dim3(10, 8, 3), 256, SMEM64>>>(ctx2, wo_l, tmpd, nullptr,
            1024, 1024, 1024, pQ, pWO, D_MODEL, 0, 0, 0, pXN, -1, -1, 352);
        rmsadd_norm_split<<<SEQ, 256>>>(x, tmpd, pXN, ln_pa_l, ln_pf_l, xn2, pXN, nullptr);
        gemm3<2><<<dim3(64, 8), 256, SMEM64>>>(xn2, wgu_l, nullptr, ga2,
            640, 640, 640, pXN, pWGU, DFF, pGA, 0, 0, 0, -1, -1, 0);
        // wd: split-K x3 (704/704/640) -> 240 CTAs, single wave
        gemm3<0><<<dim3(10, 8, 3), 256, SMEM64>>>(ga2, wd_l, tmpd, nullptr,
            2048, 2048, 2048, pGA, pWD, D_MODEL, 0, 0, 0, pXN, -1, -1, 704);
        rmsadd_norm_split<<<SEQ, 256>>>(x, tmpd, pXN, ln_ff_l, next_w, xn2, pXN,
            (l + 1 == NLAYERS) ? xnh : nullptr);
    }

    lmhead_h<<<dim3(8, VOCAB / 128), 256, SMEMLMH>>>(xnh, embed, out);
    (void)in_sizes; (void)n_in; (void)out_size;
}